// round 4
// baseline (speedup 1.0000x reference)
#include <cuda_runtime.h>
#include <cuda_bf16.h>
#include <math.h>
#include <cstdint>

#define NMAX 50000
#define NPAD 50176   // 128-aligned padding for OOB-safe cp.async tails
#define EMAX 400000
#define DD   256
#define HH   128
#define G3   384
#define SROW 144     // smem bytes per row (72 bf16) — conflict-free ldmatrix

// ------------------- fp32 scratch -------------------
__device__ float g_HS [NMAX*HH];
__device__ float g_HT [NMAX*HH];
__device__ float g_AGG[NMAX*HH];
__device__ float g_GI [NMAX*G3];
__device__ float g_GH [NMAX*G3];
__device__ float g_AS [NMAX];
__device__ float g_AT [NMAX];
__device__ float g_DEN[NMAX];
__device__ float g_EX [EMAX];
__device__ float g_HUI[NMAX*HH];
__device__ float g_HIU[NMAX*HH];
__device__ float g_HII[NMAX*HH];
// ------------------- bf16 hi/lo split operands -------------------
__device__ __nv_bfloat16 g_XUh[NPAD*DD], g_XUl[NPAD*DD];
__device__ __nv_bfloat16 g_XIh[NPAD*DD], g_XIl[NPAD*DD];
__device__ __nv_bfloat16 g_HTh[NPAD*HH], g_HTl[NPAD*HH];
__device__ __nv_bfloat16 g_AGh[NPAD*HH], g_AGl[NPAD*HH];
// pre-split weights: WT [128][256] (transposed), WG [384][128]
__device__ __nv_bfloat16 g_WTh[6*128*256], g_WTl[6*128*256];
__device__ __nv_bfloat16 g_WGh[6*384*128], g_WGl[6*384*128];

// ------------------- PTX helpers -------------------
__device__ __forceinline__ uint32_t smem_u32(const void* p) {
    uint32_t a;
    asm("{ .reg .u64 t; cvta.to.shared.u64 t, %1; cvt.u32.u64 %0, t; }" : "=r"(a) : "l"(p));
    return a;
}
__device__ __forceinline__ void ldsm4(uint32_t* r, uint32_t addr) {
    asm volatile("ldmatrix.sync.aligned.m8n8.x4.shared.b16 {%0,%1,%2,%3}, [%4];"
                 : "=r"(r[0]), "=r"(r[1]), "=r"(r[2]), "=r"(r[3]) : "r"(addr));
}
__device__ __forceinline__ void mma_bf16(float* d, const uint32_t* a, const uint32_t* b) {
    asm volatile(
        "mma.sync.aligned.m16n8k16.row.col.f32.bf16.bf16.f32 "
        "{%0,%1,%2,%3}, {%4,%5,%6,%7}, {%8,%9}, {%0,%1,%2,%3};"
        : "+f"(d[0]), "+f"(d[1]), "+f"(d[2]), "+f"(d[3])
        : "r"(a[0]), "r"(a[1]), "r"(a[2]), "r"(a[3]), "r"(b[0]), "r"(b[1]));
}
__device__ __forceinline__ void cpa16(uint32_t dst, const void* src) {
    asm volatile("cp.async.cg.shared.global [%0], [%1], 16;" :: "r"(dst), "l"(src));
}
__device__ __forceinline__ void cpcommit() {
    asm volatile("cp.async.commit_group;" ::: "memory");
}

// ------------------- prep / split kernels -------------------
__global__ void prep_wt(const float* __restrict__ w,
                        __nv_bfloat16* __restrict__ oh, __nv_bfloat16* __restrict__ ol)
{
    int i = blockIdx.x * blockDim.x + threadIdx.x;
    if (i >= 128 * 256) return;
    int n = i >> 8, k = i & 255;
    float x = w[k * 128 + n];
    __nv_bfloat16 h = __float2bfloat16(x);
    oh[i] = h;
    ol[i] = __float2bfloat16(x - __bfloat162float(h));
}
__global__ void prep_wg(const float* __restrict__ w,
                        __nv_bfloat16* __restrict__ oh, __nv_bfloat16* __restrict__ ol)
{
    int i = blockIdx.x * blockDim.x + threadIdx.x;
    if (i >= 384 * 128) return;
    float x = w[i];
    __nv_bfloat16 h = __float2bfloat16(x);
    oh[i] = h;
    ol[i] = __float2bfloat16(x - __bfloat162float(h));
}
// generic fp32 -> bf16 hi/lo split, vectorized by 4
__global__ void split_k(const float* __restrict__ in,
                        __nv_bfloat16* __restrict__ oh, __nv_bfloat16* __restrict__ ol, int n4)
{
    int i = blockIdx.x * blockDim.x + threadIdx.x;
    if (i >= n4) return;
    float4 v = reinterpret_cast<const float4*>(in)[i];
    __nv_bfloat16 h0 = __float2bfloat16(v.x);
    __nv_bfloat16 h1 = __float2bfloat16(v.y);
    __nv_bfloat16 h2 = __float2bfloat16(v.z);
    __nv_bfloat16 h3 = __float2bfloat16(v.w);
    uint2 hp, lp;
    hp.x = ((uint32_t)__bfloat16_as_ushort(h1) << 16) | __bfloat16_as_ushort(h0);
    hp.y = ((uint32_t)__bfloat16_as_ushort(h3) << 16) | __bfloat16_as_ushort(h2);
    __nv_bfloat16 l0 = __float2bfloat16(v.x - __bfloat162float(h0));
    __nv_bfloat16 l1 = __float2bfloat16(v.y - __bfloat162float(h1));
    __nv_bfloat16 l2 = __float2bfloat16(v.z - __bfloat162float(h2));
    __nv_bfloat16 l3 = __float2bfloat16(v.w - __bfloat162float(h3));
    lp.x = ((uint32_t)__bfloat16_as_ushort(l1) << 16) | __bfloat16_as_ushort(l0);
    lp.y = ((uint32_t)__bfloat16_as_ushort(l3) << 16) | __bfloat16_as_ushort(l2);
    reinterpret_cast<uint2*>(oh)[i] = hp;
    reinterpret_cast<uint2*>(ol)[i] = lp;
}

// ------------------- pipelined bf16-split tensor-core GEMM -------------------
// C[M,Nc] = (Ah+Al)[M,K] @ (Bh+Bl)[Nc,K]^T, 3-term emulation.
// CTA tile 128x128, BK=64, 2-stage cp.async double buffer, 8 warps (32x64 each).
#define TILE_B  (128 * SROW)         // 18432 bytes per operand tile
#define STAGE_B (4 * TILE_B)         // 73728 per stage
template<bool HASBIAS>
__global__ void __launch_bounds__(256) mm_gemm(
    const __nv_bfloat16* __restrict__ Ah, const __nv_bfloat16* __restrict__ Al,
    const __nv_bfloat16* __restrict__ Bh, const __nv_bfloat16* __restrict__ Bl,
    const float* __restrict__ bias, float* __restrict__ C,
    int M, int Nc, int K)
{
    extern __shared__ char smem[];
    const uint32_t sb = smem_u32(smem);

    const int tid  = threadIdx.x;
    const int wid  = tid >> 5;
    const int lane = tid & 31;
    const int warp_m = wid & 3;
    const int warp_n = wid >> 2;
    const int m0 = blockIdx.x * 128;
    const int n0 = blockIdx.y * 128;

    float acc[2][8][4];
#pragma unroll
    for (int i = 0; i < 2; i++)
#pragma unroll
        for (int j = 0; j < 8; j++)
#pragma unroll
            for (int t = 0; t < 4; t++) acc[i][j][t] = 0.f;

    const int nchunks = K >> 6;

    // ---- async fill of one stage ----
    const int frow = tid >> 1;          // 0..127
    const int fq4  = (tid & 1) * 4;     // 0 or 4 (four 16B chunks each)
    // each thread: rows frow, chunks fq4..fq4+3 on all 4 operand tiles = 16 cp.async

#define FILL(kc, stg) do {                                                       \
        uint32_t s0 = sb + (stg) * STAGE_B;                                      \
        int k0f = (kc) << 6;                                                     \
        size_t aoff = (size_t)(m0 + frow) * K + k0f + fq4 * 8;                   \
        size_t boff = (size_t)(n0 + frow) * K + k0f + fq4 * 8;                   \
        uint32_t doff = frow * SROW + fq4 * 16;                                  \
        _Pragma("unroll")                                                        \
        for (int qq = 0; qq < 4; qq++) {                                         \
            cpa16(s0 + doff + qq * 16,                Ah + aoff + qq * 8);       \
            cpa16(s0 + TILE_B + doff + qq * 16,       Al + aoff + qq * 8);       \
            cpa16(s0 + 2 * TILE_B + doff + qq * 16,   Bh + boff + qq * 8);       \
            cpa16(s0 + 3 * TILE_B + doff + qq * 16,   Bl + boff + qq * 8);       \
        }                                                                        \
        cpcommit();                                                              \
    } while (0)

    FILL(0, 0);

    for (int kc = 0; kc < nchunks; kc++) {
        if (kc + 1 < nchunks) {
            FILL(kc + 1, (kc + 1) & 1);
            asm volatile("cp.async.wait_group 1;" ::: "memory");
        } else {
            asm volatile("cp.async.wait_group 0;" ::: "memory");
        }
        __syncthreads();

        const uint32_t s0  = sb + (kc & 1) * STAGE_B;
        const uint32_t sAh = s0;
        const uint32_t sAl = s0 + TILE_B;
        const uint32_t sBh = s0 + 2 * TILE_B;
        const uint32_t sBl = s0 + 3 * TILE_B;

#pragma unroll
        for (int ks = 0; ks < 4; ks++) {
            uint32_t afh[2][4], afl[2][4];
            {
                int r  = lane & 15;
                int c8 = lane >> 4;
                uint32_t off = (uint32_t)((warp_m * 32 + r) * SROW + (ks * 16 + c8 * 8) * 2);
                ldsm4(afh[0], sAh + off);
                ldsm4(afh[1], sAh + off + 16 * SROW);
                ldsm4(afl[0], sAl + off);
                ldsm4(afl[1], sAl + off + 16 * SROW);
            }
            uint32_t bfh[8][2], bfl[8][2];
            {
                int sub = lane >> 3, wi = lane & 7;
                int n_off = (sub >> 1) * 8 + wi;
                int k_off = ks * 16 + (sub & 1) * 8;
                uint32_t base = (uint32_t)((warp_n * 64 + n_off) * SROW + k_off * 2);
#pragma unroll
                for (int jj = 0; jj < 4; jj++) {
                    uint32_t r4[4];
                    ldsm4(r4, sBh + base + jj * 16 * SROW);
                    bfh[2 * jj][0] = r4[0]; bfh[2 * jj][1] = r4[1];
                    bfh[2 * jj + 1][0] = r4[2]; bfh[2 * jj + 1][1] = r4[3];
                    ldsm4(r4, sBl + base + jj * 16 * SROW);
                    bfl[2 * jj][0] = r4[0]; bfl[2 * jj][1] = r4[1];
                    bfl[2 * jj + 1][0] = r4[2]; bfl[2 * jj + 1][1] = r4[3];
                }
            }
#pragma unroll
            for (int mi = 0; mi < 2; mi++)
#pragma unroll
                for (int j = 0; j < 8; j++) {
                    mma_bf16(acc[mi][j], afh[mi], bfh[j]);
                    mma_bf16(acc[mi][j], afh[mi], bfl[j]);
                    mma_bf16(acc[mi][j], afl[mi], bfh[j]);
                }
        }
        __syncthreads();
    }

    // ---- epilogue ----
#pragma unroll
    for (int mi = 0; mi < 2; mi++) {
        int gr = m0 + warp_m * 32 + mi * 16 + (lane >> 2);
#pragma unroll
        for (int j = 0; j < 8; j++) {
            int gc = n0 + warp_n * 64 + j * 8 + 2 * (lane & 3);
            float b0 = 0.f, b1 = 0.f;
            if (HASBIAS) { b0 = bias[gc]; b1 = bias[gc + 1]; }
            if (gr < M) {
                float2 v = make_float2(acc[mi][j][0] + b0, acc[mi][j][1] + b1);
                *reinterpret_cast<float2*>(C + (size_t)gr * Nc + gc) = v;
            }
            if (gr + 8 < M) {
                float2 v = make_float2(acc[mi][j][2] + b0, acc[mi][j][3] + b1);
                *reinterpret_cast<float2*>(C + (size_t)(gr + 8) * Nc + gc) = v;
            }
        }
    }
}

// ------------------- edge phase + pointwise -------------------
__global__ void alpha_k(const float* __restrict__ feat, const float* __restrict__ q,
                        float* __restrict__ out, int n)
{
    int warp = (blockIdx.x * blockDim.x + threadIdx.x) >> 5;
    int lane = threadIdx.x & 31;
    if (warp >= n) return;
    float4 a = *reinterpret_cast<const float4*>(feat + (long long)warp * HH + lane * 4);
    float4 b = *reinterpret_cast<const float4*>(q + lane * 4);
    float s = a.x * b.x + a.y * b.y + a.z * b.z + a.w * b.w;
#pragma unroll
    for (int o = 16; o; o >>= 1) s += __shfl_xor_sync(0xffffffffu, s, o);
    if (lane == 0) out[warp] = s;
}

__global__ void zero_k(int n)
{
    int i = blockIdx.x * blockDim.x + threadIdx.x;
    if (i < n * HH) g_AGG[i] = 0.f;
    if (i < n)      g_DEN[i] = 0.f;
}

__global__ void edge_logit_k(const int* __restrict__ ei, int E)
{
    int e = blockIdx.x * blockDim.x + threadIdx.x;
    if (e >= E) return;
    int si = ei[e];
    int ti = ei[E + e];
    float l = g_AS[si] + g_AT[ti];
    l = (l > 0.f) ? l : 0.2f * l;
    float ex = expf(l);
    g_EX[e] = ex;
    atomicAdd(&g_DEN[ti], ex);
}

__global__ void edge_scatter_k(const int* __restrict__ ei, int E)
{
    int gw   = (blockIdx.x * blockDim.x + threadIdx.x) >> 5;
    int lane = threadIdx.x & 31;
    if (gw >= E) return;
    int si = ei[gw];
    int ti = ei[E + gw];
    float c = g_EX[gw] / (g_DEN[ti] + 1e-16f);
    float4 v = *reinterpret_cast<const float4*>(g_HS + (long long)si * HH + lane * 4);
    float* dst = g_AGG + (long long)ti * HH + lane * 4;
    asm volatile("red.global.add.v4.f32 [%0], {%1,%2,%3,%4};"
                 :: "l"(dst), "f"(c * v.x), "f"(c * v.y), "f"(c * v.z), "f"(c * v.w)
                 : "memory");
}

__global__ void gru_k(float* __restrict__ out, int n)
{
    int i = blockIdx.x * blockDim.x + threadIdx.x;
    if (i >= n * HH) return;
    int nn = i / HH, h = i % HH;
    const float* gi = g_GI + (long long)nn * G3;
    const float* gh = g_GH + (long long)nn * G3;
    float r = 1.f / (1.f + expf(-(gi[h] + gh[h])));
    float z = 1.f / (1.f + expf(-(gi[HH + h] + gh[HH + h])));
    float g = tanhf(gi[2 * HH + h] + r * gh[2 * HH + h]);
    float a = g_AGG[i];
    out[i] = (1.f - z) * g + z * a;
}

__global__ void relu_copy_k(float* __restrict__ out, int total)
{
    int i = blockIdx.x * blockDim.x + threadIdx.x;
    if (i < total) out[i] = fmaxf(g_HIU[i], 0.f);
}

__global__ void sem_item_k(float* __restrict__ out, const float* __restrict__ g, int n)
{
    int warp = (blockIdx.x * blockDim.x + threadIdx.x) >> 5;
    int lane = threadIdx.x & 31;
    if (warp >= n) return;
    float4 v0 = *reinterpret_cast<const float4*>(g_HUI + (long long)warp * HH + lane * 4);
    float4 v1 = *reinterpret_cast<const float4*>(g_HII + (long long)warp * HH + lane * 4);
    float4 gv = *reinterpret_cast<const float4*>(g + lane * 4);
    float d0 = v0.x * gv.x + v0.y * gv.y + v0.z * gv.z + v0.w * gv.w;
    float d1 = v1.x * gv.x + v1.y * gv.y + v1.z * gv.z + v1.w * gv.w;
#pragma unroll
    for (int o = 16; o; o >>= 1) {
        d0 += __shfl_xor_sync(0xffffffffu, d0, o);
        d1 += __shfl_xor_sync(0xffffffffu, d1, o);
    }
    float a0 = expf(d0), a1 = expf(d1);
    float inv = 1.f / (a0 + a1);
    float w0 = a0 * inv, w1 = a1 * inv;
    float4 o4;
    o4.x = fmaxf(w0 * v0.x + w1 * v1.x, 0.f);
    o4.y = fmaxf(w0 * v0.y + w1 * v1.y, 0.f);
    o4.z = fmaxf(w0 * v0.z + w1 * v1.z, 0.f);
    o4.w = fmaxf(w0 * v0.w + w1 * v1.w, 0.f);
    *reinterpret_cast<float4*>(out + (long long)warp * HH + lane * 4) = o4;
}

// ---------------------------------------------------------------
extern "C" void kernel_launch(void* const* d_in, const int* in_sizes, int n_in,
                              void* d_out, int out_size)
{
    const float* x_user = (const float*)d_in[0];
    const float* x_item = (const float*)d_in[1];
    const int*   ei_ui  = (const int*)d_in[2];
    const int*   ei_iu  = (const int*)d_in[3];
    const int*   ei_ii  = (const int*)d_in[4];

    int N = in_sizes[0] / DD;
    int E = in_sizes[2] / 2;
    if (N > NMAX) N = NMAX;
    if (E > EMAX) E = EMAX;

    float* out = (float*)d_out;

    float *pHS, *pHT, *pAGG, *pGI, *pGH, *pAS, *pAT;
    float *pUI, *pIU, *pII;
    __nv_bfloat16 *pXUh, *pXUl, *pXIh, *pXIl, *pHTh, *pHTl, *pAGh, *pAGl;
    __nv_bfloat16 *pWTh, *pWTl, *pWGh, *pWGl;
    cudaGetSymbolAddress((void**)&pHS,  g_HS);
    cudaGetSymbolAddress((void**)&pHT,  g_HT);
    cudaGetSymbolAddress((void**)&pAGG, g_AGG);
    cudaGetSymbolAddress((void**)&pGI,  g_GI);
    cudaGetSymbolAddress((void**)&pGH,  g_GH);
    cudaGetSymbolAddress((void**)&pAS,  g_AS);
    cudaGetSymbolAddress((void**)&pAT,  g_AT);
    cudaGetSymbolAddress((void**)&pUI,  g_HUI);
    cudaGetSymbolAddress((void**)&pIU,  g_HIU);
    cudaGetSymbolAddress((void**)&pII,  g_HII);
    cudaGetSymbolAddress((void**)&pXUh, g_XUh);
    cudaGetSymbolAddress((void**)&pXUl, g_XUl);
    cudaGetSymbolAddress((void**)&pXIh, g_XIh);
    cudaGetSymbolAddress((void**)&pXIl, g_XIl);
    cudaGetSymbolAddress((void**)&pHTh, g_HTh);
    cudaGetSymbolAddress((void**)&pHTl, g_HTl);
    cudaGetSymbolAddress((void**)&pAGh, g_AGh);
    cudaGetSymbolAddress((void**)&pAGl, g_AGl);
    cudaGetSymbolAddress((void**)&pWTh, g_WTh);
    cudaGetSymbolAddress((void**)&pWTl, g_WTl);
    cudaGetSymbolAddress((void**)&pWGh, g_WGh);
    cudaGetSymbolAddress((void**)&pWGl, g_WGl);

    const int SMEMSZ = 2 * STAGE_B;  // 147456
    cudaFuncSetAttribute(mm_gemm<false>, cudaFuncAttributeMaxDynamicSharedMemorySize, SMEMSZ);
    cudaFuncSetAttribute(mm_gemm<true>,  cudaFuncAttributeMaxDynamicSharedMemorySize, SMEMSZ);

    struct RelDesc {
        const __nv_bfloat16 *ash, *asl;  // pre-split source-A for hs
        const __nv_bfloat16 *ath, *atl;  // pre-split target-A for ht
        const int* ei;
        int base;
        float* hout;
    };
    RelDesc rels[3] = {
        { pXUh, pXUl, pXIh, pXIl, ei_ui,  5, pUI },
        { pXIh, pXIl, pXUh, pXUl, ei_iu, 12, pIU },
        { pXIh, pXIl, pXIh, pXIl, ei_ii, 19, pII },
    };

    // ---- one-time splits ----
    int x4 = (N * DD) / 4;
    split_k<<<(x4 + 255) / 256, 256>>>(x_user, pXUh, pXUl, x4);
    split_k<<<(x4 + 255) / 256, 256>>>(x_item, pXIh, pXIl, x4);
    for (int r = 0; r < 3; r++) {
        const RelDesc& R = rels[r];
        prep_wt<<<128, 256>>>((const float*)d_in[R.base + 0],
                              pWTh + (r * 2 + 0) * 128 * 256, pWTl + (r * 2 + 0) * 128 * 256);
        prep_wt<<<128, 256>>>((const float*)d_in[R.base + 1],
                              pWTh + (r * 2 + 1) * 128 * 256, pWTl + (r * 2 + 1) * 128 * 256);
        prep_wg<<<192, 256>>>((const float*)d_in[R.base + 3],
                              pWGh + (r * 2 + 0) * 384 * 128, pWGl + (r * 2 + 0) * 384 * 128);
        prep_wg<<<192, 256>>>((const float*)d_in[R.base + 4],
                              pWGh + (r * 2 + 1) * 384 * 128, pWGl + (r * 2 + 1) * 384 * 128);
    }

    const int mb = (N + 127) / 128;
    dim3 gG1(mb, 1);
    dim3 gG2(mb, 3);
    int nwBlocks = (N * 32 + 255) / 256;
    int zBlocks  = (N * HH + 255) / 256;
    int e1Blocks = (E + 255) / 256;
    int e2Blocks = (E * 32 + 255) / 256;
    int h4 = (N * HH) / 4;
    int sBlocks = (h4 + 255) / 256;

    for (int r = 0; r < 3; r++) {
        const RelDesc& R = rels[r];
        const float* q   = (const float*)d_in[R.base + 2];
        const float* bih = (const float*)d_in[R.base + 5];
        const float* bhh = (const float*)d_in[R.base + 6];
        int wt0 = (r * 2 + 0) * 128 * 256;
        int wt1 = (r * 2 + 1) * 128 * 256;
        int wg0 = (r * 2 + 0) * 384 * 128;
        int wg1 = (r * 2 + 1) * 384 * 128;

        mm_gemm<false><<<gG1, 256, SMEMSZ>>>(R.ash, R.asl, pWTh + wt0, pWTl + wt0,
                                             nullptr, pHS, N, HH, DD);
        mm_gemm<false><<<gG1, 256, SMEMSZ>>>(R.ath, R.atl, pWTh + wt1, pWTl + wt1,
                                             nullptr, pHT, N, HH, DD);

        alpha_k<<<nwBlocks, 256>>>(pHS, q,      pAS, N);
        alpha_k<<<nwBlocks, 256>>>(pHT, q + HH, pAT, N);

        split_k<<<sBlocks, 256>>>(pHT, pHTh, pHTl, h4);

        zero_k<<<zBlocks, 256>>>(N);
        edge_logit_k<<<e1Blocks, 256>>>(R.ei, E);
        edge_scatter_k<<<e2Blocks, 256>>>(R.ei, E);

        split_k<<<sBlocks, 256>>>(pAGG, pAGh, pAGl, h4);

        mm_gemm<true><<<gG2, 256, SMEMSZ>>>(pHTh, pHTl, pWGh + wg0, pWGl + wg0,
                                            bih, pGI, N, G3, HH);
        mm_gemm<true><<<gG2, 256, SMEMSZ>>>(pAGh, pAGl, pWGh + wg1, pWGl + wg1,
                                            bhh, pGH, N, G3, HH);

        gru_k<<<zBlocks, 256>>>(R.hout, N);
    }

    relu_copy_k<<<zBlocks, 256>>>(out, N * HH);
    const float* g_item = (const float*)d_in[27];
    sem_item_k<<<(N + 7) / 8, 256>>>(out + (long long)N * HH, g_item, N);
}

// round 5
// speedup vs baseline: 1.5005x; 1.5005x over previous
#include <cuda_runtime.h>
#include <cuda_bf16.h>
#include <math.h>
#include <cstdint>

#define NMAX 50000
#define NPAD 50176   // 392*128
#define EMAX 400000
#define DD   256
#define HH   128
#define G3   384
#define SROW 144                 // smem bytes per 64-bf16 row (+16B pad)
#define TILE_B (128 * SROW)      // 18432
#define SMEMSZ (4 * TILE_B)      // 73728

// ------------------- scratch -------------------
__device__ __align__(16) float g_HS [3][NPAD*HH];
__device__ __align__(16) float g_HT [3][NPAD*HH];
__device__ __align__(16) float g_AGG[3][NPAD*HH];
__device__ __align__(16) float g_GI [3][NPAD*G3];
__device__ __align__(16) float g_GH [3][NPAD*G3];
__device__ __align__(16) float g_AS [3][NMAX];
__device__ __align__(16) float g_AT [3][NMAX];
__device__ __align__(16) float g_DEN[3][NMAX];
__device__ __align__(16) float g_EX [3][EMAX];
__device__ __align__(16) float g_HOUT[3][NPAD*HH];
__device__ __align__(16) __nv_bfloat16 g_XUh[NPAD*DD], g_XUl[NPAD*DD];
__device__ __align__(16) __nv_bfloat16 g_XIh[NPAD*DD], g_XIl[NPAD*DD];
__device__ __align__(16) __nv_bfloat16 g_HTh[3][NPAD*HH], g_HTl[3][NPAD*HH];
__device__ __align__(16) __nv_bfloat16 g_AGh[3][NPAD*HH], g_AGl[3][NPAD*HH];
__device__ __align__(16) __nv_bfloat16 g_WTh[6][128*DD], g_WTl[6][128*DD];
__device__ __align__(16) __nv_bfloat16 g_WGh[6][G3*HH],  g_WGl[6][G3*HH];

// ------------------- PTX helpers -------------------
__device__ __forceinline__ uint32_t smem_u32(const void* p) {
    uint32_t a;
    asm("{ .reg .u64 t; cvta.to.shared.u64 t, %1; cvt.u32.u64 %0, t; }" : "=r"(a) : "l"(p));
    return a;
}
__device__ __forceinline__ void ldsm4(uint32_t* r, uint32_t addr) {
    asm volatile("ldmatrix.sync.aligned.m8n8.x4.shared.b16 {%0,%1,%2,%3}, [%4];"
                 : "=r"(r[0]), "=r"(r[1]), "=r"(r[2]), "=r"(r[3]) : "r"(addr));
}
__device__ __forceinline__ void mma_bf16(float* d, const uint32_t* a, const uint32_t* b) {
    asm volatile(
        "mma.sync.aligned.m16n8k16.row.col.f32.bf16.bf16.f32 "
        "{%0,%1,%2,%3}, {%4,%5,%6,%7}, {%8,%9}, {%0,%1,%2,%3};"
        : "+f"(d[0]), "+f"(d[1]), "+f"(d[2]), "+f"(d[3])
        : "r"(a[0]), "r"(a[1]), "r"(a[2]), "r"(a[3]), "r"(b[0]), "r"(b[1]));
}
__device__ __forceinline__ void cpa16(uint32_t dst, const void* src) {
    asm volatile("cp.async.cg.shared.global [%0], [%1], 16;" :: "r"(dst), "l"(src));
}

__device__ __forceinline__ void split4(float4 v, uint2& hp, uint2& lp) {
    __nv_bfloat16 h0 = __float2bfloat16(v.x), h1 = __float2bfloat16(v.y);
    __nv_bfloat16 h2 = __float2bfloat16(v.z), h3 = __float2bfloat16(v.w);
    hp.x = ((uint32_t)__bfloat16_as_ushort(h1) << 16) | __bfloat16_as_ushort(h0);
    hp.y = ((uint32_t)__bfloat16_as_ushort(h3) << 16) | __bfloat16_as_ushort(h2);
    __nv_bfloat16 l0 = __float2bfloat16(v.x - __bfloat162float(h0));
    __nv_bfloat16 l1 = __float2bfloat16(v.y - __bfloat162float(h1));
    __nv_bfloat16 l2 = __float2bfloat16(v.z - __bfloat162float(h2));
    __nv_bfloat16 l3 = __float2bfloat16(v.w - __bfloat162float(h3));
    lp.x = ((uint32_t)__bfloat16_as_ushort(l1) << 16) | __bfloat16_as_ushort(l0);
    lp.y = ((uint32_t)__bfloat16_as_ushort(l3) << 16) | __bfloat16_as_ushort(l2);
}

// ------------------- prep kernels -------------------
// split x_user/x_item -> bf16 hi/lo (vector-of-4)
__global__ void split_x_k(const float* __restrict__ xu, const float* __restrict__ xi, int n4)
{
    int i = blockIdx.x * blockDim.x + threadIdx.x;
    if (i >= 2 * n4) return;
    const float* src = (i < n4) ? xu : xi;
    int j = (i < n4) ? i : i - n4;
    float4 v = reinterpret_cast<const float4*>(src)[j];
    uint2 hp, lp;
    split4(v, hp, lp);
    if (i < n4) {
        reinterpret_cast<uint2*>(g_XUh)[j] = hp;
        reinterpret_cast<uint2*>(g_XUl)[j] = lp;
    } else {
        reinterpret_cast<uint2*>(g_XIh)[j] = hp;
        reinterpret_cast<uint2*>(g_XIl)[j] = lp;
    }
}
// transpose+split 6 x w[256][128] -> [128][256]
__global__ void prep_wt_all(const float* w0, const float* w1, const float* w2,
                            const float* w3, const float* w4, const float* w5)
{
    const float* ws[6] = {w0, w1, w2, w3, w4, w5};
    int i = blockIdx.x * blockDim.x + threadIdx.x;
    if (i >= 6 * 128 * 256) return;
    int z = i >> 15, j = i & 32767;
    int n = j >> 8, k = j & 255;
    float x = ws[z][k * 128 + n];
    __nv_bfloat16 h = __float2bfloat16(x);
    g_WTh[z][j] = h;
    g_WTl[z][j] = __float2bfloat16(x - __bfloat162float(h));
}
// split 6 x w[384][128]
__global__ void prep_wg_all(const float* w0, const float* w1, const float* w2,
                            const float* w3, const float* w4, const float* w5)
{
    const float* ws[6] = {w0, w1, w2, w3, w4, w5};
    int i = blockIdx.x * blockDim.x + threadIdx.x;
    if (i >= 6 * G3 * HH) return;
    int z = i / (G3 * HH), j = i % (G3 * HH);
    float x = ws[z][j];
    __nv_bfloat16 h = __float2bfloat16(x);
    g_WGh[z][j] = h;
    g_WGl[z][j] = __float2bfloat16(x - __bfloat162float(h));
}
// split HT[3] and AGG[3] -> bf16 hi/lo
__global__ void split6_k(int n4)   // n4 = NPAD*HH/4
{
    long long i = (long long)blockIdx.x * blockDim.x + threadIdx.x;
    if (i >= 6LL * n4) return;
    int z = (int)(i / n4), j = (int)(i % n4);
    const float* src = (z < 3) ? g_HT[z] : g_AGG[z - 3];
    float4 v = reinterpret_cast<const float4*>(src)[j];
    uint2 hp, lp;
    split4(v, hp, lp);
    __nv_bfloat16* dh = (z < 3) ? g_HTh[z] : g_AGh[z - 3];
    __nv_bfloat16* dl = (z < 3) ? g_HTl[z] : g_AGl[z - 3];
    reinterpret_cast<uint2*>(dh)[j] = hp;
    reinterpret_cast<uint2*>(dl)[j] = lp;
}

// ------------------- shared GEMM core (bf16-split, mma.sync) -------------------
// 128x128 CTA tile, BK=64, 8 warps of 32x64. Single-stage smem, cp.async fill.
struct GemmPtrs {
    const __nv_bfloat16 *Ah, *Al, *Bh, *Bl;
    const float* bias;
    float* C;
};

__device__ __forceinline__ void gemm_core(const GemmPtrs& P, int M, int Nc, int K,
                                          int m0, int n0, char* smem)
{
    const uint32_t sb = smem_u32(smem);
    const int tid  = threadIdx.x;
    const int wid  = tid >> 5;
    const int lane = tid & 31;
    const int warp_m = wid & 3;
    const int warp_n = wid >> 2;

    float acc[2][8][4];
#pragma unroll
    for (int i = 0; i < 2; i++)
#pragma unroll
        for (int j = 0; j < 8; j++)
#pragma unroll
            for (int t = 0; t < 4; t++) acc[i][j][t] = 0.f;

    const int nchunks = K >> 6;
    for (int kc = 0; kc < nchunks; kc++) {
        const int k0 = kc << 6;
        // fill: 4096 x 16B cp.async, 16 per thread
#pragma unroll
        for (int it = 0; it < 16; it++) {
            int s = tid + it * 256;
            int tile = s >> 10, w = s & 1023, row = w >> 3, q = w & 7;
            uint32_t dst = sb + tile * TILE_B + row * SROW + q * 16;
            const __nv_bfloat16* src;
            size_t off;
            if (tile < 2) {
                src = (tile == 0) ? P.Ah : P.Al;
                off = (size_t)(m0 + row) * K + k0 + q * 8;
            } else {
                src = (tile == 2) ? P.Bh : P.Bl;
                off = (size_t)(n0 + row) * K + k0 + q * 8;
            }
            cpa16(dst, src + off);
        }
        asm volatile("cp.async.commit_group;" ::: "memory");
        asm volatile("cp.async.wait_group 0;" ::: "memory");
        __syncthreads();

        const uint32_t sAh = sb;
        const uint32_t sAl = sb + TILE_B;
        const uint32_t sBh = sb + 2 * TILE_B;
        const uint32_t sBl = sb + 3 * TILE_B;

#pragma unroll
        for (int ks = 0; ks < 4; ks++) {
            uint32_t afh[2][4], afl[2][4];
            {
                int r  = lane & 15;
                int c8 = lane >> 4;
                uint32_t off = (uint32_t)((warp_m * 32 + r) * SROW + (ks * 16 + c8 * 8) * 2);
                ldsm4(afh[0], sAh + off);
                ldsm4(afh[1], sAh + off + 16 * SROW);
                ldsm4(afl[0], sAl + off);
                ldsm4(afl[1], sAl + off + 16 * SROW);
            }
            uint32_t bfh[8][2], bfl[8][2];
            {
                int sub = lane >> 3, wi = lane & 7;
                int n_off = (sub >> 1) * 8 + wi;
                int k_off = ks * 16 + (sub & 1) * 8;
                uint32_t base = (uint32_t)((warp_n * 64 + n_off) * SROW + k_off * 2);
#pragma unroll
                for (int jj = 0; jj < 4; jj++) {
                    uint32_t r4[4];
                    ldsm4(r4, sBh + base + jj * 16 * SROW);
                    bfh[2 * jj][0] = r4[0]; bfh[2 * jj][1] = r4[1];
                    bfh[2 * jj + 1][0] = r4[2]; bfh[2 * jj + 1][1] = r4[3];
                    ldsm4(r4, sBl + base + jj * 16 * SROW);
                    bfl[2 * jj][0] = r4[0]; bfl[2 * jj][1] = r4[1];
                    bfl[2 * jj + 1][0] = r4[2]; bfl[2 * jj + 1][1] = r4[3];
                }
            }
#pragma unroll
            for (int mi = 0; mi < 2; mi++)
#pragma unroll
                for (int j = 0; j < 8; j++) {
                    mma_bf16(acc[mi][j], afh[mi], bfh[j]);
                    mma_bf16(acc[mi][j], afh[mi], bfl[j]);
                    mma_bf16(acc[mi][j], afl[mi], bfh[j]);
                }
        }
        __syncthreads();
    }

#pragma unroll
    for (int mi = 0; mi < 2; mi++) {
        int gr = m0 + warp_m * 32 + mi * 16 + (lane >> 2);
#pragma unroll
        for (int j = 0; j < 8; j++) {
            int gc = n0 + warp_n * 64 + j * 8 + 2 * (lane & 3);
            float b0 = 0.f, b1 = 0.f;
            if (P.bias) { b0 = P.bias[gc]; b1 = P.bias[gc + 1]; }
            if (gr < M) {
                float2 v = make_float2(acc[mi][j][0] + b0, acc[mi][j][1] + b1);
                *reinterpret_cast<float2*>(P.C + (size_t)gr * Nc + gc) = v;
            }
            if (gr + 8 < M) {
                float2 v = make_float2(acc[mi][j][2] + b0, acc[mi][j][3] + b1);
                *reinterpret_cast<float2*>(P.C + (size_t)(gr + 8) * Nc + gc) = v;
            }
        }
    }
}

// batched hs/ht: grid(392,1,6), K=256, Nc=128
__global__ void __launch_bounds__(256) hsht_gemm(int M)
{
    extern __shared__ char smem[];
    int z = blockIdx.z, r = z >> 1;
    const __nv_bfloat16* Ah[6] = {g_XUh, g_XIh, g_XIh, g_XUh, g_XIh, g_XIh};
    const __nv_bfloat16* Al[6] = {g_XUl, g_XIl, g_XIl, g_XUl, g_XIl, g_XIl};
    GemmPtrs P;
    P.Ah = Ah[z]; P.Al = Al[z];
    P.Bh = g_WTh[z]; P.Bl = g_WTl[z];
    P.bias = nullptr;
    P.C = (z & 1) ? g_HT[r] : g_HS[r];
    gemm_core(P, M, HH, DD, blockIdx.x * 128, 0, smem);
}

// batched GRU gates: grid(392,3,6), K=128, Nc=384
__global__ void __launch_bounds__(256) gru_gemm(
    int M,
    const float* b0, const float* b1, const float* b2,
    const float* b3, const float* b4, const float* b5)
{
    extern __shared__ char smem[];
    int z = blockIdx.z, r = z >> 1, which = z & 1;
    const float* biases[6] = {b0, b1, b2, b3, b4, b5};
    GemmPtrs P;
    P.Ah = which ? g_AGh[r] : g_HTh[r];
    P.Al = which ? g_AGl[r] : g_HTl[r];
    P.Bh = g_WGh[z]; P.Bl = g_WGl[z];
    P.bias = biases[z];
    P.C = which ? g_GH[r] : g_GI[r];
    gemm_core(P, M, G3, HH, blockIdx.x * 128, blockIdx.y * 128, smem);
}

// ------------------- batched edge / pointwise -------------------
__global__ void alpha_all(const float* q0, const float* q1, const float* q2, int n)
{
    int gw = (blockIdx.x * blockDim.x + threadIdx.x) >> 5;
    int lane = threadIdx.x & 31;
    if (gw >= 6 * n) return;
    int sel = gw / n, node = gw - sel * n;
    int r = sel >> 1, which = sel & 1;
    const float* qs[3] = {q0, q1, q2};
    const float* feat = which ? g_HT[r] : g_HS[r];
    const float* q = qs[r] + which * HH;
    float4 a = *reinterpret_cast<const float4*>(feat + (size_t)node * HH + lane * 4);
    float4 b = *reinterpret_cast<const float4*>(q + lane * 4);
    float s = a.x * b.x + a.y * b.y + a.z * b.z + a.w * b.w;
#pragma unroll
    for (int o = 16; o; o >>= 1) s += __shfl_xor_sync(0xffffffffu, s, o);
    if (lane == 0) {
        if (which) g_AT[r][node] = s;
        else       g_AS[r][node] = s;
    }
}

__global__ void zero_all(int n)
{
    long long i = (long long)blockIdx.x * blockDim.x + threadIdx.x;
    if (i < 3LL * NPAD * HH) (&g_AGG[0][0])[i] = 0.f;
    if (i < 3LL * n)         (&g_DEN[0][0])[i] = 0.f;
}

__global__ void edge_logit_all(const int* e0, const int* e1, const int* e2, int E)
{
    int e = blockIdx.x * blockDim.x + threadIdx.x;
    if (e >= 3 * E) return;
    int r = e / E, le = e - r * E;
    const int* ei = (r == 0) ? e0 : (r == 1) ? e1 : e2;
    int si = ei[le];
    int ti = ei[E + le];
    float l = g_AS[r][si] + g_AT[r][ti];
    l = (l > 0.f) ? l : 0.2f * l;
    float ex = expf(l);
    g_EX[r][le] = ex;
    atomicAdd(&g_DEN[r][ti], ex);
}

__global__ void edge_scatter_all(const int* e0, const int* e1, const int* e2, int E)
{
    int gw   = (blockIdx.x * blockDim.x + threadIdx.x) >> 5;
    int lane = threadIdx.x & 31;
    if (gw >= 3 * E) return;
    int r = gw / E, le = gw - r * E;
    const int* ei = (r == 0) ? e0 : (r == 1) ? e1 : e2;
    int si = ei[le];
    int ti = ei[E + le];
    float c = g_EX[r][le] / (g_DEN[r][ti] + 1e-16f);
    float4 v = *reinterpret_cast<const float4*>(g_HS[r] + (size_t)si * HH + lane * 4);
    float* dst = g_AGG[r] + (size_t)ti * HH + lane * 4;
    asm volatile("red.global.add.v4.f32 [%0], {%1,%2,%3,%4};"
                 :: "l"(dst), "f"(c * v.x), "f"(c * v.y), "f"(c * v.z), "f"(c * v.w)
                 : "memory");
}

__global__ void gru_all(int n)
{
    long long i = (long long)blockIdx.x * blockDim.x + threadIdx.x;
    if (i >= 3LL * n * HH) return;
    int r = (int)(i / ((long long)n * HH));
    int j = (int)(i - (long long)r * n * HH);
    int nn = j / HH, h = j - nn * HH;
    const float* gi = g_GI[r] + (size_t)nn * G3;
    const float* gh = g_GH[r] + (size_t)nn * G3;
    float rr = 1.f / (1.f + expf(-(gi[h] + gh[h])));
    float z  = 1.f / (1.f + expf(-(gi[HH + h] + gh[HH + h])));
    float g  = tanhf(gi[2 * HH + h] + rr * gh[2 * HH + h]);
    float a  = g_AGG[r][(size_t)nn * HH + h];
    g_HOUT[r][j] = (1.f - z) * g + z * a;
}

// out_user = relu(HOUT[1]); out_item = relu(sem_att(HOUT[0], HOUT[2], g_item))
__global__ void final_k(float* __restrict__ out, const float* __restrict__ g, int n)
{
    int warp = (blockIdx.x * blockDim.x + threadIdx.x) >> 5;
    int lane = threadIdx.x & 31;
    if (warp >= n) return;
    size_t off = (size_t)warp * HH + lane * 4;
    // user
    float4 u = *reinterpret_cast<const float4*>(g_HOUT[1] + off);
    u.x = fmaxf(u.x, 0.f); u.y = fmaxf(u.y, 0.f);
    u.z = fmaxf(u.z, 0.f); u.w = fmaxf(u.w, 0.f);
    *reinterpret_cast<float4*>(out + off) = u;
    // item
    float4 v0 = *reinterpret_cast<const float4*>(g_HOUT[0] + off);
    float4 v1 = *reinterpret_cast<const float4*>(g_HOUT[2] + off);
    float4 gv = *reinterpret_cast<const float4*>(g + lane * 4);
    float d0 = v0.x * gv.x + v0.y * gv.y + v0.z * gv.z + v0.w * gv.w;
    float d1 = v1.x * gv.x + v1.y * gv.y + v1.z * gv.z + v1.w * gv.w;
#pragma unroll
    for (int o = 16; o; o >>= 1) {
        d0 += __shfl_xor_sync(0xffffffffu, d0, o);
        d1 += __shfl_xor_sync(0xffffffffu, d1, o);
    }
    float a0 = expf(d0), a1 = expf(d1);
    float inv = 1.f / (a0 + a1);
    float w0 = a0 * inv, w1 = a1 * inv;
    float4 o4;
    o4.x = fmaxf(w0 * v0.x + w1 * v1.x, 0.f);
    o4.y = fmaxf(w0 * v0.y + w1 * v1.y, 0.f);
    o4.z = fmaxf(w0 * v0.z + w1 * v1.z, 0.f);
    o4.w = fmaxf(w0 * v0.w + w1 * v1.w, 0.f);
    *reinterpret_cast<float4*>(out + (size_t)n * HH + off) = o4;
}

// ---------------------------------------------------------------
extern "C" void kernel_launch(void* const* d_in, const int* in_sizes, int n_in,
                              void* d_out, int out_size)
{
    const float* x_user = (const float*)d_in[0];
    const float* x_item = (const float*)d_in[1];
    const int*   ei_ui  = (const int*)d_in[2];
    const int*   ei_iu  = (const int*)d_in[3];
    const int*   ei_ii  = (const int*)d_in[4];

    int N = in_sizes[0] / DD;
    int E = in_sizes[2] / 2;
    if (N > NMAX) N = NMAX;
    if (E > EMAX) E = EMAX;

    float* out = (float*)d_out;

    cudaFuncSetAttribute(hsht_gemm, cudaFuncAttributeMaxDynamicSharedMemorySize, SMEMSZ);
    cudaFuncSetAttribute(gru_gemm,  cudaFuncAttributeMaxDynamicSharedMemorySize, SMEMSZ);

    // ---- prep: splits ----
    int x4 = (N * DD) / 4;
    split_x_k<<<(2 * x4 + 255) / 256, 256>>>(x_user, x_item, x4);
    prep_wt_all<<<(6 * 128 * 256 + 255) / 256, 256>>>(
        (const float*)d_in[5],  (const float*)d_in[6],
        (const float*)d_in[12], (const float*)d_in[13],
        (const float*)d_in[19], (const float*)d_in[20]);
    prep_wg_all<<<(6 * G3 * HH + 255) / 256, 256>>>(
        (const float*)d_in[8],  (const float*)d_in[9],
        (const float*)d_in[15], (const float*)d_in[16],
        (const float*)d_in[22], (const float*)d_in[23]);

    const int mb = NPAD / 128;   // 392

    // ---- all 6 hs/ht GEMMs ----
    hsht_gemm<<<dim3(mb, 1, 6), 256, SMEMSZ>>>(N);

    // ---- alpha scalars (6 sets) ----
    int aBlocks = (int)(((long long)6 * N * 32 + 255) / 256);
    alpha_all<<<aBlocks, 256>>>((const float*)d_in[7], (const float*)d_in[14],
                                (const float*)d_in[21], N);

    // ---- zero agg/den ----
    long long ztot = 3LL * NPAD * HH;
    zero_all<<<(int)((ztot + 255) / 256), 256>>>(N);

    // ---- edge phase (3 relations batched) ----
    edge_logit_all<<<(3 * E + 255) / 256, 256>>>(ei_ui, ei_iu, ei_ii, E);
    int sBlocks = (int)(((long long)3 * E * 32 + 255) / 256);
    edge_scatter_all<<<sBlocks, 256>>>(ei_ui, ei_iu, ei_ii, E);

    // ---- split HT + AGG to bf16 ----
    int n4 = NPAD * HH / 4;
    split6_k<<<(int)((6LL * n4 + 255) / 256), 256>>>(n4);

    // ---- all 6 GRU gate GEMMs ----
    gru_gemm<<<dim3(mb, 3, 6), 256, SMEMSZ>>>(
        N,
        (const float*)d_in[10], (const float*)d_in[11],
        (const float*)d_in[17], (const float*)d_in[18],
        (const float*)d_in[24], (const float*)d_in[25]);

    // ---- GRU combine (3 relations) ----
    gru_all<<<(int)((3LL * N * HH + 255) / 256), 256>>>(N);

    // ---- final outputs ----
    final_k<<<(N * 32 + 255) / 256, 256>>>(out, (const float*)d_in[27], N);
}

// round 6
// speedup vs baseline: 1.5044x; 1.0026x over previous
#include <cuda_runtime.h>
#include <cuda_bf16.h>
#include <math.h>
#include <cstdint>

#define NMAX 50000
#define NPAD 50176   // 392*128
#define EMAX 400000
#define DD   256
#define HH   128
#define G3   384
#define SROW 80                  // smem bytes per 32-bf16 row (64B + 16B pad)
#define TILE_B (128 * SROW)      // 10240
#define STAGE_B (4 * TILE_B)     // 40960
#define SMEMSZ (2 * STAGE_B)     // 81920

// ------------------- scratch -------------------
__device__ __align__(16) float g_HS [3][NPAD*HH];
__device__ __align__(16) float g_HT [3][NPAD*HH];
__device__ __align__(16) float g_AGG[3][NPAD*HH];
__device__ __align__(16) float g_GI [3][NPAD*G3];
__device__ __align__(16) float g_GH [3][NPAD*G3];
__device__ __align__(16) float g_AS [3][NMAX];
__device__ __align__(16) float g_AT [3][NMAX];
__device__ __align__(16) float g_DEN[3][NMAX];
__device__ __align__(16) float g_EX [3][EMAX];
__device__ __align__(16) float g_HOUT[3][NPAD*HH];
__device__ __align__(16) __nv_bfloat16 g_XUh[NPAD*DD], g_XUl[NPAD*DD];
__device__ __align__(16) __nv_bfloat16 g_XIh[NPAD*DD], g_XIl[NPAD*DD];
__device__ __align__(16) __nv_bfloat16 g_HTh[3][NPAD*HH], g_HTl[3][NPAD*HH];
__device__ __align__(16) __nv_bfloat16 g_AGh[3][NPAD*HH], g_AGl[3][NPAD*HH];
__device__ __align__(16) __nv_bfloat16 g_WTh[6][128*DD], g_WTl[6][128*DD];
__device__ __align__(16) __nv_bfloat16 g_WGh[6][G3*HH],  g_WGl[6][G3*HH];

// ------------------- PTX helpers -------------------
__device__ __forceinline__ uint32_t smem_u32(const void* p) {
    uint32_t a;
    asm("{ .reg .u64 t; cvta.to.shared.u64 t, %1; cvt.u32.u64 %0, t; }" : "=r"(a) : "l"(p));
    return a;
}
__device__ __forceinline__ void ldsm4(uint32_t* r, uint32_t addr) {
    asm volatile("ldmatrix.sync.aligned.m8n8.x4.shared.b16 {%0,%1,%2,%3}, [%4];"
                 : "=r"(r[0]), "=r"(r[1]), "=r"(r[2]), "=r"(r[3]) : "r"(addr));
}
__device__ __forceinline__ void mma_bf16(float* d, const uint32_t* a, const uint32_t* b) {
    asm volatile(
        "mma.sync.aligned.m16n8k16.row.col.f32.bf16.bf16.f32 "
        "{%0,%1,%2,%3}, {%4,%5,%6,%7}, {%8,%9}, {%0,%1,%2,%3};"
        : "+f"(d[0]), "+f"(d[1]), "+f"(d[2]), "+f"(d[3])
        : "r"(a[0]), "r"(a[1]), "r"(a[2]), "r"(a[3]), "r"(b[0]), "r"(b[1]));
}
__device__ __forceinline__ void cpa16(uint32_t dst, const void* src) {
    asm volatile("cp.async.cg.shared.global [%0], [%1], 16;" :: "r"(dst), "l"(src));
}
__device__ __forceinline__ void split4(float4 v, uint2& hp, uint2& lp) {
    __nv_bfloat16 h0 = __float2bfloat16(v.x), h1 = __float2bfloat16(v.y);
    __nv_bfloat16 h2 = __float2bfloat16(v.z), h3 = __float2bfloat16(v.w);
    hp.x = ((uint32_t)__bfloat16_as_ushort(h1) << 16) | __bfloat16_as_ushort(h0);
    hp.y = ((uint32_t)__bfloat16_as_ushort(h3) << 16) | __bfloat16_as_ushort(h2);
    __nv_bfloat16 l0 = __float2bfloat16(v.x - __bfloat162float(h0));
    __nv_bfloat16 l1 = __float2bfloat16(v.y - __bfloat162float(h1));
    __nv_bfloat16 l2 = __float2bfloat16(v.z - __bfloat162float(h2));
    __nv_bfloat16 l3 = __float2bfloat16(v.w - __bfloat162float(h3));
    lp.x = ((uint32_t)__bfloat16_as_ushort(l1) << 16) | __bfloat16_as_ushort(l0);
    lp.y = ((uint32_t)__bfloat16_as_ushort(l3) << 16) | __bfloat16_as_ushort(l2);
}

// ------------------- prep kernels -------------------
__global__ void split_x_k(const float* __restrict__ xu, const float* __restrict__ xi, int n4)
{
    int i = blockIdx.x * blockDim.x + threadIdx.x;
    if (i >= 2 * n4) return;
    const float* src = (i < n4) ? xu : xi;
    int j = (i < n4) ? i : i - n4;
    float4 v = reinterpret_cast<const float4*>(src)[j];
    uint2 hp, lp;
    split4(v, hp, lp);
    if (i < n4) {
        reinterpret_cast<uint2*>(g_XUh)[j] = hp;
        reinterpret_cast<uint2*>(g_XUl)[j] = lp;
    } else {
        reinterpret_cast<uint2*>(g_XIh)[j] = hp;
        reinterpret_cast<uint2*>(g_XIl)[j] = lp;
    }
}
__global__ void prep_wt_all(const float* w0, const float* w1, const float* w2,
                            const float* w3, const float* w4, const float* w5)
{
    const float* ws[6] = {w0, w1, w2, w3, w4, w5};
    int i = blockIdx.x * blockDim.x + threadIdx.x;
    if (i >= 6 * 128 * 256) return;
    int z = i >> 15, j = i & 32767;
    int n = j >> 8, k = j & 255;
    float x = ws[z][k * 128 + n];
    __nv_bfloat16 h = __float2bfloat16(x);
    g_WTh[z][j] = h;
    g_WTl[z][j] = __float2bfloat16(x - __bfloat162float(h));
}
__global__ void prep_wg_all(const float* w0, const float* w1, const float* w2,
                            const float* w3, const float* w4, const float* w5)
{
    const float* ws[6] = {w0, w1, w2, w3, w4, w5};
    int i = blockIdx.x * blockDim.x + threadIdx.x;
    if (i >= 6 * G3 * HH) return;
    int z = i / (G3 * HH), j = i % (G3 * HH);
    float x = ws[z][j];
    __nv_bfloat16 h = __float2bfloat16(x);
    g_WGh[z][j] = h;
    g_WGl[z][j] = __float2bfloat16(x - __bfloat162float(h));
}
__global__ void split6_k(int n4)   // n4 = NPAD*HH/4
{
    long long i = (long long)blockIdx.x * blockDim.x + threadIdx.x;
    if (i >= 6LL * n4) return;
    int z = (int)(i / n4), j = (int)(i % n4);
    const float* src = (z < 3) ? g_HT[z] : g_AGG[z - 3];
    float4 v = reinterpret_cast<const float4*>(src)[j];
    uint2 hp, lp;
    split4(v, hp, lp);
    __nv_bfloat16* dh = (z < 3) ? g_HTh[z] : g_AGh[z - 3];
    __nv_bfloat16* dl = (z < 3) ? g_HTl[z] : g_AGl[z - 3];
    reinterpret_cast<uint2*>(dh)[j] = hp;
    reinterpret_cast<uint2*>(dl)[j] = lp;
}

// ------------------- pipelined GEMM core (BK=32, 2-stage) -------------------
struct GemmPtrs {
    const __nv_bfloat16 *Ah, *Al, *Bh, *Bl;
    const float* bias;
    float* C;
};

__device__ __forceinline__ void gemm_core(const GemmPtrs& P, int M, int Nc, int K,
                                          int m0, int n0, char* smem)
{
    const uint32_t sb = smem_u32(smem);
    const int tid  = threadIdx.x;
    const int wid  = tid >> 5;
    const int lane = tid & 31;
    const int warp_m = wid & 3;
    const int warp_n = wid >> 2;

    float acc[2][8][4];
#pragma unroll
    for (int i = 0; i < 2; i++)
#pragma unroll
        for (int j = 0; j < 8; j++)
#pragma unroll
            for (int t = 0; t < 4; t++) acc[i][j][t] = 0.f;

    const int nchunks = K >> 5;

    // per-thread fill assignment: 2048 cp.async / 256 threads = 8
    // s = tid + it*256; tile = s>>9; w = s&511; row = w>>2; q = w&3
#define FILL(kc, stg) do {                                                      \
        const int k0f = (kc) << 5;                                              \
        const uint32_t s0 = sb + (stg) * STAGE_B;                               \
        _Pragma("unroll")                                                       \
        for (int it = 0; it < 8; it++) {                                        \
            int s = tid + it * 256;                                             \
            int tile = s >> 9, w = s & 511, row = w >> 2, q = w & 3;            \
            uint32_t dst = s0 + tile * TILE_B + row * SROW + q * 16;            \
            const __nv_bfloat16* src;                                           \
            size_t off;                                                         \
            if (tile < 2) {                                                     \
                src = (tile == 0) ? P.Ah : P.Al;                                \
                off = (size_t)(m0 + row) * K + k0f + q * 8;                     \
            } else {                                                            \
                src = (tile == 2) ? P.Bh : P.Bl;                                \
                off = (size_t)(n0 + row) * K + k0f + q * 8;                     \
            }                                                                   \
            cpa16(dst, src + off);                                              \
        }                                                                       \
        asm volatile("cp.async.commit_group;" ::: "memory");                    \
    } while (0)

    FILL(0, 0);

    for (int kc = 0; kc < nchunks; kc++) {
        if (kc + 1 < nchunks) {
            FILL(kc + 1, (kc + 1) & 1);
            asm volatile("cp.async.wait_group 1;" ::: "memory");
        } else {
            asm volatile("cp.async.wait_group 0;" ::: "memory");
        }
        __syncthreads();

        const uint32_t s0  = sb + (kc & 1) * STAGE_B;
        const uint32_t sAh = s0;
        const uint32_t sAl = s0 + TILE_B;
        const uint32_t sBh = s0 + 2 * TILE_B;
        const uint32_t sBl = s0 + 3 * TILE_B;

#pragma unroll
        for (int ks = 0; ks < 2; ks++) {
            uint32_t afh[2][4], afl[2][4];
            {
                int r  = lane & 15;
                int c8 = lane >> 4;
                uint32_t off = (uint32_t)((warp_m * 32 + r) * SROW + (ks * 16 + c8 * 8) * 2);
                ldsm4(afh[0], sAh + off);
                ldsm4(afh[1], sAh + off + 16 * SROW);
                ldsm4(afl[0], sAl + off);
                ldsm4(afl[1], sAl + off + 16 * SROW);
            }
            uint32_t bfh[8][2], bfl[8][2];
            {
                int sub = lane >> 3, wi = lane & 7;
                int n_off = (sub >> 1) * 8 + wi;
                int k_off = ks * 16 + (sub & 1) * 8;
                uint32_t base = (uint32_t)((warp_n * 64 + n_off) * SROW + k_off * 2);
#pragma unroll
                for (int jj = 0; jj < 4; jj++) {
                    uint32_t r4[4];
                    ldsm4(r4, sBh + base + jj * 16 * SROW);
                    bfh[2 * jj][0] = r4[0]; bfh[2 * jj][1] = r4[1];
                    bfh[2 * jj + 1][0] = r4[2]; bfh[2 * jj + 1][1] = r4[3];
                    ldsm4(r4, sBl + base + jj * 16 * SROW);
                    bfl[2 * jj][0] = r4[0]; bfl[2 * jj][1] = r4[1];
                    bfl[2 * jj + 1][0] = r4[2]; bfl[2 * jj + 1][1] = r4[3];
                }
            }
#pragma unroll
            for (int mi = 0; mi < 2; mi++)
#pragma unroll
                for (int j = 0; j < 8; j++) {
                    mma_bf16(acc[mi][j], afh[mi], bfh[j]);
                    mma_bf16(acc[mi][j], afh[mi], bfl[j]);
                    mma_bf16(acc[mi][j], afl[mi], bfh[j]);
                }
        }
        __syncthreads();
    }
#undef FILL

#pragma unroll
    for (int mi = 0; mi < 2; mi++) {
        int gr = m0 + warp_m * 32 + mi * 16 + (lane >> 2);
#pragma unroll
        for (int j = 0; j < 8; j++) {
            int gc = n0 + warp_n * 64 + j * 8 + 2 * (lane & 3);
            float b0 = 0.f, b1 = 0.f;
            if (P.bias) { b0 = P.bias[gc]; b1 = P.bias[gc + 1]; }
            if (gr < M) {
                float2 v = make_float2(acc[mi][j][0] + b0, acc[mi][j][1] + b1);
                *reinterpret_cast<float2*>(P.C + (size_t)gr * Nc + gc) = v;
            }
            if (gr + 8 < M) {
                float2 v = make_float2(acc[mi][j][2] + b0, acc[mi][j][3] + b1);
                *reinterpret_cast<float2*>(P.C + (size_t)(gr + 8) * Nc + gc) = v;
            }
        }
    }
}

// batched hs/ht: grid(392,1,6), K=256, Nc=128
__global__ void __launch_bounds__(256) hsht_gemm(int M)
{
    extern __shared__ char smem[];
    int z = blockIdx.z, r = z >> 1;
    const __nv_bfloat16* Ah[6] = {g_XUh, g_XIh, g_XIh, g_XUh, g_XIh, g_XIh};
    const __nv_bfloat16* Al[6] = {g_XUl, g_XIl, g_XIl, g_XUl, g_XIl, g_XIl};
    GemmPtrs P;
    P.Ah = Ah[z]; P.Al = Al[z];
    P.Bh = g_WTh[z]; P.Bl = g_WTl[z];
    P.bias = nullptr;
    P.C = (z & 1) ? g_HT[r] : g_HS[r];
    gemm_core(P, M, HH, DD, blockIdx.x * 128, 0, smem);
}

// batched GRU gates: grid(392,3,6), K=128, Nc=384
__global__ void __launch_bounds__(256) gru_gemm(
    int M,
    const float* b0, const float* b1, const float* b2,
    const float* b3, const float* b4, const float* b5)
{
    extern __shared__ char smem[];
    int z = blockIdx.z, r = z >> 1, which = z & 1;
    const float* biases[6] = {b0, b1, b2, b3, b4, b5};
    GemmPtrs P;
    P.Ah = which ? g_AGh[r] : g_HTh[r];
    P.Al = which ? g_AGl[r] : g_HTl[r];
    P.Bh = g_WGh[z]; P.Bl = g_WGl[z];
    P.bias = biases[z];
    P.C = which ? g_GH[r] : g_GI[r];
    gemm_core(P, M, G3, HH, blockIdx.x * 128, blockIdx.y * 128, smem);
}

// ------------------- batched edge / pointwise -------------------
__global__ void alpha_all(const float* q0, const float* q1, const float* q2, int n)
{
    int gw = (blockIdx.x * blockDim.x + threadIdx.x) >> 5;
    int lane = threadIdx.x & 31;
    if (gw >= 6 * n) return;
    int sel = gw / n, node = gw - sel * n;
    int r = sel >> 1, which = sel & 1;
    const float* qs[3] = {q0, q1, q2};
    const float* feat = which ? g_HT[r] : g_HS[r];
    const float* q = qs[r] + which * HH;
    float4 a = *reinterpret_cast<const float4*>(feat + (size_t)node * HH + lane * 4);
    float4 b = *reinterpret_cast<const float4*>(q + lane * 4);
    float s = a.x * b.x + a.y * b.y + a.z * b.z + a.w * b.w;
#pragma unroll
    for (int o = 16; o; o >>= 1) s += __shfl_xor_sync(0xffffffffu, s, o);
    if (lane == 0) {
        if (which) g_AT[r][node] = s;
        else       g_AS[r][node] = s;
    }
}

__global__ void zero_all(int n)
{
    long long i = (long long)blockIdx.x * blockDim.x + threadIdx.x;
    if (i < 3LL * NPAD * HH) (&g_AGG[0][0])[i] = 0.f;
    if (i < 3LL * n)         (&g_DEN[0][0])[i] = 0.f;
}

__global__ void edge_logit_all(const int* e0, const int* e1, const int* e2, int E)
{
    int e = blockIdx.x * blockDim.x + threadIdx.x;
    if (e >= 3 * E) return;
    int r = e / E, le = e - r * E;
    const int* ei = (r == 0) ? e0 : (r == 1) ? e1 : e2;
    int si = ei[le];
    int ti = ei[E + le];
    float l = g_AS[r][si] + g_AT[r][ti];
    l = (l > 0.f) ? l : 0.2f * l;
    float ex = expf(l);
    g_EX[r][le] = ex;
    atomicAdd(&g_DEN[r][ti], ex);
}

__global__ void edge_scatter_all(const int* e0, const int* e1, const int* e2, int E)
{
    int gw   = (blockIdx.x * blockDim.x + threadIdx.x) >> 5;
    int lane = threadIdx.x & 31;
    if (gw >= 3 * E) return;
    int r = gw / E, le = gw - r * E;
    const int* ei = (r == 0) ? e0 : (r == 1) ? e1 : e2;
    int si = ei[le];
    int ti = ei[E + le];
    float c = g_EX[r][le] / (g_DEN[r][ti] + 1e-16f);
    float4 v = *reinterpret_cast<const float4*>(g_HS[r] + (size_t)si * HH + lane * 4);
    float* dst = g_AGG[r] + (size_t)ti * HH + lane * 4;
    asm volatile("red.global.add.v4.f32 [%0], {%1,%2,%3,%4};"
                 :: "l"(dst), "f"(c * v.x), "f"(c * v.y), "f"(c * v.z), "f"(c * v.w)
                 : "memory");
}

__global__ void gru_all(int n)
{
    long long i = (long long)blockIdx.x * blockDim.x + threadIdx.x;
    if (i >= 3LL * n * HH) return;
    int r = (int)(i / ((long long)n * HH));
    int j = (int)(i - (long long)r * n * HH);
    int nn = j / HH, h = j - nn * HH;
    const float* gi = g_GI[r] + (size_t)nn * G3;
    const float* gh = g_GH[r] + (size_t)nn * G3;
    float rr = 1.f / (1.f + expf(-(gi[h] + gh[h])));
    float z  = 1.f / (1.f + expf(-(gi[HH + h] + gh[HH + h])));
    float g  = tanhf(gi[2 * HH + h] + rr * gh[2 * HH + h]);
    float a  = g_AGG[r][(size_t)nn * HH + h];
    g_HOUT[r][j] = (1.f - z) * g + z * a;
}

__global__ void final_k(float* __restrict__ out, const float* __restrict__ g, int n)
{
    int warp = (blockIdx.x * blockDim.x + threadIdx.x) >> 5;
    int lane = threadIdx.x & 31;
    if (warp >= n) return;
    size_t off = (size_t)warp * HH + lane * 4;
    float4 u = *reinterpret_cast<const float4*>(g_HOUT[1] + off);
    u.x = fmaxf(u.x, 0.f); u.y = fmaxf(u.y, 0.f);
    u.z = fmaxf(u.z, 0.f); u.w = fmaxf(u.w, 0.f);
    *reinterpret_cast<float4*>(out + off) = u;
    float4 v0 = *reinterpret_cast<const float4*>(g_HOUT[0] + off);
    float4 v1 = *reinterpret_cast<const float4*>(g_HOUT[2] + off);
    float4 gv = *reinterpret_cast<const float4*>(g + lane * 4);
    float d0 = v0.x * gv.x + v0.y * gv.y + v0.z * gv.z + v0.w * gv.w;
    float d1 = v1.x * gv.x + v1.y * gv.y + v1.z * gv.z + v1.w * gv.w;
#pragma unroll
    for (int o = 16; o; o >>= 1) {
        d0 += __shfl_xor_sync(0xffffffffu, d0, o);
        d1 += __shfl_xor_sync(0xffffffffu, d1, o);
    }
    float a0 = expf(d0), a1 = expf(d1);
    float inv = 1.f / (a0 + a1);
    float w0 = a0 * inv, w1 = a1 * inv;
    float4 o4;
    o4.x = fmaxf(w0 * v0.x + w1 * v1.x, 0.f);
    o4.y = fmaxf(w0 * v0.y + w1 * v1.y, 0.f);
    o4.z = fmaxf(w0 * v0.z + w1 * v1.z, 0.f);
    o4.w = fmaxf(w0 * v0.w + w1 * v1.w, 0.f);
    *reinterpret_cast<float4*>(out + (size_t)n * HH + off) = o4;
}

// ---------------------------------------------------------------
extern "C" void kernel_launch(void* const* d_in, const int* in_sizes, int n_in,
                              void* d_out, int out_size)
{
    const float* x_user = (const float*)d_in[0];
    const float* x_item = (const float*)d_in[1];
    const int*   ei_ui  = (const int*)d_in[2];
    const int*   ei_iu  = (const int*)d_in[3];
    const int*   ei_ii  = (const int*)d_in[4];

    int N = in_sizes[0] / DD;
    int E = in_sizes[2] / 2;
    if (N > NMAX) N = NMAX;
    if (E > EMAX) E = EMAX;

    float* out = (float*)d_out;

    cudaFuncSetAttribute(hsht_gemm, cudaFuncAttributeMaxDynamicSharedMemorySize, SMEMSZ);
    cudaFuncSetAttribute(gru_gemm,  cudaFuncAttributeMaxDynamicSharedMemorySize, SMEMSZ);

    int x4 = (N * DD) / 4;
    split_x_k<<<(2 * x4 + 255) / 256, 256>>>(x_user, x_item, x4);
    prep_wt_all<<<(6 * 128 * 256 + 255) / 256, 256>>>(
        (const float*)d_in[5],  (const float*)d_in[6],
        (const float*)d_in[12], (const float*)d_in[13],
        (const float*)d_in[19], (const float*)d_in[20]);
    prep_wg_all<<<(6 * G3 * HH + 255) / 256, 256>>>(
        (const float*)d_in[8],  (const float*)d_in[9],
        (const float*)d_in[15], (const float*)d_in[16],
        (const float*)d_in[22], (const float*)d_in[23]);

    const int mb = NPAD / 128;   // 392

    hsht_gemm<<<dim3(mb, 1, 6), 256, SMEMSZ>>>(N);

    int aBlocks = (int)(((long long)6 * N * 32 + 255) / 256);
    alpha_all<<<aBlocks, 256>>>((const float*)d_in[7], (const float*)d_in[14],
                                (const float*)d_in[21], N);

    long long ztot = 3LL * NPAD * HH;
    zero_all<<<(int)((ztot + 255) / 256), 256>>>(N);

    edge_logit_all<<<(3 * E + 255) / 256, 256>>>(ei_ui, ei_iu, ei_ii, E);
    int sBlocks = (int)(((long long)3 * E * 32 + 255) / 256);
    edge_scatter_all<<<sBlocks, 256>>>(ei_ui, ei_iu, ei_ii, E);

    int n4 = NPAD * HH / 4;
    split6_k<<<(int)((6LL * n4 + 255) / 256), 256>>>(n4);

    gru_gemm<<<dim3(mb, 3, 6), 256, SMEMSZ>>>(
        N,
        (const float*)d_in[10], (const float*)d_in[11],
        (const float*)d_in[17], (const float*)d_in[18],
        (const float*)d_in[24], (const float*)d_in[25]);

    gru_all<<<(int)((3LL * N * HH + 255) / 256), 256>>>(N);

    final_k<<<(N * 32 + 255) / 256, 256>>>(out, (const float*)d_in[27], N);
}

// round 7
// speedup vs baseline: 1.7031x; 1.1321x over previous
#include <cuda_runtime.h>
#include <cuda_bf16.h>
#include <math.h>
#include <cstdint>

#define NMAX 50000
#define NPAD 50176   // 392*128
#define EMAX 400000
#define DD   256
#define HH   128
#define G3   384
#define SROW 80                  // smem bytes per 32-bf16 row (64B + 16B pad)
#define TILE_B (128 * SROW)      // 10240
#define STAGE_B (4 * TILE_B)     // 40960
#define SMEMSZ (2 * STAGE_B)     // 81920

// ------------------- scratch -------------------
__device__ __align__(16) float g_HS [3][NPAD*HH];
__device__ __align__(16) float g_HT [3][NPAD*HH];
__device__ __align__(16) float g_AGG[3][NPAD*HH];
__device__ __align__(16) float g_GI [3][NPAD*G3];
__device__ __align__(16) float g_GH [3][NPAD*G3];
__device__ __align__(16) float g_AS [3][NMAX];
__device__ __align__(16) float g_AT [3][NMAX];
__device__ __align__(16) float g_HOUT[3][NPAD*HH];
__device__ __align__(16) __nv_bfloat16 g_XUh[NPAD*DD], g_XUl[NPAD*DD];
__device__ __align__(16) __nv_bfloat16 g_XIh[NPAD*DD], g_XIl[NPAD*DD];
__device__ __align__(16) __nv_bfloat16 g_HTh[3][NPAD*HH], g_HTl[3][NPAD*HH];
__device__ __align__(16) __nv_bfloat16 g_AGh[3][NPAD*HH], g_AGl[3][NPAD*HH];
__device__ __align__(16) __nv_bfloat16 g_WTh[6][128*DD], g_WTl[6][128*DD];
__device__ __align__(16) __nv_bfloat16 g_WGh[6][G3*HH],  g_WGl[6][G3*HH];
// CSR structures for gather-based aggregation
__device__ int g_CNT [3*NMAX];
__device__ int g_OFF [3*NMAX];
__device__ int g_CUR [3*NMAX];
__device__ int g_SRC [3*EMAX];
__device__ int g_BSUM[256];

// ------------------- PTX helpers -------------------
__device__ __forceinline__ uint32_t smem_u32(const void* p) {
    uint32_t a;
    asm("{ .reg .u64 t; cvta.to.shared.u64 t, %1; cvt.u32.u64 %0, t; }" : "=r"(a) : "l"(p));
    return a;
}
__device__ __forceinline__ void ldsm4(uint32_t* r, uint32_t addr) {
    asm volatile("ldmatrix.sync.aligned.m8n8.x4.shared.b16 {%0,%1,%2,%3}, [%4];"
                 : "=r"(r[0]), "=r"(r[1]), "=r"(r[2]), "=r"(r[3]) : "r"(addr));
}
__device__ __forceinline__ void mma_bf16(float* d, const uint32_t* a, const uint32_t* b) {
    asm volatile(
        "mma.sync.aligned.m16n8k16.row.col.f32.bf16.bf16.f32 "
        "{%0,%1,%2,%3}, {%4,%5,%6,%7}, {%8,%9}, {%0,%1,%2,%3};"
        : "+f"(d[0]), "+f"(d[1]), "+f"(d[2]), "+f"(d[3])
        : "r"(a[0]), "r"(a[1]), "r"(a[2]), "r"(a[3]), "r"(b[0]), "r"(b[1]));
}
__device__ __forceinline__ void cpa16(uint32_t dst, const void* src) {
    asm volatile("cp.async.cg.shared.global [%0], [%1], 16;" :: "r"(dst), "l"(src));
}
__device__ __forceinline__ void split4(float4 v, uint2& hp, uint2& lp) {
    __nv_bfloat16 h0 = __float2bfloat16(v.x), h1 = __float2bfloat16(v.y);
    __nv_bfloat16 h2 = __float2bfloat16(v.z), h3 = __float2bfloat16(v.w);
    hp.x = ((uint32_t)__bfloat16_as_ushort(h1) << 16) | __bfloat16_as_ushort(h0);
    hp.y = ((uint32_t)__bfloat16_as_ushort(h3) << 16) | __bfloat16_as_ushort(h2);
    __nv_bfloat16 l0 = __float2bfloat16(v.x - __bfloat162float(h0));
    __nv_bfloat16 l1 = __float2bfloat16(v.y - __bfloat162float(h1));
    __nv_bfloat16 l2 = __float2bfloat16(v.z - __bfloat162float(h2));
    __nv_bfloat16 l3 = __float2bfloat16(v.w - __bfloat162float(h3));
    lp.x = ((uint32_t)__bfloat16_as_ushort(l1) << 16) | __bfloat16_as_ushort(l0);
    lp.y = ((uint32_t)__bfloat16_as_ushort(l3) << 16) | __bfloat16_as_ushort(l2);
}

// ------------------- prep kernels -------------------
__global__ void split_x_k(const float* __restrict__ xu, const float* __restrict__ xi, int n4)
{
    int i = blockIdx.x * blockDim.x + threadIdx.x;
    if (i >= 2 * n4) return;
    const float* src = (i < n4) ? xu : xi;
    int j = (i < n4) ? i : i - n4;
    float4 v = reinterpret_cast<const float4*>(src)[j];
    uint2 hp, lp;
    split4(v, hp, lp);
    if (i < n4) {
        reinterpret_cast<uint2*>(g_XUh)[j] = hp;
        reinterpret_cast<uint2*>(g_XUl)[j] = lp;
    } else {
        reinterpret_cast<uint2*>(g_XIh)[j] = hp;
        reinterpret_cast<uint2*>(g_XIl)[j] = lp;
    }
}
__global__ void prep_wt_all(const float* w0, const float* w1, const float* w2,
                            const float* w3, const float* w4, const float* w5)
{
    const float* ws[6] = {w0, w1, w2, w3, w4, w5};
    int i = blockIdx.x * blockDim.x + threadIdx.x;
    if (i >= 6 * 128 * 256) return;
    int z = i >> 15, j = i & 32767;
    int n = j >> 8, k = j & 255;
    float x = ws[z][k * 128 + n];
    __nv_bfloat16 h = __float2bfloat16(x);
    g_WTh[z][j] = h;
    g_WTl[z][j] = __float2bfloat16(x - __bfloat162float(h));
}
__global__ void prep_wg_all(const float* w0, const float* w1, const float* w2,
                            const float* w3, const float* w4, const float* w5)
{
    const float* ws[6] = {w0, w1, w2, w3, w4, w5};
    int i = blockIdx.x * blockDim.x + threadIdx.x;
    if (i >= 6 * G3 * HH) return;
    int z = i / (G3 * HH), j = i % (G3 * HH);
    float x = ws[z][j];
    __nv_bfloat16 h = __float2bfloat16(x);
    g_WGh[z][j] = h;
    g_WGl[z][j] = __float2bfloat16(x - __bfloat162float(h));
}
__global__ void split6_k(int n4)   // n4 = NPAD*HH/4
{
    long long i = (long long)blockIdx.x * blockDim.x + threadIdx.x;
    if (i >= 6LL * n4) return;
    int z = (int)(i / n4), j = (int)(i % n4);
    const float* src = (z < 3) ? g_HT[z] : g_AGG[z - 3];
    float4 v = reinterpret_cast<const float4*>(src)[j];
    uint2 hp, lp;
    split4(v, hp, lp);
    __nv_bfloat16* dh = (z < 3) ? g_HTh[z] : g_AGh[z - 3];
    __nv_bfloat16* dl = (z < 3) ? g_HTl[z] : g_AGl[z - 3];
    reinterpret_cast<uint2*>(dh)[j] = hp;
    reinterpret_cast<uint2*>(dl)[j] = lp;
}

// ------------------- pipelined GEMM core (BK=32, 2-stage) -------------------
struct GemmPtrs {
    const __nv_bfloat16 *Ah, *Al, *Bh, *Bl;
    const float* bias;
    float* C;
};

__device__ __forceinline__ void gemm_core(const GemmPtrs& P, int M, int Nc, int K,
                                          int m0, int n0, char* smem)
{
    const uint32_t sb = smem_u32(smem);
    const int tid  = threadIdx.x;
    const int wid  = tid >> 5;
    const int lane = tid & 31;
    const int warp_m = wid & 3;
    const int warp_n = wid >> 2;

    float acc[2][8][4];
#pragma unroll
    for (int i = 0; i < 2; i++)
#pragma unroll
        for (int j = 0; j < 8; j++)
#pragma unroll
            for (int t = 0; t < 4; t++) acc[i][j][t] = 0.f;

    const int nchunks = K >> 5;

#define FILL(kc, stg) do {                                                      \
        const int k0f = (kc) << 5;                                              \
        const uint32_t s0 = sb + (stg) * STAGE_B;                               \
        _Pragma("unroll")                                                       \
        for (int it = 0; it < 8; it++) {                                        \
            int s = tid + it * 256;                                             \
            int tile = s >> 9, w = s & 511, row = w >> 2, q = w & 3;            \
            uint32_t dst = s0 + tile * TILE_B + row * SROW + q * 16;            \
            const __nv_bfloat16* src;                                           \
            size_t off;                                                         \
            if (tile < 2) {                                                     \
                src = (tile == 0) ? P.Ah : P.Al;                                \
                off = (size_t)(m0 + row) * K + k0f + q * 8;                     \
            } else {                                                            \
                src = (tile == 2) ? P.Bh : P.Bl;                                \
                off = (size_t)(n0 + row) * K + k0f + q * 8;                     \
            }                                                                   \
            cpa16(dst, src + off);                                              \
        }                                                                       \
        asm volatile("cp.async.commit_group;" ::: "memory");                    \
    } while (0)

    FILL(0, 0);

    for (int kc = 0; kc < nchunks; kc++) {
        if (kc + 1 < nchunks) {
            FILL(kc + 1, (kc + 1) & 1);
            asm volatile("cp.async.wait_group 1;" ::: "memory");
        } else {
            asm volatile("cp.async.wait_group 0;" ::: "memory");
        }
        __syncthreads();

        const uint32_t s0  = sb + (kc & 1) * STAGE_B;
        const uint32_t sAh = s0;
        const uint32_t sAl = s0 + TILE_B;
        const uint32_t sBh = s0 + 2 * TILE_B;
        const uint32_t sBl = s0 + 3 * TILE_B;

#pragma unroll
        for (int ks = 0; ks < 2; ks++) {
            uint32_t afh[2][4], afl[2][4];
            {
                int r  = lane & 15;
                int c8 = lane >> 4;
                uint32_t off = (uint32_t)((warp_m * 32 + r) * SROW + (ks * 16 + c8 * 8) * 2);
                ldsm4(afh[0], sAh + off);
                ldsm4(afh[1], sAh + off + 16 * SROW);
                ldsm4(afl[0], sAl + off);
                ldsm4(afl[1], sAl + off + 16 * SROW);
            }
            uint32_t bfh[8][2], bfl[8][2];
            {
                int sub = lane >> 3, wi = lane & 7;
                int n_off = (sub >> 1) * 8 + wi;
                int k_off = ks * 16 + (sub & 1) * 8;
                uint32_t base = (uint32_t)((warp_n * 64 + n_off) * SROW + k_off * 2);
#pragma unroll
                for (int jj = 0; jj < 4; jj++) {
                    uint32_t r4[4];
                    ldsm4(r4, sBh + base + jj * 16 * SROW);
                    bfh[2 * jj][0] = r4[0]; bfh[2 * jj][1] = r4[1];
                    bfh[2 * jj + 1][0] = r4[2]; bfh[2 * jj + 1][1] = r4[3];
                    ldsm4(r4, sBl + base + jj * 16 * SROW);
                    bfl[2 * jj][0] = r4[0]; bfl[2 * jj][1] = r4[1];
                    bfl[2 * jj + 1][0] = r4[2]; bfl[2 * jj + 1][1] = r4[3];
                }
            }
#pragma unroll
            for (int mi = 0; mi < 2; mi++)
#pragma unroll
                for (int j = 0; j < 8; j++) {
                    mma_bf16(acc[mi][j], afh[mi], bfh[j]);
                    mma_bf16(acc[mi][j], afh[mi], bfl[j]);
                    mma_bf16(acc[mi][j], afl[mi], bfh[j]);
                }
        }
        __syncthreads();
    }
#undef FILL

#pragma unroll
    for (int mi = 0; mi < 2; mi++) {
        int gr = m0 + warp_m * 32 + mi * 16 + (lane >> 2);
#pragma unroll
        for (int j = 0; j < 8; j++) {
            int gc = n0 + warp_n * 64 + j * 8 + 2 * (lane & 3);
            float b0 = 0.f, b1 = 0.f;
            if (P.bias) { b0 = P.bias[gc]; b1 = P.bias[gc + 1]; }
            if (gr < M) {
                float2 v = make_float2(acc[mi][j][0] + b0, acc[mi][j][1] + b1);
                *reinterpret_cast<float2*>(P.C + (size_t)gr * Nc + gc) = v;
            }
            if (gr + 8 < M) {
                float2 v = make_float2(acc[mi][j][2] + b0, acc[mi][j][3] + b1);
                *reinterpret_cast<float2*>(P.C + (size_t)(gr + 8) * Nc + gc) = v;
            }
        }
    }
}

__global__ void __launch_bounds__(256) hsht_gemm(int M)
{
    extern __shared__ char smem[];
    int z = blockIdx.z, r = z >> 1;
    const __nv_bfloat16* Ah[6] = {g_XUh, g_XIh, g_XIh, g_XUh, g_XIh, g_XIh};
    const __nv_bfloat16* Al[6] = {g_XUl, g_XIl, g_XIl, g_XUl, g_XIl, g_XIl};
    GemmPtrs P;
    P.Ah = Ah[z]; P.Al = Al[z];
    P.Bh = g_WTh[z]; P.Bl = g_WTl[z];
    P.bias = nullptr;
    P.C = (z & 1) ? g_HT[r] : g_HS[r];
    gemm_core(P, M, HH, DD, blockIdx.x * 128, 0, smem);
}

__global__ void __launch_bounds__(256) gru_gemm(
    int M,
    const float* b0, const float* b1, const float* b2,
    const float* b3, const float* b4, const float* b5)
{
    extern __shared__ char smem[];
    int z = blockIdx.z, r = z >> 1, which = z & 1;
    const float* biases[6] = {b0, b1, b2, b3, b4, b5};
    GemmPtrs P;
    P.Ah = which ? g_AGh[r] : g_HTh[r];
    P.Al = which ? g_AGl[r] : g_HTl[r];
    P.Bh = g_WGh[z]; P.Bl = g_WGl[z];
    P.bias = biases[z];
    P.C = which ? g_GH[r] : g_GI[r];
    gemm_core(P, M, G3, HH, blockIdx.x * 128, blockIdx.y * 128, smem);
}

// ------------------- CSR build -------------------
__global__ void hist_k(const int* e0, const int* e1, const int* e2, int E, int N)
{
    int e = blockIdx.x * blockDim.x + threadIdx.x;
    if (e >= 3 * E) return;
    int r = e / E, le = e - r * E;
    const int* ei = (r == 0) ? e0 : (r == 1) ? e1 : e2;
    int ti = ei[E + le];
    atomicAdd(&g_CNT[r * N + ti], 1);
}
// block-wise exclusive scan (1024/block)
__global__ void scan1_k(int ntot)
{
    __shared__ int sh[1024];
    int tid = threadIdx.x;
    int gid = blockIdx.x * 1024 + tid;
    int v = (gid < ntot) ? g_CNT[gid] : 0;
    sh[tid] = v;
    __syncthreads();
    for (int o = 1; o < 1024; o <<= 1) {
        int t = (tid >= o) ? sh[tid - o] : 0;
        __syncthreads();
        sh[tid] += t;
        __syncthreads();
    }
    if (gid < ntot) g_OFF[gid] = sh[tid] - v;   // exclusive within block
    if (tid == 1023) g_BSUM[blockIdx.x] = sh[1023];
}
__global__ void scan2_k(int nb)
{
    if (threadIdx.x == 0 && blockIdx.x == 0) {
        int run = 0;
        for (int i = 0; i < nb; i++) {
            int v = g_BSUM[i];
            g_BSUM[i] = run;
            run += v;
        }
    }
}
__global__ void scan3_k(int ntot)
{
    int gid = blockIdx.x * 1024 + threadIdx.x;
    if (gid >= ntot) return;
    int o = g_OFF[gid] + g_BSUM[blockIdx.x];
    g_OFF[gid] = o;
    g_CUR[gid] = o;
}
__global__ void scatter_idx_k(const int* e0, const int* e1, const int* e2, int E, int N)
{
    int e = blockIdx.x * blockDim.x + threadIdx.x;
    if (e >= 3 * E) return;
    int r = e / E, le = e - r * E;
    const int* ei = (r == 0) ? e0 : (r == 1) ? e1 : e2;
    int si = ei[le];
    int ti = ei[E + le];
    int pos = atomicAdd(&g_CUR[r * N + ti], 1);
    g_SRC[pos] = si;
}

// ------------------- gather aggregation (no atomics) -------------------
// one warp per (relation, target node): softmax-weighted sum of hs rows
__global__ void gather_k(int N, int Etot)
{
    int gw   = (blockIdx.x * blockDim.x + threadIdx.x) >> 5;
    int lane = threadIdx.x & 31;
    if (gw >= 3 * N) return;
    int r = gw / N, ti = gw - r * N;
    int idx = r * N + ti;
    int s = g_OFF[idx];
    int e = (idx + 1 < 3 * N) ? g_OFF[idx + 1] : Etot;
    float* dst = g_AGG[r] + (size_t)ti * HH + lane * 4;
    if (s == e) {   // empty segment -> zeros
        *reinterpret_cast<float4*>(dst) = make_float4(0.f, 0.f, 0.f, 0.f);
        return;
    }
    float at = g_AT[r][ti];
    // pass 1: denominator
    float den = 0.f;
    for (int base = s; base < e; base += 32) {
        int k = base + lane;
        if (k < e) {
            int si = g_SRC[k];
            float l = g_AS[r][si] + at;
            l = (l > 0.f) ? l : 0.2f * l;
            den += expf(l);
        }
    }
#pragma unroll
    for (int o = 16; o; o >>= 1) den += __shfl_xor_sync(0xffffffffu, den, o);
    float inv = 1.f / (den + 1e-16f);
    // pass 2: weighted accumulation
    float4 acc = make_float4(0.f, 0.f, 0.f, 0.f);
    for (int base = s; base < e; base += 32) {
        int k = base + lane;
        int si = 0;
        float ex = 0.f;
        if (k < e) {
            si = g_SRC[k];
            float l = g_AS[r][si] + at;
            l = (l > 0.f) ? l : 0.2f * l;
            ex = expf(l);
        }
        int cnt = min(32, e - base);
        for (int j = 0; j < cnt; j++) {
            float exj = __shfl_sync(0xffffffffu, ex, j);
            int   sij = __shfl_sync(0xffffffffu, si, j);
            float4 v = *reinterpret_cast<const float4*>(
                g_HS[r] + (size_t)sij * HH + lane * 4);
            acc.x += exj * v.x;
            acc.y += exj * v.y;
            acc.z += exj * v.z;
            acc.w += exj * v.w;
        }
    }
    acc.x *= inv; acc.y *= inv; acc.z *= inv; acc.w *= inv;
    *reinterpret_cast<float4*>(dst) = acc;
}

// ------------------- pointwise -------------------
__global__ void alpha_all(const float* q0, const float* q1, const float* q2, int n)
{
    int gw = (blockIdx.x * blockDim.x + threadIdx.x) >> 5;
    int lane = threadIdx.x & 31;
    if (gw >= 6 * n) return;
    int sel = gw / n, node = gw - sel * n;
    int r = sel >> 1, which = sel & 1;
    const float* qs[3] = {q0, q1, q2};
    const float* feat = which ? g_HT[r] : g_HS[r];
    const float* q = qs[r] + which * HH;
    float4 a = *reinterpret_cast<const float4*>(feat + (size_t)node * HH + lane * 4);
    float4 b = *reinterpret_cast<const float4*>(q + lane * 4);
    float s = a.x * b.x + a.y * b.y + a.z * b.z + a.w * b.w;
#pragma unroll
    for (int o = 16; o; o >>= 1) s += __shfl_xor_sync(0xffffffffu, s, o);
    if (lane == 0) {
        if (which) g_AT[r][node] = s;
        else       g_AS[r][node] = s;
    }
}

__global__ void gru_all(int n)
{
    long long i = (long long)blockIdx.x * blockDim.x + threadIdx.x;
    if (i >= 3LL * n * HH) return;
    int r = (int)(i / ((long long)n * HH));
    int j = (int)(i - (long long)r * n * HH);
    int nn = j / HH, h = j - nn * HH;
    const float* gi = g_GI[r] + (size_t)nn * G3;
    const float* gh = g_GH[r] + (size_t)nn * G3;
    float rr = 1.f / (1.f + expf(-(gi[h] + gh[h])));
    float z  = 1.f / (1.f + expf(-(gi[HH + h] + gh[HH + h])));
    float g  = tanhf(gi[2 * HH + h] + rr * gh[2 * HH + h]);
    float a  = g_AGG[r][(size_t)nn * HH + h];
    g_HOUT[r][j] = (1.f - z) * g + z * a;
}

__global__ void final_k(float* __restrict__ out, const float* __restrict__ g, int n)
{
    int warp = (blockIdx.x * blockDim.x + threadIdx.x) >> 5;
    int lane = threadIdx.x & 31;
    if (warp >= n) return;
    size_t off = (size_t)warp * HH + lane * 4;
    float4 u = *reinterpret_cast<const float4*>(g_HOUT[1] + off);
    u.x = fmaxf(u.x, 0.f); u.y = fmaxf(u.y, 0.f);
    u.z = fmaxf(u.z, 0.f); u.w = fmaxf(u.w, 0.f);
    *reinterpret_cast<float4*>(out + off) = u;
    float4 v0 = *reinterpret_cast<const float4*>(g_HOUT[0] + off);
    float4 v1 = *reinterpret_cast<const float4*>(g_HOUT[2] + off);
    float4 gv = *reinterpret_cast<const float4*>(g + lane * 4);
    float d0 = v0.x * gv.x + v0.y * gv.y + v0.z * gv.z + v0.w * gv.w;
    float d1 = v1.x * gv.x + v1.y * gv.y + v1.z * gv.z + v1.w * gv.w;
#pragma unroll
    for (int o = 16; o; o >>= 1) {
        d0 += __shfl_xor_sync(0xffffffffu, d0, o);
        d1 += __shfl_xor_sync(0xffffffffu, d1, o);
    }
    float a0 = expf(d0), a1 = expf(d1);
    float inv = 1.f / (a0 + a1);
    float w0 = a0 * inv, w1 = a1 * inv;
    float4 o4;
    o4.x = fmaxf(w0 * v0.x + w1 * v1.x, 0.f);
    o4.y = fmaxf(w0 * v0.y + w1 * v1.y, 0.f);
    o4.z = fmaxf(w0 * v0.z + w1 * v1.z, 0.f);
    o4.w = fmaxf(w0 * v0.w + w1 * v1.w, 0.f);
    *reinterpret_cast<float4*>(out + (size_t)n * HH + off) = o4;
}

// ---------------------------------------------------------------
extern "C" void kernel_launch(void* const* d_in, const int* in_sizes, int n_in,
                              void* d_out, int out_size)
{
    const float* x_user = (const float*)d_in[0];
    const float* x_item = (const float*)d_in[1];
    const int*   ei_ui  = (const int*)d_in[2];
    const int*   ei_iu  = (const int*)d_in[3];
    const int*   ei_ii  = (const int*)d_in[4];

    int N = in_sizes[0] / DD;
    int E = in_sizes[2] / 2;
    if (N > NMAX) N = NMAX;
    if (E > EMAX) E = EMAX;

    float* out = (float*)d_out;

    cudaFuncSetAttribute(hsht_gemm, cudaFuncAttributeMaxDynamicSharedMemorySize, SMEMSZ);
    cudaFuncSetAttribute(gru_gemm,  cudaFuncAttributeMaxDynamicSharedMemorySize, SMEMSZ);

    // ---- prep: splits ----
    int x4 = (N * DD) / 4;
    split_x_k<<<(2 * x4 + 255) / 256, 256>>>(x_user, x_item, x4);
    prep_wt_all<<<(6 * 128 * 256 + 255) / 256, 256>>>(
        (const float*)d_in[5],  (const float*)d_in[6],
        (const float*)d_in[12], (const float*)d_in[13],
        (const float*)d_in[19], (const float*)d_in[20]);
    prep_wg_all<<<(6 * G3 * HH + 255) / 256, 256>>>(
        (const float*)d_in[8],  (const float*)d_in[9],
        (const float*)d_in[15], (const float*)d_in[16],
        (const float*)d_in[22], (const float*)d_in[23]);

    // ---- CSR build (independent of GEMM results) ----
    int ntot = 3 * N;
    void* pcnt;
    cudaGetSymbolAddress(&pcnt, g_CNT);
    cudaMemsetAsync(pcnt, 0, ntot * sizeof(int));
    hist_k<<<(3 * E + 255) / 256, 256>>>(ei_ui, ei_iu, ei_ii, E, N);
    int nb = (ntot + 1023) / 1024;
    scan1_k<<<nb, 1024>>>(ntot);
    scan2_k<<<1, 32>>>(nb);
    scan3_k<<<nb, 1024>>>(ntot);
    scatter_idx_k<<<(3 * E + 255) / 256, 256>>>(ei_ui, ei_iu, ei_ii, E, N);

    const int mb = NPAD / 128;   // 392

    // ---- hs/ht GEMMs ----
    hsht_gemm<<<dim3(mb, 1, 6), 256, SMEMSZ>>>(N);

    // ---- attention scalars ----
    int aBlocks = (int)(((long long)6 * N * 32 + 255) / 256);
    alpha_all<<<aBlocks, 256>>>((const float*)d_in[7], (const float*)d_in[14],
                                (const float*)d_in[21], N);

    // ---- gather aggregation ----
    gather_k<<<(int)(((long long)3 * N * 32 + 255) / 256), 256>>>(N, 3 * E);

    // ---- split HT + AGG ----
    int n4 = NPAD * HH / 4;
    split6_k<<<(int)((6LL * n4 + 255) / 256), 256>>>(n4);

    // ---- GRU gate GEMMs ----
    gru_gemm<<<dim3(mb, 3, 6), 256, SMEMSZ>>>(
        N,
        (const float*)d_in[10], (const float*)d_in[11],
        (const float*)d_in[17], (const float*)d_in[18],
        (const float*)d_in[24], (const float*)d_in[25]);

    gru_all<<<(int)((3LL * N * HH + 255) / 256), 256>>>(N);

    final_k<<<(N * 32 + 255) / 256, 256>>>(out, (const float*)d_in[27], N);
}

// round 8
// speedup vs baseline: 2.0361x; 1.1955x over previous
#include <cuda_runtime.h>
#include <cuda_bf16.h>
#include <cuda_fp16.h>
#include <math.h>
#include <cstdint>

#define NMAX 50000
#define NPAD 50176   // 392*128
#define EMAX 400000
#define DD   256
#define HH   128
#define G3   384
#define SROW 80                  // smem bytes per 32-bf16 row (64B + 16B pad)
#define TILE_B (128 * SROW)      // 10240
#define STAGE_B (4 * TILE_B)     // 40960
#define SMEMSZ (2 * STAGE_B)     // 81920 (hsht)
// gru_gemm B-resident layout
#define BROW   272               // 128*2 + 16 pad
#define GB_TILE (128 * BROW)     // 34816 per component
#define GA_TILE (128 * SROW)     // 10240 per component
#define GSMEM  (2 * GB_TILE + 4 * GA_TILE)  // 110592

// ------------------- scratch -------------------
__device__ __align__(16) float g_HS [3][NPAD*HH];
__device__ __align__(16) float g_HT [3][NPAD*HH];
__device__ __align__(16) float g_AGG[3][NPAD*HH];
__device__ __align__(16) __half g_GI16[3][NPAD*G3];
__device__ __align__(16) __half g_GH16[3][NPAD*G3];
__device__ __align__(16) float g_AS [3][NMAX];
__device__ __align__(16) float g_AT [3][NMAX];
__device__ __align__(16) float g_HOUT[3][NPAD*HH];
__device__ __align__(16) __nv_bfloat16 g_XUh[NPAD*DD], g_XUl[NPAD*DD];
__device__ __align__(16) __nv_bfloat16 g_XIh[NPAD*DD], g_XIl[NPAD*DD];
__device__ __align__(16) __nv_bfloat16 g_HTh[3][NPAD*HH], g_HTl[3][NPAD*HH];
__device__ __align__(16) __nv_bfloat16 g_AGh[3][NPAD*HH], g_AGl[3][NPAD*HH];
__device__ __align__(16) __nv_bfloat16 g_WTh[6][128*DD], g_WTl[6][128*DD];
__device__ __align__(16) __nv_bfloat16 g_WGh[6][G3*HH],  g_WGl[6][G3*HH];
// CSR
__device__ int g_CNT [3*NMAX];
__device__ int g_OFF [3*NMAX];
__device__ int g_CUR [3*NMAX];
__device__ int g_SRC [3*EMAX];
__device__ int g_BSUM[256];

// ------------------- PTX helpers -------------------
__device__ __forceinline__ uint32_t smem_u32(const void* p) {
    uint32_t a;
    asm("{ .reg .u64 t; cvta.to.shared.u64 t, %1; cvt.u32.u64 %0, t; }" : "=r"(a) : "l"(p));
    return a;
}
__device__ __forceinline__ void ldsm4(uint32_t* r, uint32_t addr) {
    asm volatile("ldmatrix.sync.aligned.m8n8.x4.shared.b16 {%0,%1,%2,%3}, [%4];"
                 : "=r"(r[0]), "=r"(r[1]), "=r"(r[2]), "=r"(r[3]) : "r"(addr));
}
__device__ __forceinline__ void mma_bf16(float* d, const uint32_t* a, const uint32_t* b) {
    asm volatile(
        "mma.sync.aligned.m16n8k16.row.col.f32.bf16.bf16.f32 "
        "{%0,%1,%2,%3}, {%4,%5,%6,%7}, {%8,%9}, {%0,%1,%2,%3};"
        : "+f"(d[0]), "+f"(d[1]), "+f"(d[2]), "+f"(d[3])
        : "r"(a[0]), "r"(a[1]), "r"(a[2]), "r"(a[3]), "r"(b[0]), "r"(b[1]));
}
__device__ __forceinline__ void cpa16(uint32_t dst, const void* src) {
    asm volatile("cp.async.cg.shared.global [%0], [%1], 16;" :: "r"(dst), "l"(src));
}
__device__ __forceinline__ void split4(float4 v, uint2& hp, uint2& lp) {
    __nv_bfloat16 h0 = __float2bfloat16(v.x), h1 = __float2bfloat16(v.y);
    __nv_bfloat16 h2 = __float2bfloat16(v.z), h3 = __float2bfloat16(v.w);
    hp.x = ((uint32_t)__bfloat16_as_ushort(h1) << 16) | __bfloat16_as_ushort(h0);
    hp.y = ((uint32_t)__bfloat16_as_ushort(h3) << 16) | __bfloat16_as_ushort(h2);
    __nv_bfloat16 l0 = __float2bfloat16(v.x - __bfloat162float(h0));
    __nv_bfloat16 l1 = __float2bfloat16(v.y - __bfloat162float(h1));
    __nv_bfloat16 l2 = __float2bfloat16(v.z - __bfloat162float(h2));
    __nv_bfloat16 l3 = __float2bfloat16(v.w - __bfloat162float(h3));
    lp.x = ((uint32_t)__bfloat16_as_ushort(l1) << 16) | __bfloat16_as_ushort(l0);
    lp.y = ((uint32_t)__bfloat16_as_ushort(l3) << 16) | __bfloat16_as_ushort(l2);
}
__device__ __forceinline__ uint32_t pack2bf(float a, float b) {
    __nv_bfloat16 h0 = __float2bfloat16(a), h1 = __float2bfloat16(b);
    return ((uint32_t)__bfloat16_as_ushort(h1) << 16) | __bfloat16_as_ushort(h0);
}

// ------------------- prep kernels -------------------
__global__ void split_x_k(const float* __restrict__ xu, const float* __restrict__ xi, int n4)
{
    int i = blockIdx.x * blockDim.x + threadIdx.x;
    if (i >= 2 * n4) return;
    const float* src = (i < n4) ? xu : xi;
    int j = (i < n4) ? i : i - n4;
    float4 v = reinterpret_cast<const float4*>(src)[j];
    uint2 hp, lp;
    split4(v, hp, lp);
    if (i < n4) {
        reinterpret_cast<uint2*>(g_XUh)[j] = hp;
        reinterpret_cast<uint2*>(g_XUl)[j] = lp;
    } else {
        reinterpret_cast<uint2*>(g_XIh)[j] = hp;
        reinterpret_cast<uint2*>(g_XIl)[j] = lp;
    }
}
__global__ void prep_wt_all(const float* w0, const float* w1, const float* w2,
                            const float* w3, const float* w4, const float* w5)
{
    const float* ws[6] = {w0, w1, w2, w3, w4, w5};
    int i = blockIdx.x * blockDim.x + threadIdx.x;
    if (i >= 6 * 128 * 256) return;
    int z = i >> 15, j = i & 32767;
    int n = j >> 8, k = j & 255;
    float x = ws[z][k * 128 + n];
    __nv_bfloat16 h = __float2bfloat16(x);
    g_WTh[z][j] = h;
    g_WTl[z][j] = __float2bfloat16(x - __bfloat162float(h));
}
__global__ void prep_wg_all(const float* w0, const float* w1, const float* w2,
                            const float* w3, const float* w4, const float* w5)
{
    const float* ws[6] = {w0, w1, w2, w3, w4, w5};
    int i = blockIdx.x * blockDim.x + threadIdx.x;
    if (i >= 6 * G3 * HH) return;
    int z = i / (G3 * HH), j = i % (G3 * HH);
    float x = ws[z][j];
    __nv_bfloat16 h = __float2bfloat16(x);
    g_WGh[z][j] = h;
    g_WGl[z][j] = __float2bfloat16(x - __bfloat162float(h));
}

// ------------------- hsht GEMM (BK=32, 2-stage, as R6/R7) -------------------
struct GemmPtrs {
    const __nv_bfloat16 *Ah, *Al, *Bh, *Bl;
    float* C;
    __nv_bfloat16 *Ch, *Cl;   // optional bf16 hi/lo outputs
};

__global__ void __launch_bounds__(256, 2) hsht_gemm(int M)
{
    extern __shared__ char smem[];
    const int z = blockIdx.z, r = z >> 1;
    const __nv_bfloat16* AhT[6] = {g_XUh, g_XIh, g_XIh, g_XUh, g_XIh, g_XIh};
    const __nv_bfloat16* AlT[6] = {g_XUl, g_XIl, g_XIl, g_XUl, g_XIl, g_XIl};
    GemmPtrs P;
    P.Ah = AhT[z]; P.Al = AlT[z];
    P.Bh = g_WTh[z]; P.Bl = g_WTl[z];
    P.C  = (z & 1) ? g_HT[r] : g_HS[r];
    P.Ch = (z & 1) ? g_HTh[r] : nullptr;
    P.Cl = (z & 1) ? g_HTl[r] : nullptr;
    const int K = DD, Nc = HH;
    const int m0 = blockIdx.x * 128, n0 = 0;

    const uint32_t sb = smem_u32(smem);
    const int tid  = threadIdx.x;
    const int wid  = tid >> 5;
    const int lane = tid & 31;
    const int warp_m = wid & 3;
    const int warp_n = wid >> 2;

    float acc[2][8][4];
#pragma unroll
    for (int i = 0; i < 2; i++)
#pragma unroll
        for (int j = 0; j < 8; j++)
#pragma unroll
            for (int t = 0; t < 4; t++) acc[i][j][t] = 0.f;

    const int nchunks = K >> 5;

#define FILL(kc, stg) do {                                                      \
        const int k0f = (kc) << 5;                                              \
        const uint32_t s0 = sb + (stg) * STAGE_B;                               \
        _Pragma("unroll")                                                       \
        for (int it = 0; it < 8; it++) {                                        \
            int s = tid + it * 256;                                             \
            int tile = s >> 9, w = s & 511, row = w >> 2, q = w & 3;            \
            uint32_t dst = s0 + tile * TILE_B + row * SROW + q * 16;            \
            const __nv_bfloat16* src;                                           \
            size_t off;                                                         \
            if (tile < 2) {                                                     \
                src = (tile == 0) ? P.Ah : P.Al;                                \
                off = (size_t)(m0 + row) * K + k0f + q * 8;                     \
            } else {                                                            \
                src = (tile == 2) ? P.Bh : P.Bl;                                \
                off = (size_t)(n0 + row) * K + k0f + q * 8;                     \
            }                                                                   \
            cpa16(dst, src + off);                                              \
        }                                                                       \
        asm volatile("cp.async.commit_group;" ::: "memory");                    \
    } while (0)

    FILL(0, 0);

    for (int kc = 0; kc < nchunks; kc++) {
        if (kc + 1 < nchunks) {
            FILL(kc + 1, (kc + 1) & 1);
            asm volatile("cp.async.wait_group 1;" ::: "memory");
        } else {
            asm volatile("cp.async.wait_group 0;" ::: "memory");
        }
        __syncthreads();

        const uint32_t s0  = sb + (kc & 1) * STAGE_B;
        const uint32_t sAh = s0;
        const uint32_t sAl = s0 + TILE_B;
        const uint32_t sBh = s0 + 2 * TILE_B;
        const uint32_t sBl = s0 + 3 * TILE_B;

#pragma unroll
        for (int ks = 0; ks < 2; ks++) {
            uint32_t afh[2][4], afl[2][4];
            {
                int rr = lane & 15;
                int c8 = lane >> 4;
                uint32_t off = (uint32_t)((warp_m * 32 + rr) * SROW + (ks * 16 + c8 * 8) * 2);
                ldsm4(afh[0], sAh + off);
                ldsm4(afh[1], sAh + off + 16 * SROW);
                ldsm4(afl[0], sAl + off);
                ldsm4(afl[1], sAl + off + 16 * SROW);
            }
            uint32_t bfh[8][2], bfl[8][2];
            {
                int sub = lane >> 3, wi = lane & 7;
                int n_off = (sub >> 1) * 8 + wi;
                int k_off = ks * 16 + (sub & 1) * 8;
                uint32_t base = (uint32_t)((warp_n * 64 + n_off) * SROW + k_off * 2);
#pragma unroll
                for (int jj = 0; jj < 4; jj++) {
                    uint32_t r4[4];
                    ldsm4(r4, sBh + base + jj * 16 * SROW);
                    bfh[2 * jj][0] = r4[0]; bfh[2 * jj][1] = r4[1];
                    bfh[2 * jj + 1][0] = r4[2]; bfh[2 * jj + 1][1] = r4[3];
                    ldsm4(r4, sBl + base + jj * 16 * SROW);
                    bfl[2 * jj][0] = r4[0]; bfl[2 * jj][1] = r4[1];
                    bfl[2 * jj + 1][0] = r4[2]; bfl[2 * jj + 1][1] = r4[3];
                }
            }
#pragma unroll
            for (int mi = 0; mi < 2; mi++)
#pragma unroll
                for (int j = 0; j < 8; j++) {
                    mma_bf16(acc[mi][j], afh[mi], bfh[j]);
                    mma_bf16(acc[mi][j], afh[mi], bfl[j]);
                    mma_bf16(acc[mi][j], afl[mi], bfh[j]);
                }
        }
        __syncthreads();
    }
#undef FILL

#pragma unroll
    for (int mi = 0; mi < 2; mi++) {
        int gr = m0 + warp_m * 32 + mi * 16 + (lane >> 2);
#pragma unroll
        for (int j = 0; j < 8; j++) {
            int gc = n0 + warp_n * 64 + j * 8 + 2 * (lane & 3);
#pragma unroll
            for (int half = 0; half < 2; half++) {
                int row = gr + half * 8;
                if (row >= M) continue;
                float v0 = acc[mi][j][2 * half + 0];
                float v1 = acc[mi][j][2 * half + 1];
                *reinterpret_cast<float2*>(P.C + (size_t)row * Nc + gc) =
                    make_float2(v0, v1);
                if (P.Ch) {
                    __nv_bfloat16 h0 = __float2bfloat16(v0);
                    __nv_bfloat16 h1 = __float2bfloat16(v1);
                    uint32_t hp = ((uint32_t)__bfloat16_as_ushort(h1) << 16) |
                                  __bfloat16_as_ushort(h0);
                    uint32_t lp = pack2bf(v0 - __bfloat162float(h0),
                                          v1 - __bfloat162float(h1));
                    *reinterpret_cast<uint32_t*>(P.Ch + (size_t)row * Nc + gc) = hp;
                    *reinterpret_cast<uint32_t*>(P.Cl + (size_t)row * Nc + gc) = lp;
                }
            }
        }
    }
}

// ------------------- gru GEMM: B resident in smem, A 2-stage, fp16 out ----
__global__ void __launch_bounds__(256, 2) gru_gemm(
    int M,
    const float* b0, const float* b1, const float* b2,
    const float* b3, const float* b4, const float* b5)
{
    extern __shared__ char smem[];
    const int z = blockIdx.z, r = z >> 1, which = z & 1;
    const float* biases[6] = {b0, b1, b2, b3, b4, b5};
    const __nv_bfloat16* Ah = which ? g_AGh[r] : g_HTh[r];
    const __nv_bfloat16* Al = which ? g_AGl[r] : g_HTl[r];
    const __nv_bfloat16* Bh = g_WGh[z];
    const __nv_bfloat16* Bl = g_WGl[z];
    const float* bias = biases[z];
    __half* C16 = which ? g_GH16[r] : g_GI16[r];
    const int K = HH;
    const int m0 = blockIdx.x * 128;
    const int n0 = blockIdx.y * 128;

    const uint32_t sb = smem_u32(smem);
    const uint32_t sBh = sb;
    const uint32_t sBl = sb + GB_TILE;
    const uint32_t sA0 = sb + 2 * GB_TILE;
    const int tid  = threadIdx.x;
    const int wid  = tid >> 5;
    const int lane = tid & 31;
    const int warp_m = wid & 3;
    const int warp_n = wid >> 2;

    float acc[2][8][4];
#pragma unroll
    for (int i = 0; i < 2; i++)
#pragma unroll
        for (int j = 0; j < 8; j++)
#pragma unroll
            for (int t = 0; t < 4; t++) acc[i][j][t] = 0.f;

    // ---- B prologue: 2 comps x 128 rows x 16 x 16B = 4096 cp.async ----
#pragma unroll
    for (int it = 0; it < 16; it++) {
        int s = tid + it * 256;
        int comp = s >> 11, w = s & 2047, row = w >> 4, q = w & 15;
        uint32_t dst = sb + comp * GB_TILE + row * BROW + q * 16;
        const __nv_bfloat16* src = comp ? Bl : Bh;
        cpa16(dst, src + (size_t)(n0 + row) * K + q * 8);
    }
    asm volatile("cp.async.commit_group;" ::: "memory");

    // ---- A fill: 2 comps x 128 rows x 4 x 16B = 1024 cp.async ----
#define FILLA(kc, stg) do {                                                     \
        const int k0f = (kc) << 5;                                              \
        const uint32_t s0 = sA0 + (stg) * 2 * GA_TILE;                          \
        _Pragma("unroll")                                                       \
        for (int it = 0; it < 4; it++) {                                        \
            int s = tid + it * 256;                                             \
            int comp = s >> 9, w = s & 511, row = w >> 2, q = w & 3;            \
            uint32_t dst = s0 + comp * GA_TILE + row * SROW + q * 16;           \
            const __nv_bfloat16* src = comp ? Al : Ah;                          \
            cpa16(dst, src + (size_t)(m0 + row) * K + k0f + q * 8);             \
        }                                                                       \
        asm volatile("cp.async.commit_group;" ::: "memory");                    \
    } while (0)

    FILLA(0, 0);

    const int nchunks = K >> 5;   // 4
    for (int kc = 0; kc < nchunks; kc++) {
        if (kc + 1 < nchunks) {
            FILLA(kc + 1, (kc + 1) & 1);
            asm volatile("cp.async.wait_group 1;" ::: "memory");
        } else {
            asm volatile("cp.async.wait_group 0;" ::: "memory");
        }
        __syncthreads();

        const uint32_t sAh = sA0 + (kc & 1) * 2 * GA_TILE;
        const uint32_t sAl = sAh + GA_TILE;

#pragma unroll
        for (int ks = 0; ks < 2; ks++) {
            const int kglob = kc * 32 + ks * 16;
            uint32_t afh[2][4], afl[2][4];
            {
                int rr = lane & 15;
                int c8 = lane >> 4;
                uint32_t off = (uint32_t)((warp_m * 32 + rr) * SROW + (ks * 16 + c8 * 8) * 2);
                ldsm4(afh[0], sAh + off);
                ldsm4(afh[1], sAh + off + 16 * SROW);
                ldsm4(afl[0], sAl + off);
                ldsm4(afl[1], sAl + off + 16 * SROW);
            }
            uint32_t bfh[8][2], bfl[8][2];
            {
                int sub = lane >> 3, wi = lane & 7;
                int n_off = (sub >> 1) * 8 + wi;
                int k_off = kglob + (sub & 1) * 8;
                uint32_t base = (uint32_t)((warp_n * 64 + n_off) * BROW + k_off * 2);
#pragma unroll
                for (int jj = 0; jj < 4; jj++) {
                    uint32_t r4[4];
                    ldsm4(r4, sBh + base + jj * 16 * BROW);
                    bfh[2 * jj][0] = r4[0]; bfh[2 * jj][1] = r4[1];
                    bfh[2 * jj + 1][0] = r4[2]; bfh[2 * jj + 1][1] = r4[3];
                    ldsm4(r4, sBl + base + jj * 16 * BROW);
                    bfl[2 * jj][0] = r4[0]; bfl[2 * jj][1] = r4[1];
                    bfl[2 * jj + 1][0] = r4[2]; bfl[2 * jj + 1][1] = r4[3];
                }
            }
#pragma unroll
            for (int mi = 0; mi < 2; mi++)
#pragma unroll
                for (int j = 0; j < 8; j++) {
                    mma_bf16(acc[mi][j], afh[mi], bfh[j]);
                    mma_bf16(acc[mi][j], afh[mi], bfl[j]);
                    mma_bf16(acc[mi][j], afl[mi], bfh[j]);
                }
        }
        __syncthreads();
    }
#undef FILLA

    // ---- epilogue: fp16 half2 stores ----
#pragma unroll
    for (int mi = 0; mi < 2; mi++) {
        int gr = m0 + warp_m * 32 + mi * 16 + (lane >> 2);
#pragma unroll
        for (int j = 0; j < 8; j++) {
            int gc = n0 + warp_n * 64 + j * 8 + 2 * (lane & 3);
            float bb0 = bias[gc], bb1 = bias[gc + 1];
#pragma unroll
            for (int half = 0; half < 2; half++) {
                int row = gr + half * 8;
                if (row >= M) continue;
                __half2 hv = __floats2half2_rn(acc[mi][j][2 * half + 0] + bb0,
                                               acc[mi][j][2 * half + 1] + bb1);
                *reinterpret_cast<__half2*>(C16 + (size_t)row * G3 + gc) = hv;
            }
        }
    }
}

// ------------------- CSR build -------------------
__global__ void hist_k(const int* e0, const int* e1, const int* e2, int E, int N)
{
    int e = blockIdx.x * blockDim.x + threadIdx.x;
    if (e >= 3 * E) return;
    int r = e / E, le = e - r * E;
    const int* ei = (r == 0) ? e0 : (r == 1) ? e1 : e2;
    atomicAdd(&g_CNT[r * N + ei[E + le]], 1);
}
__global__ void scan1_k(int ntot)
{
    __shared__ int sh[1024];
    int tid = threadIdx.x;
    int gid = blockIdx.x * 1024 + tid;
    int v = (gid < ntot) ? g_CNT[gid] : 0;
    sh[tid] = v;
    __syncthreads();
    for (int o = 1; o < 1024; o <<= 1) {
        int t = (tid >= o) ? sh[tid - o] : 0;
        __syncthreads();
        sh[tid] += t;
        __syncthreads();
    }
    if (gid < ntot) g_OFF[gid] = sh[tid] - v;
    if (tid == 1023) g_BSUM[blockIdx.x] = sh[1023];
}
__global__ void scan2_k(int nb)
{
    if (threadIdx.x == 0 && blockIdx.x == 0) {
        int run = 0;
        for (int i = 0; i < nb; i++) {
            int v = g_BSUM[i];
            g_BSUM[i] = run;
            run += v;
        }
    }
}
__global__ void scan3_k(int ntot)
{
    int gid = blockIdx.x * 1024 + threadIdx.x;
    if (gid >= ntot) return;
    int o = g_OFF[gid] + g_BSUM[blockIdx.x];
    g_OFF[gid] = o;
    g_CUR[gid] = o;
}
__global__ void scatter_idx_k(const int* e0, const int* e1, const int* e2, int E, int N)
{
    int e = blockIdx.x * blockDim.x + threadIdx.x;
    if (e >= 3 * E) return;
    int r = e / E, le = e - r * E;
    const int* ei = (r == 0) ? e0 : (r == 1) ? e1 : e2;
    int si = ei[le];
    int ti = ei[E + le];
    int pos = atomicAdd(&g_CUR[r * N + ti], 1);
    g_SRC[pos] = si;
}

// ------------------- gather aggregation (writes fp32 + bf16 hi/lo) -------
__global__ void gather_k(int N, int Etot)
{
    int gw   = (blockIdx.x * blockDim.x + threadIdx.x) >> 5;
    int lane = threadIdx.x & 31;
    if (gw >= 3 * N) return;
    int r = gw / N, ti = gw - r * N;
    int idx = r * N + ti;
    int s = g_OFF[idx];
    int e = (idx + 1 < 3 * N) ? g_OFF[idx + 1] : Etot;
    float* dst = g_AGG[r] + (size_t)ti * HH + lane * 4;
    uint2* dsth = reinterpret_cast<uint2*>(g_AGh[r] + (size_t)ti * HH + lane * 4);
    uint2* dstl = reinterpret_cast<uint2*>(g_AGl[r] + (size_t)ti * HH + lane * 4);
    float4 acc = make_float4(0.f, 0.f, 0.f, 0.f);
    if (s < e) {
        float at = g_AT[r][ti];
        float den = 0.f;
        for (int base = s; base < e; base += 32) {
            int k = base + lane;
            if (k < e) {
                int si = g_SRC[k];
                float l = g_AS[r][si] + at;
                l = (l > 0.f) ? l : 0.2f * l;
                den += expf(l);
            }
        }
#pragma unroll
        for (int o = 16; o; o >>= 1) den += __shfl_xor_sync(0xffffffffu, den, o);
        float inv = 1.f / (den + 1e-16f);
        for (int base = s; base < e; base += 32) {
            int k = base + lane;
            int si = 0;
            float ex = 0.f;
            if (k < e) {
                si = g_SRC[k];
                float l = g_AS[r][si] + at;
                l = (l > 0.f) ? l : 0.2f * l;
                ex = expf(l);
            }
            int cnt = min(32, e - base);
            for (int j = 0; j < cnt; j++) {
                float exj = __shfl_sync(0xffffffffu, ex, j);
                int   sij = __shfl_sync(0xffffffffu, si, j);
                float4 v = *reinterpret_cast<const float4*>(
                    g_HS[r] + (size_t)sij * HH + lane * 4);
                acc.x += exj * v.x;
                acc.y += exj * v.y;
                acc.z += exj * v.z;
                acc.w += exj * v.w;
            }
        }
        acc.x *= inv; acc.y *= inv; acc.z *= inv; acc.w *= inv;
    }
    *reinterpret_cast<float4*>(dst) = acc;
    uint2 hp, lp;
    split4(acc, hp, lp);
    *dsth = hp;
    *dstl = lp;
}

// ------------------- pointwise -------------------
__global__ void alpha_all(const float* q0, const float* q1, const float* q2, int n)
{
    int gw = (blockIdx.x * blockDim.x + threadIdx.x) >> 5;
    int lane = threadIdx.x & 31;
    if (gw >= 6 * n) return;
    int sel = gw / n, node = gw - sel * n;
    int r = sel >> 1, which = sel & 1;
    const float* qs[3] = {q0, q1, q2};
    const float* feat = which ? g_HT[r] : g_HS[r];
    const float* q = qs[r] + which * HH;
    float4 a = *reinterpret_cast<const float4*>(feat + (size_t)node * HH + lane * 4);
    float4 b = *reinterpret_cast<const float4*>(q + lane * 4);
    float s = a.x * b.x + a.y * b.y + a.z * b.z + a.w * b.w;
#pragma unroll
    for (int o = 16; o; o >>= 1) s += __shfl_xor_sync(0xffffffffu, s, o);
    if (lane == 0) {
        if (which) g_AT[r][node] = s;
        else       g_AS[r][node] = s;
    }
}

__global__ void gru_all(int n)
{
    long long i = (long long)blockIdx.x * blockDim.x + threadIdx.x;
    if (i >= 3LL * n * HH) return;
    int r = (int)(i / ((long long)n * HH));
    int j = (int)(i - (long long)r * n * HH);
    int nn = j / HH, h = j - nn * HH;
    const __half* gi = g_GI16[r] + (size_t)nn * G3;
    const __half* gh = g_GH16[r] + (size_t)nn * G3;
    float rr = 1.f / (1.f + expf(-(__half2float(gi[h]) + __half2float(gh[h]))));
    float z  = 1.f / (1.f + expf(-(__half2float(gi[HH + h]) + __half2float(gh[HH + h]))));
    float g  = tanhf(__half2float(gi[2 * HH + h]) + rr * __half2float(gh[2 * HH + h]));
    float a  = g_AGG[r][(size_t)nn * HH + h];
    g_HOUT[r][j] = (1.f - z) * g + z * a;
}

__global__ void final_k(float* __restrict__ out, const float* __restrict__ g, int n)
{
    int warp = (blockIdx.x * blockDim.x + threadIdx.x) >> 5;
    int lane = threadIdx.x & 31;
    if (warp >= n) return;
    size_t off = (size_t)warp * HH + lane * 4;
    float4 u = *reinterpret_cast<const float4*>(g_HOUT[1] + off);
    u.x = fmaxf(u.x, 0.f); u.y = fmaxf(u.y, 0.f);
    u.z = fmaxf(u.z, 0.f); u.w = fmaxf(u.w, 0.f);
    *reinterpret_cast<float4*>(out + off) = u;
    float4 v0 = *reinterpret_cast<const float4*>(g_HOUT[0] + off);
    float4 v1 = *reinterpret_cast<const float4*>(g_HOUT[2] + off);
    float4 gv = *reinterpret_cast<const float4*>(g + lane * 4);
    float d0 = v0.x * gv.x + v0.y * gv.y + v0.z * gv.z + v0.w * gv.w;
    float d1 = v1.x * gv.x + v1.y * gv.y + v1.z * gv.z + v1.w * gv.w;
#pragma unroll
    for (int o = 16; o; o >>= 1) {
        d0 += __shfl_xor_sync(0xffffffffu, d0, o);
        d1 += __shfl_xor_sync(0xffffffffu, d1, o);
    }
    float a0 = expf(d0), a1 = expf(d1);
    float inv = 1.f / (a0 + a1);
    float w0 = a0 * inv, w1 = a1 * inv;
    float4 o4;
    o4.x = fmaxf(w0 * v0.x + w1 * v1.x, 0.f);
    o4.y = fmaxf(w0 * v0.y + w1 * v1.y, 0.f);
    o4.z = fmaxf(w0 * v0.z + w1 * v1.z, 0.f);
    o4.w = fmaxf(w0 * v0.w + w1 * v1.w, 0.f);
    *reinterpret_cast<float4*>(out + (size_t)n * HH + off) = o4;
}

// ---------------------------------------------------------------
extern "C" void kernel_launch(void* const* d_in, const int* in_sizes, int n_in,
                              void* d_out, int out_size)
{
    const float* x_user = (const float*)d_in[0];
    const float* x_item = (const float*)d_in[1];
    const int*   ei_ui  = (const int*)d_in[2];
    const int*   ei_iu  = (const int*)d_in[3];
    const int*   ei_ii  = (const int*)d_in[4];

    int N = in_sizes[0] / DD;
    int E = in_sizes[2] / 2;
    if (N > NMAX) N = NMAX;
    if (E > EMAX) E = EMAX;

    float* out = (float*)d_out;

    cudaFuncSetAttribute(hsht_gemm, cudaFuncAttributeMaxDynamicSharedMemorySize, SMEMSZ);
    cudaFuncSetAttribute(gru_gemm,  cudaFuncAttributeMaxDynamicSharedMemorySize, GSMEM);

    // prep splits
    int x4 = (N * DD) / 4;
    split_x_k<<<(2 * x4 + 255) / 256, 256>>>(x_user, x_item, x4);
    prep_wt_all<<<(6 * 128 * 256 + 255) / 256, 256>>>(
        (const float*)d_in[5],  (const float*)d_in[6],
        (const float*)d_in[12], (const float*)d_in[13],
        (const float*)d_in[19], (const float*)d_in[20]);
    prep_wg_all<<<(6 * G3 * HH + 255) / 256, 256>>>(
        (const float*)d_in[8],  (const float*)d_in[9],
        (const float*)d_in[15], (const float*)d_in[16],
        (const float*)d_in[22], (const float*)d_in[23]);

    // CSR build
    int ntot = 3 * N;
    void* pcnt;
    cudaGetSymbolAddress(&pcnt, g_CNT);
    cudaMemsetAsync(pcnt, 0, ntot * sizeof(int));
    hist_k<<<(3 * E + 255) / 256, 256>>>(ei_ui, ei_iu, ei_ii, E, N);
    int nb = (ntot + 1023) / 1024;
    scan1_k<<<nb, 1024>>>(ntot);
    scan2_k<<<1, 32>>>(nb);
    scan3_k<<<nb, 1024>>>(ntot);
    scatter_idx_k<<<(3 * E + 255) / 256, 256>>>(ei_ui, ei_iu, ei_ii, E, N);

    const int mb = NPAD / 128;   // 392

    hsht_gemm<<<dim3(mb, 1, 6), 256, SMEMSZ>>>(N);

    int aBlocks = (int)(((long long)6 * N * 32 + 255) / 256);
    alpha_all<<<aBlocks, 256>>>((const float*)d_in[7], (const float*)d_in[14],
                                (const float*)d_in[21], N);

    gather_k<<<(int)(((long long)3 * N * 32 + 255) / 256), 256>>>(N, 3 * E);

    gru_gemm<<<dim3(mb, 3, 6), 256, GSMEM>>>(
        N,
        (const float*)d_in[10], (const float*)d_in[11],
        (const float*)d_in[17], (const float*)d_in[18],
        (const float*)d_in[24], (const float*)d_in[25]);

    gru_all<<<(int)((3LL * N * HH + 255) / 256), 256>>>(N);

    final_k<<<(N * 32 + 255) / 256, 256>>>(out, (const float*)d_in[27], N);
}

// round 9
// speedup vs baseline: 2.1863x; 1.0738x over previous
#include <cuda_runtime.h>
#include <cuda_bf16.h>
#include <cuda_fp16.h>
#include <math.h>
#include <cstdint>

#define NMAX 50000
#define NPAD 50176   // 392*128
#define EMAX 400000
#define DD   256
#define HH   128
#define G3   384
#define SROW 80                  // smem bytes per 32-halfword row (64B + 16B pad)
#define TILE_B (128 * SROW)      // 10240
#define STAGE_B (4 * TILE_B)     // 40960
#define SMEMSZ (2 * STAGE_B)     // 81920 (hsht)
// gru_gemm: B single fp16 resident, A (hi/lo fp16) 2-stage
#define BROW   272               // 128*2 + 16 pad
#define GB_TILE (128 * BROW)     // 34816
#define GA_TILE (128 * SROW)     // 10240
#define GSMEM  (GB_TILE + 4 * GA_TILE)  // 75776

// ------------------- scratch -------------------
__device__ __align__(16) float g_HS [3][NPAD*HH];
__device__ __align__(16) float g_HT [3][NPAD*HH];
__device__ __align__(16) float g_AGG[3][NPAD*HH];
__device__ __align__(16) __half g_GI16[3][NPAD*G3];
__device__ __align__(16) __half g_GH16[3][NPAD*G3];
__device__ __align__(16) float g_AS [3][NMAX];
__device__ __align__(16) float g_AT [3][NMAX];
__device__ __align__(16) float g_HOUT[3][NPAD*HH];
__device__ __align__(16) __nv_bfloat16 g_XUh[NPAD*DD], g_XUl[NPAD*DD];
__device__ __align__(16) __nv_bfloat16 g_XIh[NPAD*DD], g_XIl[NPAD*DD];
__device__ __align__(16) __half g_HTh[3][NPAD*HH], g_HTl[3][NPAD*HH];   // fp16 hi/lo
__device__ __align__(16) __half g_AGh[3][NPAD*HH], g_AGl[3][NPAD*HH];   // fp16 hi/lo
__device__ __align__(16) __nv_bfloat16 g_WTh[6][128*DD], g_WTl[6][128*DD];
__device__ __align__(16) __half g_WG16[6][G3*HH];                        // fp16 single
// CSR
__device__ int g_CNT [3*NMAX];
__device__ int g_OFF [3*NMAX];
__device__ int g_CUR [3*NMAX];
__device__ int g_SRC [3*EMAX];
__device__ int g_BSUM[256];

// ------------------- PTX helpers -------------------
__device__ __forceinline__ uint32_t smem_u32(const void* p) {
    uint32_t a;
    asm("{ .reg .u64 t; cvta.to.shared.u64 t, %1; cvt.u32.u64 %0, t; }" : "=r"(a) : "l"(p));
    return a;
}
__device__ __forceinline__ void ldsm4(uint32_t* r, uint32_t addr) {
    asm volatile("ldmatrix.sync.aligned.m8n8.x4.shared.b16 {%0,%1,%2,%3}, [%4];"
                 : "=r"(r[0]), "=r"(r[1]), "=r"(r[2]), "=r"(r[3]) : "r"(addr));
}
__device__ __forceinline__ void mma_bf16(float* d, const uint32_t* a, const uint32_t* b) {
    asm volatile(
        "mma.sync.aligned.m16n8k16.row.col.f32.bf16.bf16.f32 "
        "{%0,%1,%2,%3}, {%4,%5,%6,%7}, {%8,%9}, {%0,%1,%2,%3};"
        : "+f"(d[0]), "+f"(d[1]), "+f"(d[2]), "+f"(d[3])
        : "r"(a[0]), "r"(a[1]), "r"(a[2]), "r"(a[3]), "r"(b[0]), "r"(b[1]));
}
__device__ __forceinline__ void mma_f16(float* d, const uint32_t* a, const uint32_t* b) {
    asm volatile(
        "mma.sync.aligned.m16n8k16.row.col.f32.f16.f16.f32 "
        "{%0,%1,%2,%3}, {%4,%5,%6,%7}, {%8,%9}, {%0,%1,%2,%3};"
        : "+f"(d[0]), "+f"(d[1]), "+f"(d[2]), "+f"(d[3])
        : "r"(a[0]), "r"(a[1]), "r"(a[2]), "r"(a[3]), "r"(b[0]), "r"(b[1]));
}
__device__ __forceinline__ void cpa16(uint32_t dst, const void* src) {
    asm volatile("cp.async.cg.shared.global [%0], [%1], 16;" :: "r"(dst), "l"(src));
}
__device__ __forceinline__ void split4(float4 v, uint2& hp, uint2& lp) {
    __nv_bfloat16 h0 = __float2bfloat16(v.x), h1 = __float2bfloat16(v.y);
    __nv_bfloat16 h2 = __float2bfloat16(v.z), h3 = __float2bfloat16(v.w);
    hp.x = ((uint32_t)__bfloat16_as_ushort(h1) << 16) | __bfloat16_as_ushort(h0);
    hp.y = ((uint32_t)__bfloat16_as_ushort(h3) << 16) | __bfloat16_as_ushort(h2);
    __nv_bfloat16 l0 = __float2bfloat16(v.x - __bfloat162float(h0));
    __nv_bfloat16 l1 = __float2bfloat16(v.y - __bfloat162float(h1));
    __nv_bfloat16 l2 = __float2bfloat16(v.z - __bfloat162float(h2));
    __nv_bfloat16 l3 = __float2bfloat16(v.w - __bfloat162float(h3));
    lp.x = ((uint32_t)__bfloat16_as_ushort(l1) << 16) | __bfloat16_as_ushort(l0);
    lp.y = ((uint32_t)__bfloat16_as_ushort(l3) << 16) | __bfloat16_as_ushort(l2);
}
// fp16 hi/lo split of 4 floats
__device__ __forceinline__ void split4h(float4 v, uint2& hp, uint2& lp) {
    __half h0 = __float2half_rn(v.x), h1 = __float2half_rn(v.y);
    __half h2 = __float2half_rn(v.z), h3 = __float2half_rn(v.w);
    __half l0 = __float2half_rn(v.x - __half2float(h0));
    __half l1 = __float2half_rn(v.y - __half2float(h1));
    __half l2 = __float2half_rn(v.z - __half2float(h2));
    __half l3 = __float2half_rn(v.w - __half2float(h3));
    hp.x = ((uint32_t)__half_as_ushort(h1) << 16) | __half_as_ushort(h0);
    hp.y = ((uint32_t)__half_as_ushort(h3) << 16) | __half_as_ushort(h2);
    lp.x = ((uint32_t)__half_as_ushort(l1) << 16) | __half_as_ushort(l0);
    lp.y = ((uint32_t)__half_as_ushort(l3) << 16) | __half_as_ushort(l2);
}

// ------------------- prep kernels -------------------
__global__ void split_x_k(const float* __restrict__ xu, const float* __restrict__ xi, int n4)
{
    int i = blockIdx.x * blockDim.x + threadIdx.x;
    if (i >= 2 * n4) return;
    const float* src = (i < n4) ? xu : xi;
    int j = (i < n4) ? i : i - n4;
    float4 v = reinterpret_cast<const float4*>(src)[j];
    uint2 hp, lp;
    split4(v, hp, lp);
    if (i < n4) {
        reinterpret_cast<uint2*>(g_XUh)[j] = hp;
        reinterpret_cast<uint2*>(g_XUl)[j] = lp;
    } else {
        reinterpret_cast<uint2*>(g_XIh)[j] = hp;
        reinterpret_cast<uint2*>(g_XIl)[j] = lp;
    }
}
__global__ void prep_wt_all(const float* w0, const float* w1, const float* w2,
                            const float* w3, const float* w4, const float* w5)
{
    const float* ws[6] = {w0, w1, w2, w3, w4, w5};
    int i = blockIdx.x * blockDim.x + threadIdx.x;
    if (i >= 6 * 128 * 256) return;
    int z = i >> 15, j = i & 32767;
    int n = j >> 8, k = j & 255;
    float x = ws[z][k * 128 + n];
    __nv_bfloat16 h = __float2bfloat16(x);
    g_WTh[z][j] = h;
    g_WTl[z][j] = __float2bfloat16(x - __bfloat162float(h));
}
__global__ void prep_wg_all(const float* w0, const float* w1, const float* w2,
                            const float* w3, const float* w4, const float* w5)
{
    const float* ws[6] = {w0, w1, w2, w3, w4, w5};
    int i = blockIdx.x * blockDim.x + threadIdx.x;
    if (i >= 6 * G3 * HH) return;
    int z = i / (G3 * HH), j = i % (G3 * HH);
    g_WG16[z][j] = __float2half_rn(ws[z][j]);
}

// ------------------- hsht GEMM (3-term bf16, BK=32, 2-stage) --------------
__global__ void __launch_bounds__(256, 2) hsht_gemm(int M)
{
    extern __shared__ char smem[];
    const int z = blockIdx.z, r = z >> 1;
    const __nv_bfloat16* AhT[6] = {g_XUh, g_XIh, g_XIh, g_XUh, g_XIh, g_XIh};
    const __nv_bfloat16* AlT[6] = {g_XUl, g_XIl, g_XIl, g_XUl, g_XIl, g_XIl};
    const __nv_bfloat16* Ah = AhT[z];
    const __nv_bfloat16* Al = AlT[z];
    const __nv_bfloat16* Bh = g_WTh[z];
    const __nv_bfloat16* Bl = g_WTl[z];
    float* C  = (z & 1) ? g_HT[r] : g_HS[r];
    __half* Ch = (z & 1) ? g_HTh[r] : nullptr;
    __half* Cl = (z & 1) ? g_HTl[r] : nullptr;
    const int K = DD, Nc = HH;
    const int m0 = blockIdx.x * 128, n0 = 0;

    const uint32_t sb = smem_u32(smem);
    const int tid  = threadIdx.x;
    const int wid  = tid >> 5;
    const int lane = tid & 31;
    const int warp_m = wid & 3;
    const int warp_n = wid >> 2;

    float acc[2][8][4];
#pragma unroll
    for (int i = 0; i < 2; i++)
#pragma unroll
        for (int j = 0; j < 8; j++)
#pragma unroll
            for (int t = 0; t < 4; t++) acc[i][j][t] = 0.f;

    const int nchunks = K >> 5;

#define FILL(kc, stg) do {                                                      \
        const int k0f = (kc) << 5;                                              \
        const uint32_t s0 = sb + (stg) * STAGE_B;                               \
        _Pragma("unroll")                                                       \
        for (int it = 0; it < 8; it++) {                                        \
            int s = tid + it * 256;                                             \
            int tile = s >> 9, w = s & 511, row = w >> 2, q = w & 3;            \
            uint32_t dst = s0 + tile * TILE_B + row * SROW + q * 16;            \
            const __nv_bfloat16* src;                                           \
            size_t off;                                                         \
            if (tile < 2) {                                                     \
                src = (tile == 0) ? Ah : Al;                                    \
                off = (size_t)(m0 + row) * K + k0f + q * 8;                     \
            } else {                                                            \
                src = (tile == 2) ? Bh : Bl;                                    \
                off = (size_t)(n0 + row) * K + k0f + q * 8;                     \
            }                                                                   \
            cpa16(dst, src + off);                                              \
        }                                                                       \
        asm volatile("cp.async.commit_group;" ::: "memory");                    \
    } while (0)

    FILL(0, 0);

    for (int kc = 0; kc < nchunks; kc++) {
        if (kc + 1 < nchunks) {
            FILL(kc + 1, (kc + 1) & 1);
            asm volatile("cp.async.wait_group 1;" ::: "memory");
        } else {
            asm volatile("cp.async.wait_group 0;" ::: "memory");
        }
        __syncthreads();

        const uint32_t s0  = sb + (kc & 1) * STAGE_B;
        const uint32_t sAh = s0;
        const uint32_t sAl = s0 + TILE_B;
        const uint32_t sBh = s0 + 2 * TILE_B;
        const uint32_t sBl = s0 + 3 * TILE_B;

#pragma unroll
        for (int ks = 0; ks < 2; ks++) {
            uint32_t afh[2][4], afl[2][4];
            {
                int rr = lane & 15;
                int c8 = lane >> 4;
                uint32_t off = (uint32_t)((warp_m * 32 + rr) * SROW + (ks * 16 + c8 * 8) * 2);
                ldsm4(afh[0], sAh + off);
                ldsm4(afh[1], sAh + off + 16 * SROW);
                ldsm4(afl[0], sAl + off);
                ldsm4(afl[1], sAl + off + 16 * SROW);
            }
            uint32_t bfh[8][2], bfl[8][2];
            {
                int sub = lane >> 3, wi = lane & 7;
                int n_off = (sub >> 1) * 8 + wi;
                int k_off = ks * 16 + (sub & 1) * 8;
                uint32_t base = (uint32_t)((warp_n * 64 + n_off) * SROW + k_off * 2);
#pragma unroll
                for (int jj = 0; jj < 4; jj++) {
                    uint32_t r4[4];
                    ldsm4(r4, sBh + base + jj * 16 * SROW);
                    bfh[2 * jj][0] = r4[0]; bfh[2 * jj][1] = r4[1];
                    bfh[2 * jj + 1][0] = r4[2]; bfh[2 * jj + 1][1] = r4[3];
                    ldsm4(r4, sBl + base + jj * 16 * SROW);
                    bfl[2 * jj][0] = r4[0]; bfl[2 * jj][1] = r4[1];
                    bfl[2 * jj + 1][0] = r4[2]; bfl[2 * jj + 1][1] = r4[3];
                }
            }
#pragma unroll
            for (int mi = 0; mi < 2; mi++)
#pragma unroll
                for (int j = 0; j < 8; j++) {
                    mma_bf16(acc[mi][j], afh[mi], bfh[j]);
                    mma_bf16(acc[mi][j], afh[mi], bfl[j]);
                    mma_bf16(acc[mi][j], afl[mi], bfh[j]);
                }
        }
        __syncthreads();
    }
#undef FILL

#pragma unroll
    for (int mi = 0; mi < 2; mi++) {
        int gr = m0 + warp_m * 32 + mi * 16 + (lane >> 2);
#pragma unroll
        for (int j = 0; j < 8; j++) {
            int gc = n0 + warp_n * 64 + j * 8 + 2 * (lane & 3);
#pragma unroll
            for (int half = 0; half < 2; half++) {
                int row = gr + half * 8;
                if (row >= M) continue;
                float v0 = acc[mi][j][2 * half + 0];
                float v1 = acc[mi][j][2 * half + 1];
                *reinterpret_cast<float2*>(C + (size_t)row * Nc + gc) =
                    make_float2(v0, v1);
                if (Ch) {
                    __half h0 = __float2half_rn(v0), h1 = __float2half_rn(v1);
                    __half l0 = __float2half_rn(v0 - __half2float(h0));
                    __half l1 = __float2half_rn(v1 - __half2float(h1));
                    uint32_t hp = ((uint32_t)__half_as_ushort(h1) << 16) | __half_as_ushort(h0);
                    uint32_t lp = ((uint32_t)__half_as_ushort(l1) << 16) | __half_as_ushort(l0);
                    *reinterpret_cast<uint32_t*>(Ch + (size_t)row * Nc + gc) = hp;
                    *reinterpret_cast<uint32_t*>(Cl + (size_t)row * Nc + gc) = lp;
                }
            }
        }
    }
}

// ---------- gru GEMM: 2-term fp16 (A hi/lo, B single), B resident ---------
__global__ void __launch_bounds__(256, 2) gru_gemm(
    int M,
    const float* b0, const float* b1, const float* b2,
    const float* b3, const float* b4, const float* b5)
{
    extern __shared__ char smem[];
    const int z = blockIdx.z, r = z >> 1, which = z & 1;
    const float* biases[6] = {b0, b1, b2, b3, b4, b5};
    const __half* Ah = which ? g_AGh[r] : g_HTh[r];
    const __half* Al = which ? g_AGl[r] : g_HTl[r];
    const __half* B16 = g_WG16[z];
    const float* bias = biases[z];
    __half* C16 = which ? g_GH16[r] : g_GI16[r];
    const int K = HH;
    const int m0 = blockIdx.x * 128;
    const int n0 = blockIdx.y * 128;

    const uint32_t sb = smem_u32(smem);
    const uint32_t sB  = sb;
    const uint32_t sA0 = sb + GB_TILE;
    const int tid  = threadIdx.x;
    const int wid  = tid >> 5;
    const int lane = tid & 31;
    const int warp_m = wid & 3;
    const int warp_n = wid >> 2;

    float acc[2][8][4];
#pragma unroll
    for (int i = 0; i < 2; i++)
#pragma unroll
        for (int j = 0; j < 8; j++)
#pragma unroll
            for (int t = 0; t < 4; t++) acc[i][j][t] = 0.f;

    // ---- B prologue: 128 rows x 16 x 16B = 2048 cp.async ----
#pragma unroll
    for (int it = 0; it < 8; it++) {
        int s = tid + it * 256;
        int row = s >> 4, q = s & 15;
        cpa16(sB + row * BROW + q * 16, B16 + (size_t)(n0 + row) * K + q * 8);
    }
    asm volatile("cp.async.commit_group;" ::: "memory");

    // ---- A fill: 2 comps x 128 rows x 4 x 16B = 1024 cp.async ----
#define FILLA(kc, stg) do {                                                     \
        const int k0f = (kc) << 5;                                              \
        const uint32_t s0 = sA0 + (stg) * 2 * GA_TILE;                          \
        _Pragma("unroll")                                                       \
        for (int it = 0; it < 4; it++) {                                        \
            int s = tid + it * 256;                                             \
            int comp = s >> 9, w = s & 511, row = w >> 2, q = w & 3;            \
            uint32_t dst = s0 + comp * GA_TILE + row * SROW + q * 16;           \
            const __half* src = comp ? Al : Ah;                                 \
            cpa16(dst, src + (size_t)(m0 + row) * K + k0f + q * 8);             \
        }                                                                       \
        asm volatile("cp.async.commit_group;" ::: "memory");                    \
    } while (0)

    FILLA(0, 0);

    const int nchunks = K >> 5;   // 4
    for (int kc = 0; kc < nchunks; kc++) {
        if (kc + 1 < nchunks) {
            FILLA(kc + 1, (kc + 1) & 1);
            asm volatile("cp.async.wait_group 1;" ::: "memory");
        } else {
            asm volatile("cp.async.wait_group 0;" ::: "memory");
        }
        __syncthreads();

        const uint32_t sAh = sA0 + (kc & 1) * 2 * GA_TILE;
        const uint32_t sAl = sAh + GA_TILE;

#pragma unroll
        for (int ks = 0; ks < 2; ks++) {
            const int kglob = kc * 32 + ks * 16;
            uint32_t afh[2][4], afl[2][4];
            {
                int rr = lane & 15;
                int c8 = lane >> 4;
                uint32_t off = (uint32_t)((warp_m * 32 + rr) * SROW + (ks * 16 + c8 * 8) * 2);
                ldsm4(afh[0], sAh + off);
                ldsm4(afh[1], sAh + off + 16 * SROW);
                ldsm4(afl[0], sAl + off);
                ldsm4(afl[1], sAl + off + 16 * SROW);
            }
            uint32_t bf[8][2];
            {
                int sub = lane >> 3, wi = lane & 7;
                int n_off = (sub >> 1) * 8 + wi;
                int k_off = kglob + (sub & 1) * 8;
                uint32_t base = (uint32_t)((warp_n * 64 + n_off) * BROW + k_off * 2);
#pragma unroll
                for (int jj = 0; jj < 4; jj++) {
                    uint32_t r4[4];
                    ldsm4(r4, sB + base + jj * 16 * BROW);
                    bf[2 * jj][0] = r4[0]; bf[2 * jj][1] = r4[1];
                    bf[2 * jj + 1][0] = r4[2]; bf[2 * jj + 1][1] = r4[3];
                }
            }
#pragma unroll
            for (int mi = 0; mi < 2; mi++)
#pragma unroll
                for (int j = 0; j < 8; j++) {
                    mma_f16(acc[mi][j], afh[mi], bf[j]);
                    mma_f16(acc[mi][j], afl[mi], bf[j]);
                }
        }
        __syncthreads();
    }
#undef FILLA

    // ---- epilogue: fp16 half2 stores ----
#pragma unroll
    for (int mi = 0; mi < 2; mi++) {
        int gr = m0 + warp_m * 32 + mi * 16 + (lane >> 2);
#pragma unroll
        for (int j = 0; j < 8; j++) {
            int gc = n0 + warp_n * 64 + j * 8 + 2 * (lane & 3);
            float bb0 = bias[gc], bb1 = bias[gc + 1];
#pragma unroll
            for (int half = 0; half < 2; half++) {
                int row = gr + half * 8;
                if (row >= M) continue;
                __half2 hv = __floats2half2_rn(acc[mi][j][2 * half + 0] + bb0,
                                               acc[mi][j][2 * half + 1] + bb1);
                *reinterpret_cast<__half2*>(C16 + (size_t)row * G3 + gc) = hv;
            }
        }
    }
}

// ------------------- CSR build -------------------
__global__ void hist_k(const int* e0, const int* e1, const int* e2, int E, int N)
{
    int e = blockIdx.x * blockDim.x + threadIdx.x;
    if (e >= 3 * E) return;
    int r = e / E, le = e - r * E;
    const int* ei = (r == 0) ? e0 : (r == 1) ? e1 : e2;
    atomicAdd(&g_CNT[r * N + ei[E + le]], 1);
}
__global__ void scan1_k(int ntot)
{
    __shared__ int sh[1024];
    int tid = threadIdx.x;
    int gid = blockIdx.x * 1024 + tid;
    int v = (gid < ntot) ? g_CNT[gid] : 0;
    sh[tid] = v;
    __syncthreads();
    for (int o = 1; o < 1024; o <<= 1) {
        int t = (tid >= o) ? sh[tid - o] : 0;
        __syncthreads();
        sh[tid] += t;
        __syncthreads();
    }
    if (gid < ntot) g_OFF[gid] = sh[tid] - v;
    if (tid == 1023) g_BSUM[blockIdx.x] = sh[1023];
}
__global__ void scan2_k(int nb)
{
    if (threadIdx.x == 0 && blockIdx.x == 0) {
        int run = 0;
        for (int i = 0; i < nb; i++) {
            int v = g_BSUM[i];
            g_BSUM[i] = run;
            run += v;
        }
    }
}
__global__ void scan3_k(int ntot)
{
    int gid = blockIdx.x * 1024 + threadIdx.x;
    if (gid >= ntot) return;
    int o = g_OFF[gid] + g_BSUM[blockIdx.x];
    g_OFF[gid] = o;
    g_CUR[gid] = o;
}
__global__ void scatter_idx_k(const int* e0, const int* e1, const int* e2, int E, int N)
{
    int e = blockIdx.x * blockDim.x + threadIdx.x;
    if (e >= 3 * E) return;
    int r = e / E, le = e - r * E;
    const int* ei = (r == 0) ? e0 : (r == 1) ? e1 : e2;
    int si = ei[le];
    int ti = ei[E + le];
    int pos = atomicAdd(&g_CUR[r * N + ti], 1);
    g_SRC[pos] = si;
}

// ------------------- gather aggregation (writes fp32 + fp16 hi/lo) -------
__global__ void gather_k(int N, int Etot)
{
    int gw   = (blockIdx.x * blockDim.x + threadIdx.x) >> 5;
    int lane = threadIdx.x & 31;
    if (gw >= 3 * N) return;
    int r = gw / N, ti = gw - r * N;
    int idx = r * N + ti;
    int s = g_OFF[idx];
    int e = (idx + 1 < 3 * N) ? g_OFF[idx + 1] : Etot;
    float* dst = g_AGG[r] + (size_t)ti * HH + lane * 4;
    uint2* dsth = reinterpret_cast<uint2*>(g_AGh[r] + (size_t)ti * HH + lane * 4);
    uint2* dstl = reinterpret_cast<uint2*>(g_AGl[r] + (size_t)ti * HH + lane * 4);
    float4 acc = make_float4(0.f, 0.f, 0.f, 0.f);
    if (s < e) {
        float at = g_AT[r][ti];
        float den = 0.f;
        for (int base = s; base < e; base += 32) {
            int k = base + lane;
            if (k < e) {
                int si = g_SRC[k];
                float l = g_AS[r][si] + at;
                l = (l > 0.f) ? l : 0.2f * l;
                den += expf(l);
            }
        }
#pragma unroll
        for (int o = 16; o; o >>= 1) den += __shfl_xor_sync(0xffffffffu, den, o);
        float inv = 1.f / (den + 1e-16f);
        for (int base = s; base < e; base += 32) {
            int k = base + lane;
            int si = 0;
            float ex = 0.f;
            if (k < e) {
                si = g_SRC[k];
                float l = g_AS[r][si] + at;
                l = (l > 0.f) ? l : 0.2f * l;
                ex = expf(l);
            }
            int cnt = min(32, e - base);
            for (int j = 0; j < cnt; j++) {
                float exj = __shfl_sync(0xffffffffu, ex, j);
                int   sij = __shfl_sync(0xffffffffu, si, j);
                float4 v = *reinterpret_cast<const float4*>(
                    g_HS[r] + (size_t)sij * HH + lane * 4);
                acc.x += exj * v.x;
                acc.y += exj * v.y;
                acc.z += exj * v.z;
                acc.w += exj * v.w;
            }
        }
        acc.x *= inv; acc.y *= inv; acc.z *= inv; acc.w *= inv;
    }
    *reinterpret_cast<float4*>(dst) = acc;
    uint2 hp, lp;
    split4h(acc, hp, lp);
    *dsth = hp;
    *dstl = lp;
}

// ------------------- pointwise -------------------
__global__ void alpha_all(const float* q0, const float* q1, const float* q2, int n)
{
    int gw = (blockIdx.x * blockDim.x + threadIdx.x) >> 5;
    int lane = threadIdx.x & 31;
    if (gw >= 6 * n) return;
    int sel = gw / n, node = gw - sel * n;
    int r = sel >> 1, which = sel & 1;
    const float* qs[3] = {q0, q1, q2};
    const float* feat = which ? g_HT[r] : g_HS[r];
    const float* q = qs[r] + which * HH;
    float4 a = *reinterpret_cast<const float4*>(feat + (size_t)node * HH + lane * 4);
    float4 b = *reinterpret_cast<const float4*>(q + lane * 4);
    float s = a.x * b.x + a.y * b.y + a.z * b.z + a.w * b.w;
#pragma unroll
    for (int o = 16; o; o >>= 1) s += __shfl_xor_sync(0xffffffffu, s, o);
    if (lane == 0) {
        if (which) g_AT[r][node] = s;
        else       g_AS[r][node] = s;
    }
}

__global__ void gru_all(int n)
{
    long long i = (long long)blockIdx.x * blockDim.x + threadIdx.x;
    if (i >= 3LL * n * HH) return;
    int r = (int)(i / ((long long)n * HH));
    int j = (int)(i - (long long)r * n * HH);
    int nn = j / HH, h = j - nn * HH;
    const __half* gi = g_GI16[r] + (size_t)nn * G3;
    const __half* gh = g_GH16[r] + (size_t)nn * G3;
    float rr = 1.f / (1.f + expf(-(__half2float(gi[h]) + __half2float(gh[h]))));
    float z  = 1.f / (1.f + expf(-(__half2float(gi[HH + h]) + __half2float(gh[HH + h]))));
    float g  = tanhf(__half2float(gi[2 * HH + h]) + rr * __half2float(gh[2 * HH + h]));
    float a  = g_AGG[r][(size_t)nn * HH + h];
    g_HOUT[r][j] = (1.f - z) * g + z * a;
}

__global__ void final_k(float* __restrict__ out, const float* __restrict__ g, int n)
{
    int warp = (blockIdx.x * blockDim.x + threadIdx.x) >> 5;
    int lane = threadIdx.x & 31;
    if (warp >= n) return;
    size_t off = (size_t)warp * HH + lane * 4;
    float4 u = *reinterpret_cast<const float4*>(g_HOUT[1] + off);
    u.x = fmaxf(u.x, 0.f); u.y = fmaxf(u.y, 0.f);
    u.z = fmaxf(u.z, 0.f); u.w = fmaxf(u.w, 0.f);
    *reinterpret_cast<float4*>(out + off) = u;
    float4 v0 = *reinterpret_cast<const float4*>(g_HOUT[0] + off);
    float4 v1 = *reinterpret_cast<const float4*>(g_HOUT[2] + off);
    float4 gv = *reinterpret_cast<const float4*>(g + lane * 4);
    float d0 = v0.x * gv.x + v0.y * gv.y + v0.z * gv.z + v0.w * gv.w;
    float d1 = v1.x * gv.x + v1.y * gv.y + v1.z * gv.z + v1.w * gv.w;
#pragma unroll
    for (int o = 16; o; o >>= 1) {
        d0 += __shfl_xor_sync(0xffffffffu, d0, o);
        d1 += __shfl_xor_sync(0xffffffffu, d1, o);
    }
    float a0 = expf(d0), a1 = expf(d1);
    float inv = 1.f / (a0 + a1);
    float w0 = a0 * inv, w1 = a1 * inv;
    float4 o4;
    o4.x = fmaxf(w0 * v0.x + w1 * v1.x, 0.f);
    o4.y = fmaxf(w0 * v0.y + w1 * v1.y, 0.f);
    o4.z = fmaxf(w0 * v0.z + w1 * v1.z, 0.f);
    o4.w = fmaxf(w0 * v0.w + w1 * v1.w, 0.f);
    *reinterpret_cast<float4*>(out + (size_t)n * HH + off) = o4;
}

// ---------------------------------------------------------------
extern "C" void kernel_launch(void* const* d_in, const int* in_sizes, int n_in,
                              void* d_out, int out_size)
{
    const float* x_user = (const float*)d_in[0];
    const float* x_item = (const float*)d_in[1];
    const int*   ei_ui  = (const int*)d_in[2];
    const int*   ei_iu  = (const int*)d_in[3];
    const int*   ei_ii  = (const int*)d_in[4];

    int N = in_sizes[0] / DD;
    int E = in_sizes[2] / 2;
    if (N > NMAX) N = NMAX;
    if (E > EMAX) E = EMAX;

    float* out = (float*)d_out;

    cudaFuncSetAttribute(hsht_gemm, cudaFuncAttributeMaxDynamicSharedMemorySize, SMEMSZ);
    cudaFuncSetAttribute(gru_gemm,  cudaFuncAttributeMaxDynamicSharedMemorySize, GSMEM);

    // prep splits
    int x4 = (N * DD) / 4;
    split_x_k<<<(2 * x4 + 255) / 256, 256>>>(x_user, x_item, x4);
    prep_wt_all<<<(6 * 128 * 256 + 255) / 256, 256>>>(
        (const float*)d_in[5],  (const float*)d_in[6],
        (const float*)d_in[12], (const float*)d_in[13],
        (const float*)d_in[19], (const float*)d_in[20]);
    prep_wg_all<<<(6 * G3 * HH + 255) / 256, 256>>>(
        (const float*)d_in[8],  (const float*)d_in[9],
        (const float*)d_in[15], (const float*)d_in[16],
        (const float*)d_in[22], (const float*)d_in[23]);

    // CSR build
    int ntot = 3 * N;
    void* pcnt;
    cudaGetSymbolAddress(&pcnt, g_CNT);
    cudaMemsetAsync(pcnt, 0, ntot * sizeof(int));
    hist_k<<<(3 * E + 255) / 256, 256>>>(ei_ui, ei_iu, ei_ii, E, N);
    int nb = (ntot + 1023) / 1024;
    scan1_k<<<nb, 1024>>>(ntot);
    scan2_k<<<1, 32>>>(nb);
    scan3_k<<<nb, 1024>>>(ntot);
    scatter_idx_k<<<(3 * E + 255) / 256, 256>>>(ei_ui, ei_iu, ei_ii, E, N);

    const int mb = NPAD / 128;   // 392

    hsht_gemm<<<dim3(mb, 1, 6), 256, SMEMSZ>>>(N);

    int aBlocks = (int)(((long long)6 * N * 32 + 255) / 256);
    alpha_all<<<aBlocks, 256>>>((const float*)d_in[7], (const float*)d_in[14],
                                (const float*)d_in[21], N);

    gather_k<<<(int)(((long long)3 * N * 32 + 255) / 256), 256>>>(N, 3 * E);

    gru_gemm<<<dim3(mb, 3, 6), 256, GSMEM>>>(
        N,
        (const float*)d_in[10], (const float*)d_in[11],
        (const float*)d_in[17], (const float*)d_in[18],
        (const float*)d_in[24], (const float*)d_in[25]);

    gru_all<<<(int)((3LL * N * HH + 255) / 256), 256>>>(N);

    final_k<<<(N * 32 + 255) / 256, 256>>>(out, (const float*)d_in[27], N);
}

// round 10
// speedup vs baseline: 2.3086x; 1.0559x over previous
#include <cuda_runtime.h>
#include <cuda_bf16.h>
#include <cuda_fp16.h>
#include <math.h>
#include <cstdint>

#define NMAX 50000
#define NPAD 50176   // 392*128
#define EMAX 400000
#define DD   256
#define HH   128
#define G3   384
#define SROW 80                  // smem bytes per 32-halfword row (64B + 16B pad)
#define TILE_B (128 * SROW)      // 10240
#define HSTAGE (3 * TILE_B)      // 30720 (hsht: Ah, Al, B16)
#define SMEMSZ (2 * HSTAGE)      // 61440
// gru_gemm: B single fp16 resident, A (hi/lo fp16) 2-stage
#define BROW   272               // 128*2 + 16 pad
#define GB_TILE (128 * BROW)     // 34816
#define GA_TILE (128 * SROW)     // 10240
#define GSMEM  (GB_TILE + 4 * GA_TILE)  // 75776

// ------------------- scratch -------------------
__device__ __align__(16) float g_HS [3][NPAD*HH];
__device__ __align__(16) float g_HT [3][NPAD*HH];
__device__ __align__(16) float g_AGG[3][NPAD*HH];
__device__ __align__(16) __half g_GI16[3][NPAD*G3];
__device__ __align__(16) __half g_GH16[3][NPAD*G3];
__device__ __align__(16) float g_AS [3][NMAX];
__device__ __align__(16) float g_AT [3][NMAX];
__device__ __align__(16) float g_HOUT[3][NPAD*HH];
__device__ __align__(16) __half g_XUh[NPAD*DD], g_XUl[NPAD*DD];   // fp16 hi/lo
__device__ __align__(16) __half g_XIh[NPAD*DD], g_XIl[NPAD*DD];
__device__ __align__(16) __half g_HTh[3][NPAD*HH], g_HTl[3][NPAD*HH];
__device__ __align__(16) __half g_AGh[3][NPAD*HH], g_AGl[3][NPAD*HH];
__device__ __align__(16) __half g_WT16[6][128*DD];                 // fp16 single
__device__ __align__(16) __half g_WG16[6][G3*HH];                  // fp16 single
// CSR
__device__ int g_CNT [3*NMAX];
__device__ int g_OFF [3*NMAX];
__device__ int g_CUR [3*NMAX];
__device__ int g_SRC [3*EMAX];
__device__ int g_BSUM[256];

// ------------------- PTX helpers -------------------
__device__ __forceinline__ uint32_t smem_u32(const void* p) {
    uint32_t a;
    asm("{ .reg .u64 t; cvta.to.shared.u64 t, %1; cvt.u32.u64 %0, t; }" : "=r"(a) : "l"(p));
    return a;
}
__device__ __forceinline__ void ldsm4(uint32_t* r, uint32_t addr) {
    asm volatile("ldmatrix.sync.aligned.m8n8.x4.shared.b16 {%0,%1,%2,%3}, [%4];"
                 : "=r"(r[0]), "=r"(r[1]), "=r"(r[2]), "=r"(r[3]) : "r"(addr));
}
__device__ __forceinline__ void mma_f16(float* d, const uint32_t* a, const uint32_t* b) {
    asm volatile(
        "mma.sync.aligned.m16n8k16.row.col.f32.f16.f16.f32 "
        "{%0,%1,%2,%3}, {%4,%5,%6,%7}, {%8,%9}, {%0,%1,%2,%3};"
        : "+f"(d[0]), "+f"(d[1]), "+f"(d[2]), "+f"(d[3])
        : "r"(a[0]), "r"(a[1]), "r"(a[2]), "r"(a[3]), "r"(b[0]), "r"(b[1]));
}
__device__ __forceinline__ void cpa16(uint32_t dst, const void* src) {
    asm volatile("cp.async.cg.shared.global [%0], [%1], 16;" :: "r"(dst), "l"(src));
}
// fp16 hi/lo split of 4 floats
__device__ __forceinline__ void split4h(float4 v, uint2& hp, uint2& lp) {
    __half h0 = __float2half_rn(v.x), h1 = __float2half_rn(v.y);
    __half h2 = __float2half_rn(v.z), h3 = __float2half_rn(v.w);
    __half l0 = __float2half_rn(v.x - __half2float(h0));
    __half l1 = __float2half_rn(v.y - __half2float(h1));
    __half l2 = __float2half_rn(v.z - __half2float(h2));
    __half l3 = __float2half_rn(v.w - __half2float(h3));
    hp.x = ((uint32_t)__half_as_ushort(h1) << 16) | __half_as_ushort(h0);
    hp.y = ((uint32_t)__half_as_ushort(h3) << 16) | __half_as_ushort(h2);
    lp.x = ((uint32_t)__half_as_ushort(l1) << 16) | __half_as_ushort(l0);
    lp.y = ((uint32_t)__half_as_ushort(l3) << 16) | __half_as_ushort(l2);
}

// ------------------- prep kernels -------------------
__global__ void split_x_k(const float* __restrict__ xu, const float* __restrict__ xi, int n4)
{
    int i = blockIdx.x * blockDim.x + threadIdx.x;
    if (i >= 2 * n4) return;
    const float* src = (i < n4) ? xu : xi;
    int j = (i < n4) ? i : i - n4;
    float4 v = reinterpret_cast<const float4*>(src)[j];
    uint2 hp, lp;
    split4h(v, hp, lp);
    if (i < n4) {
        reinterpret_cast<uint2*>(g_XUh)[j] = hp;
        reinterpret_cast<uint2*>(g_XUl)[j] = lp;
    } else {
        reinterpret_cast<uint2*>(g_XIh)[j] = hp;
        reinterpret_cast<uint2*>(g_XIl)[j] = lp;
    }
}
__global__ void prep_wt_all(const float* w0, const float* w1, const float* w2,
                            const float* w3, const float* w4, const float* w5)
{
    const float* ws[6] = {w0, w1, w2, w3, w4, w5};
    int i = blockIdx.x * blockDim.x + threadIdx.x;
    if (i >= 6 * 128 * 256) return;
    int z = i >> 15, j = i & 32767;
    int n = j >> 8, k = j & 255;
    g_WT16[z][j] = __float2half_rn(ws[z][k * 128 + n]);
}
__global__ void prep_wg_all(const float* w0, const float* w1, const float* w2,
                            const float* w3, const float* w4, const float* w5)
{
    const float* ws[6] = {w0, w1, w2, w3, w4, w5};
    int i = blockIdx.x * blockDim.x + threadIdx.x;
    if (i >= 6 * G3 * HH) return;
    int z = i / (G3 * HH), j = i % (G3 * HH);
    g_WG16[z][j] = __float2half_rn(ws[z][j]);
}

// -------- hsht GEMM: 2-term fp16 (A hi/lo, B single), BK=32, 2-stage ------
__global__ void __launch_bounds__(256, 2) hsht_gemm(int M)
{
    extern __shared__ char smem[];
    const int z = blockIdx.z, r = z >> 1;
    const __half* AhT[6] = {g_XUh, g_XIh, g_XIh, g_XUh, g_XIh, g_XIh};
    const __half* AlT[6] = {g_XUl, g_XIl, g_XIl, g_XUl, g_XIl, g_XIl};
    const __half* Ah = AhT[z];
    const __half* Al = AlT[z];
    const __half* B16 = g_WT16[z];
    float* C  = (z & 1) ? g_HT[r] : g_HS[r];
    __half* Ch = (z & 1) ? g_HTh[r] : nullptr;
    __half* Cl = (z & 1) ? g_HTl[r] : nullptr;
    const int K = DD, Nc = HH;
    const int m0 = blockIdx.x * 128, n0 = 0;

    const uint32_t sb = smem_u32(smem);
    const int tid  = threadIdx.x;
    const int wid  = tid >> 5;
    const int lane = tid & 31;
    const int warp_m = wid & 3;
    const int warp_n = wid >> 2;

    float acc[2][8][4];
#pragma unroll
    for (int i = 0; i < 2; i++)
#pragma unroll
        for (int j = 0; j < 8; j++)
#pragma unroll
            for (int t = 0; t < 4; t++) acc[i][j][t] = 0.f;

    const int nchunks = K >> 5;   // 8

    // fill: 3 tiles x 512 = 1536 cp.async, 6 per thread
#define FILL(kc, stg) do {                                                      \
        const int k0f = (kc) << 5;                                              \
        const uint32_t s0 = sb + (stg) * HSTAGE;                                \
        _Pragma("unroll")                                                       \
        for (int it = 0; it < 6; it++) {                                        \
            int s = tid + it * 256;                                             \
            int tile = s >> 9, w = s & 511, row = w >> 2, q = w & 3;            \
            uint32_t dst = s0 + tile * TILE_B + row * SROW + q * 16;            \
            const __half* src;                                                  \
            size_t off;                                                         \
            if (tile < 2) {                                                     \
                src = (tile == 0) ? Ah : Al;                                    \
                off = (size_t)(m0 + row) * K + k0f + q * 8;                     \
            } else {                                                            \
                src = B16;                                                      \
                off = (size_t)(n0 + row) * K + k0f + q * 8;                     \
            }                                                                   \
            cpa16(dst, src + off);                                              \
        }                                                                       \
        asm volatile("cp.async.commit_group;" ::: "memory");                    \
    } while (0)

    FILL(0, 0);

    for (int kc = 0; kc < nchunks; kc++) {
        if (kc + 1 < nchunks) {
            FILL(kc + 1, (kc + 1) & 1);
            asm volatile("cp.async.wait_group 1;" ::: "memory");
        } else {
            asm volatile("cp.async.wait_group 0;" ::: "memory");
        }
        __syncthreads();

        const uint32_t s0  = sb + (kc & 1) * HSTAGE;
        const uint32_t sAh = s0;
        const uint32_t sAl = s0 + TILE_B;
        const uint32_t sB  = s0 + 2 * TILE_B;

#pragma unroll
        for (int ks = 0; ks < 2; ks++) {
            uint32_t afh[2][4], afl[2][4];
            {
                int rr = lane & 15;
                int c8 = lane >> 4;
                uint32_t off = (uint32_t)((warp_m * 32 + rr) * SROW + (ks * 16 + c8 * 8) * 2);
                ldsm4(afh[0], sAh + off);
                ldsm4(afh[1], sAh + off + 16 * SROW);
                ldsm4(afl[0], sAl + off);
                ldsm4(afl[1], sAl + off + 16 * SROW);
            }
            uint32_t bf[8][2];
            {
                int sub = lane >> 3, wi = lane & 7;
                int n_off = (sub >> 1) * 8 + wi;
                int k_off = ks * 16 + (sub & 1) * 8;
                uint32_t base = (uint32_t)((warp_n * 64 + n_off) * SROW + k_off * 2);
#pragma unroll
                for (int jj = 0; jj < 4; jj++) {
                    uint32_t r4[4];
                    ldsm4(r4, sB + base + jj * 16 * SROW);
                    bf[2 * jj][0] = r4[0]; bf[2 * jj][1] = r4[1];
                    bf[2 * jj + 1][0] = r4[2]; bf[2 * jj + 1][1] = r4[3];
                }
            }
#pragma unroll
            for (int mi = 0; mi < 2; mi++)
#pragma unroll
                for (int j = 0; j < 8; j++) {
                    mma_f16(acc[mi][j], afh[mi], bf[j]);
                    mma_f16(acc[mi][j], afl[mi], bf[j]);
                }
        }
        __syncthreads();
    }
#undef FILL

#pragma unroll
    for (int mi = 0; mi < 2; mi++) {
        int gr = m0 + warp_m * 32 + mi * 16 + (lane >> 2);
#pragma unroll
        for (int j = 0; j < 8; j++) {
            int gc = n0 + warp_n * 64 + j * 8 + 2 * (lane & 3);
#pragma unroll
            for (int half = 0; half < 2; half++) {
                int row = gr + half * 8;
                if (row >= M) continue;
                float v0 = acc[mi][j][2 * half + 0];
                float v1 = acc[mi][j][2 * half + 1];
                *reinterpret_cast<float2*>(C + (size_t)row * Nc + gc) =
                    make_float2(v0, v1);
                if (Ch) {
                    __half h0 = __float2half_rn(v0), h1 = __float2half_rn(v1);
                    __half l0 = __float2half_rn(v0 - __half2float(h0));
                    __half l1 = __float2half_rn(v1 - __half2float(h1));
                    uint32_t hp = ((uint32_t)__half_as_ushort(h1) << 16) | __half_as_ushort(h0);
                    uint32_t lp = ((uint32_t)__half_as_ushort(l1) << 16) | __half_as_ushort(l0);
                    *reinterpret_cast<uint32_t*>(Ch + (size_t)row * Nc + gc) = hp;
                    *reinterpret_cast<uint32_t*>(Cl + (size_t)row * Nc + gc) = lp;
                }
            }
        }
    }
}

// ---------- gru GEMM: 2-term fp16 (A hi/lo, B single), B resident ---------
__global__ void __launch_bounds__(256, 2) gru_gemm(
    int M,
    const float* b0, const float* b1, const float* b2,
    const float* b3, const float* b4, const float* b5)
{
    extern __shared__ char smem[];
    const int z = blockIdx.z, r = z >> 1, which = z & 1;
    const float* biases[6] = {b0, b1, b2, b3, b4, b5};
    const __half* Ah = which ? g_AGh[r] : g_HTh[r];
    const __half* Al = which ? g_AGl[r] : g_HTl[r];
    const __half* B16 = g_WG16[z];
    const float* bias = biases[z];
    __half* C16 = which ? g_GH16[r] : g_GI16[r];
    const int K = HH;
    const int m0 = blockIdx.x * 128;
    const int n0 = blockIdx.y * 128;

    const uint32_t sb = smem_u32(smem);
    const uint32_t sB  = sb;
    const uint32_t sA0 = sb + GB_TILE;
    const int tid  = threadIdx.x;
    const int wid  = tid >> 5;
    const int lane = tid & 31;
    const int warp_m = wid & 3;
    const int warp_n = wid >> 2;

    float acc[2][8][4];
#pragma unroll
    for (int i = 0; i < 2; i++)
#pragma unroll
        for (int j = 0; j < 8; j++)
#pragma unroll
            for (int t = 0; t < 4; t++) acc[i][j][t] = 0.f;

    // B prologue
#pragma unroll
    for (int it = 0; it < 8; it++) {
        int s = tid + it * 256;
        int row = s >> 4, q = s & 15;
        cpa16(sB + row * BROW + q * 16, B16 + (size_t)(n0 + row) * K + q * 8);
    }
    asm volatile("cp.async.commit_group;" ::: "memory");

#define FILLA(kc, stg) do {                                                     \
        const int k0f = (kc) << 5;                                              \
        const uint32_t s0 = sA0 + (stg) * 2 * GA_TILE;                          \
        _Pragma("unroll")                                                       \
        for (int it = 0; it < 4; it++) {                                        \
            int s = tid + it * 256;                                             \
            int comp = s >> 9, w = s & 511, row = w >> 2, q = w & 3;            \
            uint32_t dst = s0 + comp * GA_TILE + row * SROW + q * 16;           \
            const __half* src = comp ? Al : Ah;                                 \
            cpa16(dst, src + (size_t)(m0 + row) * K + k0f + q * 8);             \
        }                                                                       \
        asm volatile("cp.async.commit_group;" ::: "memory");                    \
    } while (0)

    FILLA(0, 0);

    const int nchunks = K >> 5;   // 4
    for (int kc = 0; kc < nchunks; kc++) {
        if (kc + 1 < nchunks) {
            FILLA(kc + 1, (kc + 1) & 1);
            asm volatile("cp.async.wait_group 1;" ::: "memory");
        } else {
            asm volatile("cp.async.wait_group 0;" ::: "memory");
        }
        __syncthreads();

        const uint32_t sAh = sA0 + (kc & 1) * 2 * GA_TILE;
        const uint32_t sAl = sAh + GA_TILE;

#pragma unroll
        for (int ks = 0; ks < 2; ks++) {
            const int kglob = kc * 32 + ks * 16;
            uint32_t afh[2][4], afl[2][4];
            {
                int rr = lane & 15;
                int c8 = lane >> 4;
                uint32_t off = (uint32_t)((warp_m * 32 + rr) * SROW + (ks * 16 + c8 * 8) * 2);
                ldsm4(afh[0], sAh + off);
                ldsm4(afh[1], sAh + off + 16 * SROW);
                ldsm4(afl[0], sAl + off);
                ldsm4(afl[1], sAl + off + 16 * SROW);
            }
            uint32_t bf[8][2];
            {
                int sub = lane >> 3, wi = lane & 7;
                int n_off = (sub >> 1) * 8 + wi;
                int k_off = kglob + (sub & 1) * 8;
                uint32_t base = (uint32_t)((warp_n * 64 + n_off) * BROW + k_off * 2);
#pragma unroll
                for (int jj = 0; jj < 4; jj++) {
                    uint32_t r4[4];
                    ldsm4(r4, sB + base + jj * 16 * BROW);
                    bf[2 * jj][0] = r4[0]; bf[2 * jj][1] = r4[1];
                    bf[2 * jj + 1][0] = r4[2]; bf[2 * jj + 1][1] = r4[3];
                }
            }
#pragma unroll
            for (int mi = 0; mi < 2; mi++)
#pragma unroll
                for (int j = 0; j < 8; j++) {
                    mma_f16(acc[mi][j], afh[mi], bf[j]);
                    mma_f16(acc[mi][j], afl[mi], bf[j]);
                }
        }
        __syncthreads();
    }
#undef FILLA

#pragma unroll
    for (int mi = 0; mi < 2; mi++) {
        int gr = m0 + warp_m * 32 + mi * 16 + (lane >> 2);
#pragma unroll
        for (int j = 0; j < 8; j++) {
            int gc = n0 + warp_n * 64 + j * 8 + 2 * (lane & 3);
            float bb0 = bias[gc], bb1 = bias[gc + 1];
#pragma unroll
            for (int half = 0; half < 2; half++) {
                int row = gr + half * 8;
                if (row >= M) continue;
                __half2 hv = __floats2half2_rn(acc[mi][j][2 * half + 0] + bb0,
                                               acc[mi][j][2 * half + 1] + bb1);
                *reinterpret_cast<__half2*>(C16 + (size_t)row * G3 + gc) = hv;
            }
        }
    }
}

// ------------------- CSR build -------------------
__global__ void hist_k(const int* e0, const int* e1, const int* e2, int E, int N)
{
    int e = blockIdx.x * blockDim.x + threadIdx.x;
    if (e >= 3 * E) return;
    int r = e / E, le = e - r * E;
    const int* ei = (r == 0) ? e0 : (r == 1) ? e1 : e2;
    atomicAdd(&g_CNT[r * N + ei[E + le]], 1);
}
__global__ void scan1_k(int ntot)
{
    __shared__ int sh[1024];
    int tid = threadIdx.x;
    int gid = blockIdx.x * 1024 + tid;
    int v = (gid < ntot) ? g_CNT[gid] : 0;
    sh[tid] = v;
    __syncthreads();
    for (int o = 1; o < 1024; o <<= 1) {
        int t = (tid >= o) ? sh[tid - o] : 0;
        __syncthreads();
        sh[tid] += t;
        __syncthreads();
    }
    if (gid < ntot) g_OFF[gid] = sh[tid] - v;
    if (tid == 1023) g_BSUM[blockIdx.x] = sh[1023];
}
__global__ void scan2_k(int nb)
{
    if (threadIdx.x == 0 && blockIdx.x == 0) {
        int run = 0;
        for (int i = 0; i < nb; i++) {
            int v = g_BSUM[i];
            g_BSUM[i] = run;
            run += v;
        }
    }
}
__global__ void scan3_k(int ntot)
{
    int gid = blockIdx.x * 1024 + threadIdx.x;
    if (gid >= ntot) return;
    int o = g_OFF[gid] + g_BSUM[blockIdx.x];
    g_OFF[gid] = o;
    g_CUR[gid] = o;
}
__global__ void scatter_idx_k(const int* e0, const int* e1, const int* e2, int E, int N)
{
    int e = blockIdx.x * blockDim.x + threadIdx.x;
    if (e >= 3 * E) return;
    int r = e / E, le = e - r * E;
    const int* ei = (r == 0) ? e0 : (r == 1) ? e1 : e2;
    int si = ei[le];
    int ti = ei[E + le];
    int pos = atomicAdd(&g_CUR[r * N + ti], 1);
    g_SRC[pos] = si;
}

// ------------------- gather aggregation -------------------
__global__ void gather_k(int N, int Etot)
{
    int gw   = (blockIdx.x * blockDim.x + threadIdx.x) >> 5;
    int lane = threadIdx.x & 31;
    if (gw >= 3 * N) return;
    int r = gw / N, ti = gw - r * N;
    int idx = r * N + ti;
    int s = g_OFF[idx];
    int e = (idx + 1 < 3 * N) ? g_OFF[idx + 1] : Etot;
    float* dst = g_AGG[r] + (size_t)ti * HH + lane * 4;
    uint2* dsth = reinterpret_cast<uint2*>(g_AGh[r] + (size_t)ti * HH + lane * 4);
    uint2* dstl = reinterpret_cast<uint2*>(g_AGl[r] + (size_t)ti * HH + lane * 4);
    float4 acc = make_float4(0.f, 0.f, 0.f, 0.f);
    if (s < e) {
        float at = g_AT[r][ti];
        float den = 0.f;
        for (int base = s; base < e; base += 32) {
            int k = base + lane;
            if (k < e) {
                int si = g_SRC[k];
                float l = g_AS[r][si] + at;
                l = (l > 0.f) ? l : 0.2f * l;
                den += expf(l);
            }
        }
#pragma unroll
        for (int o = 16; o; o >>= 1) den += __shfl_xor_sync(0xffffffffu, den, o);
        float inv = 1.f / (den + 1e-16f);
        for (int base = s; base < e; base += 32) {
            int k = base + lane;
            int si = 0;
            float ex = 0.f;
            if (k < e) {
                si = g_SRC[k];
                float l = g_AS[r][si] + at;
                l = (l > 0.f) ? l : 0.2f * l;
                ex = expf(l);
            }
            int cnt = min(32, e - base);
            for (int j = 0; j < cnt; j++) {
                float exj = __shfl_sync(0xffffffffu, ex, j);
                int   sij = __shfl_sync(0xffffffffu, si, j);
                float4 v = *reinterpret_cast<const float4*>(
                    g_HS[r] + (size_t)sij * HH + lane * 4);
                acc.x += exj * v.x;
                acc.y += exj * v.y;
                acc.z += exj * v.z;
                acc.w += exj * v.w;
            }
        }
        acc.x *= inv; acc.y *= inv; acc.z *= inv; acc.w *= inv;
    }
    *reinterpret_cast<float4*>(dst) = acc;
    uint2 hp, lp;
    split4h(acc, hp, lp);
    *dsth = hp;
    *dstl = lp;
}

// ------------------- pointwise -------------------
__global__ void alpha_all(const float* q0, const float* q1, const float* q2, int n)
{
    int gw = (blockIdx.x * blockDim.x + threadIdx.x) >> 5;
    int lane = threadIdx.x & 31;
    if (gw >= 6 * n) return;
    int sel = gw / n, node = gw - sel * n;
    int r = sel >> 1, which = sel & 1;
    const float* qs[3] = {q0, q1, q2};
    const float* feat = which ? g_HT[r] : g_HS[r];
    const float* q = qs[r] + which * HH;
    float4 a = *reinterpret_cast<const float4*>(feat + (size_t)node * HH + lane * 4);
    float4 b = *reinterpret_cast<const float4*>(q + lane * 4);
    float s = a.x * b.x + a.y * b.y + a.z * b.z + a.w * b.w;
#pragma unroll
    for (int o = 16; o; o >>= 1) s += __shfl_xor_sync(0xffffffffu, s, o);
    if (lane == 0) {
        if (which) g_AT[r][node] = s;
        else       g_AS[r][node] = s;
    }
}

__global__ void gru_all(int n)
{
    long long i = (long long)blockIdx.x * blockDim.x + threadIdx.x;
    if (i >= 3LL * n * HH) return;
    int r = (int)(i / ((long long)n * HH));
    int j = (int)(i - (long long)r * n * HH);
    int nn = j / HH, h = j - nn * HH;
    const __half* gi = g_GI16[r] + (size_t)nn * G3;
    const __half* gh = g_GH16[r] + (size_t)nn * G3;
    float rr = 1.f / (1.f + expf(-(__half2float(gi[h]) + __half2float(gh[h]))));
    float z  = 1.f / (1.f + expf(-(__half2float(gi[HH + h]) + __half2float(gh[HH + h]))));
    float g  = tanhf(__half2float(gi[2 * HH + h]) + rr * __half2float(gh[2 * HH + h]));
    float a  = g_AGG[r][(size_t)nn * HH + h];
    g_HOUT[r][j] = (1.f - z) * g + z * a;
}

__global__ void final_k(float* __restrict__ out, const float* __restrict__ g, int n)
{
    int warp = (blockIdx.x * blockDim.x + threadIdx.x) >> 5;
    int lane = threadIdx.x & 31;
    if (warp >= n) return;
    size_t off = (size_t)warp * HH + lane * 4;
    float4 u = *reinterpret_cast<const float4*>(g_HOUT[1] + off);
    u.x = fmaxf(u.x, 0.f); u.y = fmaxf(u.y, 0.f);
    u.z = fmaxf(u.z, 0.f); u.w = fmaxf(u.w, 0.f);
    *reinterpret_cast<float4*>(out + off) = u;
    float4 v0 = *reinterpret_cast<const float4*>(g_HOUT[0] + off);
    float4 v1 = *reinterpret_cast<const float4*>(g_HOUT[2] + off);
    float4 gv = *reinterpret_cast<const float4*>(g + lane * 4);
    float d0 = v0.x * gv.x + v0.y * gv.y + v0.z * gv.z + v0.w * gv.w;
    float d1 = v1.x * gv.x + v1.y * gv.y + v1.z * gv.z + v1.w * gv.w;
#pragma unroll
    for (int o = 16; o; o >>= 1) {
        d0 += __shfl_xor_sync(0xffffffffu, d0, o);
        d1 += __shfl_xor_sync(0xffffffffu, d1, o);
    }
    float a0 = expf(d0), a1 = expf(d1);
    float inv = 1.f / (a0 + a1);
    float w0 = a0 * inv, w1 = a1 * inv;
    float4 o4;
    o4.x = fmaxf(w0 * v0.x + w1 * v1.x, 0.f);
    o4.y = fmaxf(w0 * v0.y + w1 * v1.y, 0.f);
    o4.z = fmaxf(w0 * v0.z + w1 * v1.z, 0.f);
    o4.w = fmaxf(w0 * v0.w + w1 * v1.w, 0.f);
    *reinterpret_cast<float4*>(out + (size_t)n * HH + off) = o4;
}

// ---------------------------------------------------------------
extern "C" void kernel_launch(void* const* d_in, const int* in_sizes, int n_in,
                              void* d_out, int out_size)
{
    const float* x_user = (const float*)d_in[0];
    const float* x_item = (const float*)d_in[1];
    const int*   ei_ui  = (const int*)d_in[2];
    const int*   ei_iu  = (const int*)d_in[3];
    const int*   ei_ii  = (const int*)d_in[4];

    int N = in_sizes[0] / DD;
    int E = in_sizes[2] / 2;
    if (N > NMAX) N = NMAX;
    if (E > EMAX) E = EMAX;

    float* out = (float*)d_out;

    cudaFuncSetAttribute(hsht_gemm, cudaFuncAttributeMaxDynamicSharedMemorySize, SMEMSZ);
    cudaFuncSetAttribute(gru_gemm,  cudaFuncAttributeMaxDynamicSharedMemorySize, GSMEM);

    // prep splits
    int x4 = (N * DD) / 4;
    split_x_k<<<(2 * x4 + 255) / 256, 256>>>(x_user, x_item, x4);
    prep_wt_all<<<(6 * 128 * 256 + 255) / 256, 256>>>(
        (const float*)d_in[5],  (const float*)d_in[6],
        (const float*)d_in[12], (const float*)d_in[13],
        (const float*)d_in[19], (const float*)d_in[20]);
    prep_wg_all<<<(6 * G3 * HH + 255) / 256, 256>>>(
        (const float*)d_in[8],  (const float*)d_in[9],
        (const float*)d_in[15], (const float*)d_in[16],
        (const float*)d_in[22], (const float*)d_in[23]);

    // CSR build
    int ntot = 3 * N;
    void* pcnt;
    cudaGetSymbolAddress(&pcnt, g_CNT);
    cudaMemsetAsync(pcnt, 0, ntot * sizeof(int));
    hist_k<<<(3 * E + 255) / 256, 256>>>(ei_ui, ei_iu, ei_ii, E, N);
    int nb = (ntot + 1023) / 1024;
    scan1_k<<<nb, 1024>>>(ntot);
    scan2_k<<<1, 32>>>(nb);
    scan3_k<<<nb, 1024>>>(ntot);
    scatter_idx_k<<<(3 * E + 255) / 256, 256>>>(ei_ui, ei_iu, ei_ii, E, N);

    const int mb = NPAD / 128;   // 392

    hsht_gemm<<<dim3(mb, 1, 6), 256, SMEMSZ>>>(N);

    int aBlocks = (int)(((long long)6 * N * 32 + 255) / 256);
    alpha_all<<<aBlocks, 256>>>((const float*)d_in[7], (const float*)d_in[14],
                                (const float*)d_in[21], N);

    gather_k<<<(int)(((long long)3 * N * 32 + 255) / 256), 256>>>(N, 3 * E);

    gru_gemm<<<dim3(mb, 3, 6), 256, GSMEM>>>(
        N,
        (const float*)d_in[10], (const float*)d_in[11],
        (const float*)d_in[17], (const float*)d_in[18],
        (const float*)d_in[24], (const float*)d_in[25]);

    gru_all<<<(int)((3LL * N * HH + 255) / 256), 256>>>(N);

    final_k<<<(N * 32 + 255) / 256, 256>>>(out, (const float*)d_in[27], N);
}

// round 11
// speedup vs baseline: 2.4946x; 1.0806x over previous
#include <cuda_runtime.h>
#include <cuda_bf16.h>
#include <cuda_fp16.h>
#include <math.h>
#include <cstdint>

#define NMAX 50000
#define NPAD 50176   // 392*128
#define EMAX 400000
#define DD   256
#define HH   128
#define G3   384
#define SROW 80                  // smem bytes per 32-halfword row (64B + 16B pad)
#define TILE_B (128 * SROW)      // 10240
#define HSTAGE (3 * TILE_B)      // 30720 (hsht: Ah, Al, B16)
#define SMEMSZ (2 * HSTAGE)      // 61440
// gru_gemm: B single fp16 resident, A single fp16 2-stage
#define BROW   272               // 128*2 + 16 pad
#define GB_TILE (128 * BROW)     // 34816
#define GA_TILE (128 * SROW)     // 10240
#define GSMEM  (GB_TILE + 2 * GA_TILE)  // 55296

// ------------------- scratch -------------------
__device__ __align__(16) float g_HS [3][NPAD*HH];
__device__ __align__(16) float g_HT [3][NPAD*HH];
__device__ __align__(16) float g_AGG[3][NPAD*HH];
__device__ __align__(16) __half g_GI16[3][NPAD*G3];
__device__ __align__(16) __half g_GH16[3][NPAD*G3];
__device__ __align__(16) float g_AS [3][NMAX];
__device__ __align__(16) float g_AT [3][NMAX];
__device__ __align__(16) float g_HOUT[3][NPAD*HH];
__device__ __align__(16) __half g_XUh[NPAD*DD], g_XUl[NPAD*DD];   // fp16 hi/lo (hsht A)
__device__ __align__(16) __half g_XIh[NPAD*DD], g_XIl[NPAD*DD];
__device__ __align__(16) __half g_HT16[3][NPAD*HH];                // fp16 single (gru A)
__device__ __align__(16) __half g_AG16[3][NPAD*HH];                // fp16 single (gru A)
__device__ __align__(16) __half g_WT16[6][128*DD];                 // fp16 single
__device__ __align__(16) __half g_WG16[6][G3*HH];                  // fp16 single
// CSR
__device__ int g_CNT [3*NMAX];
__device__ int g_OFF [3*NMAX];
__device__ int g_CUR [3*NMAX];
__device__ int g_SRC [3*EMAX];
__device__ int g_BSUM[256];

// ------------------- PTX helpers -------------------
__device__ __forceinline__ uint32_t smem_u32(const void* p) {
    uint32_t a;
    asm("{ .reg .u64 t; cvta.to.shared.u64 t, %1; cvt.u32.u64 %0, t; }" : "=r"(a) : "l"(p));
    return a;
}
__device__ __forceinline__ void ldsm4(uint32_t* r, uint32_t addr) {
    asm volatile("ldmatrix.sync.aligned.m8n8.x4.shared.b16 {%0,%1,%2,%3}, [%4];"
                 : "=r"(r[0]), "=r"(r[1]), "=r"(r[2]), "=r"(r[3]) : "r"(addr));
}
__device__ __forceinline__ void mma_f16(float* d, const uint32_t* a, const uint32_t* b) {
    asm volatile(
        "mma.sync.aligned.m16n8k16.row.col.f32.f16.f16.f32 "
        "{%0,%1,%2,%3}, {%4,%5,%6,%7}, {%8,%9}, {%0,%1,%2,%3};"
        : "+f"(d[0]), "+f"(d[1]), "+f"(d[2]), "+f"(d[3])
        : "r"(a[0]), "r"(a[1]), "r"(a[2]), "r"(a[3]), "r"(b[0]), "r"(b[1]));
}
__device__ __forceinline__ void cpa16(uint32_t dst, const void* src) {
    asm volatile("cp.async.cg.shared.global [%0], [%1], 16;" :: "r"(dst), "l"(src));
}
// fp16 hi/lo split of 4 floats
__device__ __forceinline__ void split4h(float4 v, uint2& hp, uint2& lp) {
    __half h0 = __float2half_rn(v.x), h1 = __float2half_rn(v.y);
    __half h2 = __float2half_rn(v.z), h3 = __float2half_rn(v.w);
    __half l0 = __float2half_rn(v.x - __half2float(h0));
    __half l1 = __float2half_rn(v.y - __half2float(h1));
    __half l2 = __float2half_rn(v.z - __half2float(h2));
    __half l3 = __float2half_rn(v.w - __half2float(h3));
    hp.x = ((uint32_t)__half_as_ushort(h1) << 16) | __half_as_ushort(h0);
    hp.y = ((uint32_t)__half_as_ushort(h3) << 16) | __half_as_ushort(h2);
    lp.x = ((uint32_t)__half_as_ushort(l1) << 16) | __half_as_ushort(l0);
    lp.y = ((uint32_t)__half_as_ushort(l3) << 16) | __half_as_ushort(l2);
}
// fp16 round-only pack of 4 floats
__device__ __forceinline__ uint2 pack4h(float4 v) {
    __half h0 = __float2half_rn(v.x), h1 = __float2half_rn(v.y);
    __half h2 = __float2half_rn(v.z), h3 = __float2half_rn(v.w);
    uint2 p;
    p.x = ((uint32_t)__half_as_ushort(h1) << 16) | __half_as_ushort(h0);
    p.y = ((uint32_t)__half_as_ushort(h3) << 16) | __half_as_ushort(h2);
    return p;
}

// ------------------- prep kernels -------------------
__global__ void split_x_k(const float* __restrict__ xu, const float* __restrict__ xi, int n4)
{
    int i = blockIdx.x * blockDim.x + threadIdx.x;
    if (i >= 2 * n4) return;
    const float* src = (i < n4) ? xu : xi;
    int j = (i < n4) ? i : i - n4;
    float4 v = reinterpret_cast<const float4*>(src)[j];
    uint2 hp, lp;
    split4h(v, hp, lp);
    if (i < n4) {
        reinterpret_cast<uint2*>(g_XUh)[j] = hp;
        reinterpret_cast<uint2*>(g_XUl)[j] = lp;
    } else {
        reinterpret_cast<uint2*>(g_XIh)[j] = hp;
        reinterpret_cast<uint2*>(g_XIl)[j] = lp;
    }
}
// fused weight prep: 6x transpose w_src/w_tgt [256][128]->[128][256] fp16,
// then 6x wih/whh [384][128] fp16
#define WT_TOT (6 * 128 * 256)
#define WG_TOT (6 * G3 * HH)
__global__ void prep_w_all(
    const float* a0, const float* a1, const float* a2,
    const float* a3, const float* a4, const float* a5,
    const float* g0, const float* g1, const float* g2,
    const float* g3, const float* g4, const float* g5)
{
    int i = blockIdx.x * blockDim.x + threadIdx.x;
    if (i < WT_TOT) {
        const float* ws[6] = {a0, a1, a2, a3, a4, a5};
        int z = i >> 15, j = i & 32767;
        int n = j >> 8, k = j & 255;
        g_WT16[z][j] = __float2half_rn(ws[z][k * 128 + n]);
    } else if (i < WT_TOT + WG_TOT) {
        const float* ws[6] = {g0, g1, g2, g3, g4, g5};
        int t = i - WT_TOT;
        int z = t / (G3 * HH), j = t % (G3 * HH);
        g_WG16[z][j] = __float2half_rn(ws[z][j]);
    }
}

// -------- hsht GEMM: 2-term fp16 (A hi/lo, B single), BK=32, 2-stage ------
__global__ void __launch_bounds__(256, 2) hsht_gemm(int M)
{
    extern __shared__ char smem[];
    const int z = blockIdx.z, r = z >> 1;
    const __half* AhT[6] = {g_XUh, g_XIh, g_XIh, g_XUh, g_XIh, g_XIh};
    const __half* AlT[6] = {g_XUl, g_XIl, g_XIl, g_XUl, g_XIl, g_XIl};
    const __half* Ah = AhT[z];
    const __half* Al = AlT[z];
    const __half* B16 = g_WT16[z];
    float* C   = (z & 1) ? g_HT[r] : g_HS[r];
    __half* C16 = (z & 1) ? g_HT16[r] : nullptr;
    const int K = DD, Nc = HH;
    const int m0 = blockIdx.x * 128, n0 = 0;

    const uint32_t sb = smem_u32(smem);
    const int tid  = threadIdx.x;
    const int wid  = tid >> 5;
    const int lane = tid & 31;
    const int warp_m = wid & 3;
    const int warp_n = wid >> 2;

    float acc[2][8][4];
#pragma unroll
    for (int i = 0; i < 2; i++)
#pragma unroll
        for (int j = 0; j < 8; j++)
#pragma unroll
            for (int t = 0; t < 4; t++) acc[i][j][t] = 0.f;

    const int nchunks = K >> 5;   // 8

#define FILL(kc, stg) do {                                                      \
        const int k0f = (kc) << 5;                                              \
        const uint32_t s0 = sb + (stg) * HSTAGE;                                \
        _Pragma("unroll")                                                       \
        for (int it = 0; it < 6; it++) {                                        \
            int s = tid + it * 256;                                             \
            int tile = s >> 9, w = s & 511, row = w >> 2, q = w & 3;            \
            uint32_t dst = s0 + tile * TILE_B + row * SROW + q * 16;            \
            const __half* src;                                                  \
            size_t off;                                                         \
            if (tile < 2) {                                                     \
                src = (tile == 0) ? Ah : Al;                                    \
                off = (size_t)(m0 + row) * K + k0f + q * 8;                     \
            } else {                                                            \
                src = B16;                                                      \
                off = (size_t)(n0 + row) * K + k0f + q * 8;                     \
            }                                                                   \
            cpa16(dst, src + off);                                              \
        }                                                                       \
        asm volatile("cp.async.commit_group;" ::: "memory");                    \
    } while (0)

    FILL(0, 0);

    for (int kc = 0; kc < nchunks; kc++) {
        if (kc + 1 < nchunks) {
            FILL(kc + 1, (kc + 1) & 1);
            asm volatile("cp.async.wait_group 1;" ::: "memory");
        } else {
            asm volatile("cp.async.wait_group 0;" ::: "memory");
        }
        __syncthreads();

        const uint32_t s0  = sb + (kc & 1) * HSTAGE;
        const uint32_t sAh = s0;
        const uint32_t sAl = s0 + TILE_B;
        const uint32_t sB  = s0 + 2 * TILE_B;

#pragma unroll
        for (int ks = 0; ks < 2; ks++) {
            uint32_t afh[2][4], afl[2][4];
            {
                int rr = lane & 15;
                int c8 = lane >> 4;
                uint32_t off = (uint32_t)((warp_m * 32 + rr) * SROW + (ks * 16 + c8 * 8) * 2);
                ldsm4(afh[0], sAh + off);
                ldsm4(afh[1], sAh + off + 16 * SROW);
                ldsm4(afl[0], sAl + off);
                ldsm4(afl[1], sAl + off + 16 * SROW);
            }
            uint32_t bf[8][2];
            {
                int sub = lane >> 3, wi = lane & 7;
                int n_off = (sub >> 1) * 8 + wi;
                int k_off = ks * 16 + (sub & 1) * 8;
                uint32_t base = (uint32_t)((warp_n * 64 + n_off) * SROW + k_off * 2);
#pragma unroll
                for (int jj = 0; jj < 4; jj++) {
                    uint32_t r4[4];
                    ldsm4(r4, sB + base + jj * 16 * SROW);
                    bf[2 * jj][0] = r4[0]; bf[2 * jj][1] = r4[1];
                    bf[2 * jj + 1][0] = r4[2]; bf[2 * jj + 1][1] = r4[3];
                }
            }
#pragma unroll
            for (int mi = 0; mi < 2; mi++)
#pragma unroll
                for (int j = 0; j < 8; j++) {
                    mma_f16(acc[mi][j], afh[mi], bf[j]);
                    mma_f16(acc[mi][j], afl[mi], bf[j]);
                }
        }
        __syncthreads();
    }
#undef FILL

#pragma unroll
    for (int mi = 0; mi < 2; mi++) {
        int gr = m0 + warp_m * 32 + mi * 16 + (lane >> 2);
#pragma unroll
        for (int j = 0; j < 8; j++) {
            int gc = n0 + warp_n * 64 + j * 8 + 2 * (lane & 3);
#pragma unroll
            for (int half = 0; half < 2; half++) {
                int row = gr + half * 8;
                if (row >= M) continue;
                float v0 = acc[mi][j][2 * half + 0];
                float v1 = acc[mi][j][2 * half + 1];
                *reinterpret_cast<float2*>(C + (size_t)row * Nc + gc) =
                    make_float2(v0, v1);
                if (C16) {
                    __half2 hv = __floats2half2_rn(v0, v1);
                    *reinterpret_cast<__half2*>(C16 + (size_t)row * Nc + gc) = hv;
                }
            }
        }
    }
}

// ---------- gru GEMM: 1-term fp16 (A single, B single), B resident --------
__global__ void __launch_bounds__(256, 2) gru_gemm(
    int M,
    const float* b0, const float* b1, const float* b2,
    const float* b3, const float* b4, const float* b5)
{
    extern __shared__ char smem[];
    const int z = blockIdx.z, r = z >> 1, which = z & 1;
    const float* biases[6] = {b0, b1, b2, b3, b4, b5};
    const __half* A16 = which ? g_AG16[r] : g_HT16[r];
    const __half* B16 = g_WG16[z];
    const float* bias = biases[z];
    __half* C16 = which ? g_GH16[r] : g_GI16[r];
    const int K = HH;
    const int m0 = blockIdx.x * 128;
    const int n0 = blockIdx.y * 128;

    const uint32_t sb = smem_u32(smem);
    const uint32_t sB  = sb;
    const uint32_t sA0 = sb + GB_TILE;
    const int tid  = threadIdx.x;
    const int wid  = tid >> 5;
    const int lane = tid & 31;
    const int warp_m = wid & 3;
    const int warp_n = wid >> 2;

    float acc[2][8][4];
#pragma unroll
    for (int i = 0; i < 2; i++)
#pragma unroll
        for (int j = 0; j < 8; j++)
#pragma unroll
            for (int t = 0; t < 4; t++) acc[i][j][t] = 0.f;

    // B prologue: 2048 cp.async
#pragma unroll
    for (int it = 0; it < 8; it++) {
        int s = tid + it * 256;
        int row = s >> 4, q = s & 15;
        cpa16(sB + row * BROW + q * 16, B16 + (size_t)(n0 + row) * K + q * 8);
    }
    asm volatile("cp.async.commit_group;" ::: "memory");

    // A fill: 512 cp.async per chunk (2 per thread)
#define FILLA(kc, stg) do {                                                     \
        const int k0f = (kc) << 5;                                              \
        const uint32_t s0 = sA0 + (stg) * GA_TILE;                              \
        _Pragma("unroll")                                                       \
        for (int it = 0; it < 2; it++) {                                        \
            int s = tid + it * 256;                                             \
            int row = s >> 2, q = s & 3;                                        \
            cpa16(s0 + row * SROW + q * 16,                                     \
                  A16 + (size_t)(m0 + row) * K + k0f + q * 8);                  \
        }                                                                       \
        asm volatile("cp.async.commit_group;" ::: "memory");                    \
    } while (0)

    FILLA(0, 0);

    const int nchunks = K >> 5;   // 4
    for (int kc = 0; kc < nchunks; kc++) {
        if (kc + 1 < nchunks) {
            FILLA(kc + 1, (kc + 1) & 1);
            asm volatile("cp.async.wait_group 1;" ::: "memory");
        } else {
            asm volatile("cp.async.wait_group 0;" ::: "memory");
        }
        __syncthreads();

        const uint32_t sA = sA0 + (kc & 1) * GA_TILE;

#pragma unroll
        for (int ks = 0; ks < 2; ks++) {
            const int kglob = kc * 32 + ks * 16;
            uint32_t af[2][4];
            {
                int rr = lane & 15;
                int c8 = lane >> 4;
                uint32_t off = (uint32_t)((warp_m * 32 + rr) * SROW + (ks * 16 + c8 * 8) * 2);
                ldsm4(af[0], sA + off);
                ldsm4(af[1], sA + off + 16 * SROW);
            }
            uint32_t bf[8][2];
            {
                int sub = lane >> 3, wi = lane & 7;
                int n_off = (sub >> 1) * 8 + wi;
                int k_off = kglob + (sub & 1) * 8;
                uint32_t base = (uint32_t)((warp_n * 64 + n_off) * BROW + k_off * 2);
#pragma unroll
                for (int jj = 0; jj < 4; jj++) {
                    uint32_t r4[4];
                    ldsm4(r4, sB + base + jj * 16 * BROW);
                    bf[2 * jj][0] = r4[0]; bf[2 * jj][1] = r4[1];
                    bf[2 * jj + 1][0] = r4[2]; bf[2 * jj + 1][1] = r4[3];
                }
            }
#pragma unroll
            for (int mi = 0; mi < 2; mi++)
#pragma unroll
                for (int j = 0; j < 8; j++)
                    mma_f16(acc[mi][j], af[mi], bf[j]);
        }
        __syncthreads();
    }
#undef FILLA

#pragma unroll
    for (int mi = 0; mi < 2; mi++) {
        int gr = m0 + warp_m * 32 + mi * 16 + (lane >> 2);
#pragma unroll
        for (int j = 0; j < 8; j++) {
            int gc = n0 + warp_n * 64 + j * 8 + 2 * (lane & 3);
            float bb0 = bias[gc], bb1 = bias[gc + 1];
#pragma unroll
            for (int half = 0; half < 2; half++) {
                int row = gr + half * 8;
                if (row >= M) continue;
                __half2 hv = __floats2half2_rn(acc[mi][j][2 * half + 0] + bb0,
                                               acc[mi][j][2 * half + 1] + bb1);
                *reinterpret_cast<__half2*>(C16 + (size_t)row * G3 + gc) = hv;
            }
        }
    }
}

// ------------------- CSR build -------------------
__global__ void hist_k(const int* e0, const int* e1, const int* e2, int E, int N)
{
    int e = blockIdx.x * blockDim.x + threadIdx.x;
    if (e >= 3 * E) return;
    int r = e / E, le = e - r * E;
    const int* ei = (r == 0) ? e0 : (r == 1) ? e1 : e2;
    atomicAdd(&g_CNT[r * N + ei[E + le]], 1);
}
__global__ void scan1_k(int ntot)
{
    __shared__ int sh[1024];
    int tid = threadIdx.x;
    int gid = blockIdx.x * 1024 + tid;
    int v = (gid < ntot) ? g_CNT[gid] : 0;
    sh[tid] = v;
    __syncthreads();
    for (int o = 1; o < 1024; o <<= 1) {
        int t = (tid >= o) ? sh[tid - o] : 0;
        __syncthreads();
        sh[tid] += t;
        __syncthreads();
    }
    if (gid < ntot) g_OFF[gid] = sh[tid] - v;
    if (tid == 1023) g_BSUM[blockIdx.x] = sh[1023];
}
// scan3 computes its own block-prefix from g_BSUM (eliminates scan2 launch)
__global__ void scan3_k(int ntot)
{
    __shared__ int base;
    if (threadIdx.x == 0) {
        int run = 0;
#pragma unroll 8
        for (int i = 0; i < blockIdx.x; i++) run += g_BSUM[i];
        base = run;
    }
    __syncthreads();
    int gid = blockIdx.x * 1024 + threadIdx.x;
    if (gid >= ntot) return;
    int o = g_OFF[gid] + base;
    g_OFF[gid] = o;
    g_CUR[gid] = o;
}
__global__ void scatter_idx_k(const int* e0, const int* e1, const int* e2, int E, int N)
{
    int e = blockIdx.x * blockDim.x + threadIdx.x;
    if (e >= 3 * E) return;
    int r = e / E, le = e - r * E;
    const int* ei = (r == 0) ? e0 : (r == 1) ? e1 : e2;
    int si = ei[le];
    int ti = ei[E + le];
    int pos = atomicAdd(&g_CUR[r * N + ti], 1);
    g_SRC[pos] = si;
}

// ------------------- gather aggregation -------------------
__global__ void gather_k(int N, int Etot)
{
    int gw   = (blockIdx.x * blockDim.x + threadIdx.x) >> 5;
    int lane = threadIdx.x & 31;
    if (gw >= 3 * N) return;
    int r = gw / N, ti = gw - r * N;
    int idx = r * N + ti;
    int s = g_OFF[idx];
    int e = (idx + 1 < 3 * N) ? g_OFF[idx + 1] : Etot;
    float* dst = g_AGG[r] + (size_t)ti * HH + lane * 4;
    uint2* dst16 = reinterpret_cast<uint2*>(g_AG16[r] + (size_t)ti * HH + lane * 4);
    float4 acc = make_float4(0.f, 0.f, 0.f, 0.f);
    if (s < e) {
        float at = g_AT[r][ti];
        float den = 0.f;
        for (int base = s; base < e; base += 32) {
            int k = base + lane;
            if (k < e) {
                int si = g_SRC[k];
                float l = g_AS[r][si] + at;
                l = (l > 0.f) ? l : 0.2f * l;
                den += expf(l);
            }
        }
#pragma unroll
        for (int o = 16; o; o >>= 1) den += __shfl_xor_sync(0xffffffffu, den, o);
        float inv = 1.f / (den + 1e-16f);
        for (int base = s; base < e; base += 32) {
            int k = base + lane;
            int si = 0;
            float ex = 0.f;
            if (k < e) {
                si = g_SRC[k];
                float l = g_AS[r][si] + at;
                l = (l > 0.f) ? l : 0.2f * l;
                ex = expf(l);
            }
            int cnt = min(32, e - base);
            for (int j = 0; j < cnt; j++) {
                float exj = __shfl_sync(0xffffffffu, ex, j);
                int   sij = __shfl_sync(0xffffffffu, si, j);
                float4 v = *reinterpret_cast<const float4*>(
                    g_HS[r] + (size_t)sij * HH + lane * 4);
                acc.x += exj * v.x;
                acc.y += exj * v.y;
                acc.z += exj * v.z;
                acc.w += exj * v.w;
            }
        }
        acc.x *= inv; acc.y *= inv; acc.z *= inv; acc.w *= inv;
    }
    *reinterpret_cast<float4*>(dst) = acc;
    *dst16 = pack4h(acc);
}

// ------------------- pointwise -------------------
__global__ void alpha_all(const float* q0, const float* q1, const float* q2, int n)
{
    int gw = (blockIdx.x * blockDim.x + threadIdx.x) >> 5;
    int lane = threadIdx.x & 31;
    if (gw >= 6 * n) return;
    int sel = gw / n, node = gw - sel * n;
    int r = sel >> 1, which = sel & 1;
    const float* qs[3] = {q0, q1, q2};
    const float* feat = which ? g_HT[r] : g_HS[r];
    const float* q = qs[r] + which * HH;
    float4 a = *reinterpret_cast<const float4*>(feat + (size_t)node * HH + lane * 4);
    float4 b = *reinterpret_cast<const float4*>(q + lane * 4);
    float s = a.x * b.x + a.y * b.y + a.z * b.z + a.w * b.w;
#pragma unroll
    for (int o = 16; o; o >>= 1) s += __shfl_xor_sync(0xffffffffu, s, o);
    if (lane == 0) {
        if (which) g_AT[r][node] = s;
        else       g_AS[r][node] = s;
    }
}

__global__ void gru_all(int n)
{
    long long i = (long long)blockIdx.x * blockDim.x + threadIdx.x;
    if (i >= 3LL * n * HH) return;
    int r = (int)(i / ((long long)n * HH));
    int j = (int)(i - (long long)r * n * HH);
    int nn = j / HH, h = j - nn * HH;
    const __half* gi = g_GI16[r] + (size_t)nn * G3;
    const __half* gh = g_GH16[r] + (size_t)nn * G3;
    float rr = 1.f / (1.f + expf(-(__half2float(gi[h]) + __half2float(gh[h]))));
    float z  = 1.f / (1.f + expf(-(__half2float(gi[HH + h]) + __half2float(gh[HH + h]))));
    float g  = tanhf(__half2float(gi[2 * HH + h]) + rr * __half2float(gh[2 * HH + h]));
    float a  = g_AGG[r][(size_t)nn * HH + h];
    g_HOUT[r][j] = (1.f - z) * g + z * a;
}

__global__ void final_k(float* __restrict__ out, const float* __restrict__ g, int n)
{
    int warp = (blockIdx.x * blockDim.x + threadIdx.x) >> 5;
    int lane = threadIdx.x & 31;
    if (warp >= n) return;
    size_t off = (size_t)warp * HH + lane * 4;
    float4 u = *reinterpret_cast<const float4*>(g_HOUT[1] + off);
    u.x = fmaxf(u.x, 0.f); u.y = fmaxf(u.y, 0.f);
    u.z = fmaxf(u.z, 0.f); u.w = fmaxf(u.w, 0.f);
    *reinterpret_cast<float4*>(out + off) = u;
    float4 v0 = *reinterpret_cast<const float4*>(g_HOUT[0] + off);
    float4 v1 = *reinterpret_cast<const float4*>(g_HOUT[2] + off);
    float4 gv = *reinterpret_cast<const float4*>(g + lane * 4);
    float d0 = v0.x * gv.x + v0.y * gv.y + v0.z * gv.z + v0.w * gv.w;
    float d1 = v1.x * gv.x + v1.y * gv.y + v1.z * gv.z + v1.w * gv.w;
#pragma unroll
    for (int o = 16; o; o >>= 1) {
        d0 += __shfl_xor_sync(0xffffffffu, d0, o);
        d1 += __shfl_xor_sync(0xffffffffu, d1, o);
    }
    float a0 = expf(d0), a1 = expf(d1);
    float inv = 1.f / (a0 + a1);
    float w0 = a0 * inv, w1 = a1 * inv;
    float4 o4;
    o4.x = fmaxf(w0 * v0.x + w1 * v1.x, 0.f);
    o4.y = fmaxf(w0 * v0.y + w1 * v1.y, 0.f);
    o4.z = fmaxf(w0 * v0.z + w1 * v1.z, 0.f);
    o4.w = fmaxf(w0 * v0.w + w1 * v1.w, 0.f);
    *reinterpret_cast<float4*>(out + (size_t)n * HH + off) = o4;
}

// ---------------------------------------------------------------
extern "C" void kernel_launch(void* const* d_in, const int* in_sizes, int n_in,
                              void* d_out, int out_size)
{
    const float* x_user = (const float*)d_in[0];
    const float* x_item = (const float*)d_in[1];
    const int*   ei_ui  = (const int*)d_in[2];
    const int*   ei_iu  = (const int*)d_in[3];
    const int*   ei_ii  = (const int*)d_in[4];

    int N = in_sizes[0] / DD;
    int E = in_sizes[2] / 2;
    if (N > NMAX) N = NMAX;
    if (E > EMAX) E = EMAX;

    float* out = (float*)d_out;

    cudaFuncSetAttribute(hsht_gemm, cudaFuncAttributeMaxDynamicSharedMemorySize, SMEMSZ);
    cudaFuncSetAttribute(gru_gemm,  cudaFuncAttributeMaxDynamicSharedMemorySize, GSMEM);

    // prep splits
    int x4 = (N * DD) / 4;
    split_x_k<<<(2 * x4 + 255) / 256, 256>>>(x_user, x_item, x4);
    prep_w_all<<<(WT_TOT + WG_TOT + 255) / 256, 256>>>(
        (const float*)d_in[5],  (const float*)d_in[6],
        (const float*)d_in[12], (const float*)d_in[13],
        (const float*)d_in[19], (const float*)d_in[20],
        (const float*)d_in[8],  (const float*)d_in[9],
        (const float*)d_in[15], (const float*)d_in[16],
        (const float*)d_in[22], (const float*)d_in[23]);

    // CSR build
    int ntot = 3 * N;
    void* pcnt;
    cudaGetSymbolAddress(&pcnt, g_CNT);
    cudaMemsetAsync(pcnt, 0, ntot * sizeof(int));
    hist_k<<<(3 * E + 255) / 256, 256>>>(ei_ui, ei_iu, ei_ii, E, N);
    int nb = (ntot + 1023) / 1024;
    scan1_k<<<nb, 1024>>>(ntot);
    scan3_k<<<nb, 1024>>>(ntot);
    scatter_idx_k<<<(3 * E + 255) / 256, 256>>>(ei_ui, ei_iu, ei_ii, E, N);

    const int mb = NPAD / 128;   // 392

    hsht_gemm<<<dim3(mb, 1, 6), 256, SMEMSZ>>>(N);

    int aBlocks = (int)(((long long)6 * N * 32 + 255) / 256);
    alpha_all<<<aBlocks, 256>>>((const float*)d_in[7], (const float*)d_in[14],
                                (const float*)d_in[21], N);

    gather_k<<<(int)(((long long)3 * N * 32 + 255) / 256), 256>>>(N, 3 * E);

    gru_gemm<<<dim3(mb, 3, 6), 256, GSMEM>>>(
        N,
        (const float*)d_in[10], (const float*)d_in[11],
        (const float*)d_in[17], (const float*)d_in[18],
        (const float*)d_in[24], (const float*)d_in[25]);

    gru_all<<<(int)((3LL * N * HH + 255) / 256), 256>>>(N);

    final_k<<<(N * 32 + 255) / 256, 256>>>(out, (const float*)d_in[27], N);
}

// round 12
// speedup vs baseline: 2.8762x; 1.1530x over previous
#include <cuda_runtime.h>
#include <cuda_fp16.h>
#include <math.h>
#include <cstdint>

#define NMAX 50000
#define NPAD 50176   // 392*128
#define EMAX 400000
#define DD   256
#define HH   128
#define G3   384
#define SROW 80                  // smem bytes per 32-halfword row (64B + 16B pad)
#define TILE_B (128 * SROW)      // 10240
#define HSTAGE (2 * TILE_B)      // 20480 (hsht: A16, B16)
#define SMEMSZ (2 * HSTAGE)      // 40960
// gru_gemm: B single fp16 resident, A single fp16 2-stage
#define BROW   272               // 128*2 + 16 pad
#define GB_TILE (128 * BROW)     // 34816
#define GA_TILE (128 * SROW)     // 10240
#define GSMEM  (GB_TILE + 2 * GA_TILE)  // 55296

// ------------------- scratch -------------------
__device__ __align__(16) float  g_AGG[3][NPAD*HH];
__device__ __align__(16) __half g_GI16[3][NPAD*G3];
__device__ __align__(16) __half g_GH16[3][NPAD*G3];
__device__ __align__(16) float  g_AS [3][NMAX];
__device__ __align__(16) float  g_AT [3][NMAX];
__device__ __align__(16) float  g_HOUT[3][NPAD*HH];
__device__ __align__(16) __half g_XU16[NPAD*DD], g_XI16[NPAD*DD];  // fp16 inputs
__device__ __align__(16) __half g_HS16[3][NPAD*HH];                // fp16 hs
__device__ __align__(16) __half g_HT16[3][NPAD*HH];                // fp16 ht
__device__ __align__(16) __half g_AG16[3][NPAD*HH];                // fp16 agg
__device__ __align__(16) __half g_WT16[6][128*DD];
__device__ __align__(16) __half g_WG16[6][G3*HH];
// CSR
__device__ int g_CNT [3*NMAX];
__device__ int g_OFF [3*NMAX];
__device__ int g_CUR [3*NMAX];
__device__ int g_SRC [3*EMAX];
__device__ int g_BSUM[256];

// ------------------- PTX helpers -------------------
__device__ __forceinline__ uint32_t smem_u32(const void* p) {
    uint32_t a;
    asm("{ .reg .u64 t; cvta.to.shared.u64 t, %1; cvt.u32.u64 %0, t; }" : "=r"(a) : "l"(p));
    return a;
}
__device__ __forceinline__ void ldsm4(uint32_t* r, uint32_t addr) {
    asm volatile("ldmatrix.sync.aligned.m8n8.x4.shared.b16 {%0,%1,%2,%3}, [%4];"
                 : "=r"(r[0]), "=r"(r[1]), "=r"(r[2]), "=r"(r[3]) : "r"(addr));
}
__device__ __forceinline__ void mma_f16(float* d, const uint32_t* a, const uint32_t* b) {
    asm volatile(
        "mma.sync.aligned.m16n8k16.row.col.f32.f16.f16.f32 "
        "{%0,%1,%2,%3}, {%4,%5,%6,%7}, {%8,%9}, {%0,%1,%2,%3};"
        : "+f"(d[0]), "+f"(d[1]), "+f"(d[2]), "+f"(d[3])
        : "r"(a[0]), "r"(a[1]), "r"(a[2]), "r"(a[3]), "r"(b[0]), "r"(b[1]));
}
__device__ __forceinline__ void cpa16(uint32_t dst, const void* src) {
    asm volatile("cp.async.cg.shared.global [%0], [%1], 16;" :: "r"(dst), "l"(src));
}
__device__ __forceinline__ uint2 pack4h(float4 v) {
    __half h0 = __float2half_rn(v.x), h1 = __float2half_rn(v.y);
    __half h2 = __float2half_rn(v.z), h3 = __float2half_rn(v.w);
    uint2 p;
    p.x = ((uint32_t)__half_as_ushort(h1) << 16) | __half_as_ushort(h0);
    p.y = ((uint32_t)__half_as_ushort(h3) << 16) | __half_as_ushort(h2);
    return p;
}
__device__ __forceinline__ float4 unpack4h(uint2 p) {
    __half2 a = *reinterpret_cast<__half2*>(&p.x);
    __half2 b = *reinterpret_cast<__half2*>(&p.y);
    float2 fa = __half22float2(a);
    float2 fb = __half22float2(b);
    return make_float4(fa.x, fa.y, fb.x, fb.y);
}

// ------------------- prep kernels -------------------
__global__ void split_x_k(const float* __restrict__ xu, const float* __restrict__ xi, int n4)
{
    int i = blockIdx.x * blockDim.x + threadIdx.x;
    if (i >= 2 * n4) return;
    const float* src = (i < n4) ? xu : xi;
    int j = (i < n4) ? i : i - n4;
    float4 v = reinterpret_cast<const float4*>(src)[j];
    uint2 p = pack4h(v);
    if (i < n4) reinterpret_cast<uint2*>(g_XU16)[j] = p;
    else        reinterpret_cast<uint2*>(g_XI16)[j] = p;
}
#define WT_TOT (6 * 128 * 256)
#define WG_TOT (6 * G3 * HH)
__global__ void prep_w_all(
    const float* a0, const float* a1, const float* a2,
    const float* a3, const float* a4, const float* a5,
    const float* g0, const float* g1, const float* g2,
    const float* g3, const float* g4, const float* g5)
{
    int i = blockIdx.x * blockDim.x + threadIdx.x;
    if (i < WT_TOT) {
        const float* ws[6] = {a0, a1, a2, a3, a4, a5};
        int z = i >> 15, j = i & 32767;
        int n = j >> 8, k = j & 255;
        g_WT16[z][j] = __float2half_rn(ws[z][k * 128 + n]);
    } else if (i < WT_TOT + WG_TOT) {
        const float* ws[6] = {g0, g1, g2, g3, g4, g5};
        int t = i - WT_TOT;
        int z = t / (G3 * HH), j = t % (G3 * HH);
        g_WG16[z][j] = __float2half_rn(ws[z][j]);
    }
}

// -------- hsht GEMM: 1-term fp16 (A single, B single), BK=32, 2-stage -----
__global__ void __launch_bounds__(256, 2) hsht_gemm(int M)
{
    extern __shared__ char smem[];
    const int z = blockIdx.z, r = z >> 1;
    const __half* AT6[6] = {g_XU16, g_XI16, g_XI16, g_XU16, g_XI16, g_XI16};
    const __half* A16 = AT6[z];
    const __half* B16 = g_WT16[z];
    __half* C16 = (z & 1) ? g_HT16[r] : g_HS16[r];
    const int K = DD, Nc = HH;
    const int m0 = blockIdx.x * 128, n0 = 0;

    const uint32_t sb = smem_u32(smem);
    const int tid  = threadIdx.x;
    const int wid  = tid >> 5;
    const int lane = tid & 31;
    const int warp_m = wid & 3;
    const int warp_n = wid >> 2;

    float acc[2][8][4];
#pragma unroll
    for (int i = 0; i < 2; i++)
#pragma unroll
        for (int j = 0; j < 8; j++)
#pragma unroll
            for (int t = 0; t < 4; t++) acc[i][j][t] = 0.f;

    const int nchunks = K >> 5;   // 8

    // fill: 2 tiles x 512 = 1024 cp.async, 4 per thread
#define FILL(kc, stg) do {                                                      \
        const int k0f = (kc) << 5;                                              \
        const uint32_t s0 = sb + (stg) * HSTAGE;                                \
        _Pragma("unroll")                                                       \
        for (int it = 0; it < 4; it++) {                                        \
            int s = tid + it * 256;                                             \
            int tile = s >> 9, w = s & 511, row = w >> 2, q = w & 3;            \
            uint32_t dst = s0 + tile * TILE_B + row * SROW + q * 16;            \
            const __half* src = tile ? B16 : A16;                               \
            size_t off = tile ? ((size_t)(n0 + row) * K + k0f + q * 8)          \
                              : ((size_t)(m0 + row) * K + k0f + q * 8);         \
            cpa16(dst, src + off);                                              \
        }                                                                       \
        asm volatile("cp.async.commit_group;" ::: "memory");                    \
    } while (0)

    FILL(0, 0);

    for (int kc = 0; kc < nchunks; kc++) {
        if (kc + 1 < nchunks) {
            FILL(kc + 1, (kc + 1) & 1);
            asm volatile("cp.async.wait_group 1;" ::: "memory");
        } else {
            asm volatile("cp.async.wait_group 0;" ::: "memory");
        }
        __syncthreads();

        const uint32_t s0 = sb + (kc & 1) * HSTAGE;
        const uint32_t sA = s0;
        const uint32_t sB = s0 + TILE_B;

#pragma unroll
        for (int ks = 0; ks < 2; ks++) {
            uint32_t af[2][4];
            {
                int rr = lane & 15;
                int c8 = lane >> 4;
                uint32_t off = (uint32_t)((warp_m * 32 + rr) * SROW + (ks * 16 + c8 * 8) * 2);
                ldsm4(af[0], sA + off);
                ldsm4(af[1], sA + off + 16 * SROW);
            }
            uint32_t bf[8][2];
            {
                int sub = lane >> 3, wi = lane & 7;
                int n_off = (sub >> 1) * 8 + wi;
                int k_off = ks * 16 + (sub & 1) * 8;
                uint32_t base = (uint32_t)((warp_n * 64 + n_off) * SROW + k_off * 2);
#pragma unroll
                for (int jj = 0; jj < 4; jj++) {
                    uint32_t r4[4];
                    ldsm4(r4, sB + base + jj * 16 * SROW);
                    bf[2 * jj][0] = r4[0]; bf[2 * jj][1] = r4[1];
                    bf[2 * jj + 1][0] = r4[2]; bf[2 * jj + 1][1] = r4[3];
                }
            }
#pragma unroll
            for (int mi = 0; mi < 2; mi++)
#pragma unroll
                for (int j = 0; j < 8; j++)
                    mma_f16(acc[mi][j], af[mi], bf[j]);
        }
        __syncthreads();
    }
#undef FILL

#pragma unroll
    for (int mi = 0; mi < 2; mi++) {
        int gr = m0 + warp_m * 32 + mi * 16 + (lane >> 2);
#pragma unroll
        for (int j = 0; j < 8; j++) {
            int gc = n0 + warp_n * 64 + j * 8 + 2 * (lane & 3);
#pragma unroll
            for (int half = 0; half < 2; half++) {
                int row = gr + half * 8;
                if (row >= M) continue;
                __half2 hv = __floats2half2_rn(acc[mi][j][2 * half + 0],
                                               acc[mi][j][2 * half + 1]);
                *reinterpret_cast<__half2*>(C16 + (size_t)row * Nc + gc) = hv;
            }
        }
    }
}

// ---------- gru GEMM: 1-term fp16 (A single, B single), B resident --------
__global__ void __launch_bounds__(256, 2) gru_gemm(
    int M,
    const float* b0, const float* b1, const float* b2,
    const float* b3, const float* b4, const float* b5)
{
    extern __shared__ char smem[];
    const int z = blockIdx.z, r = z >> 1, which = z & 1;
    const float* biases[6] = {b0, b1, b2, b3, b4, b5};
    const __half* A16 = which ? g_AG16[r] : g_HT16[r];
    const __half* B16 = g_WG16[z];
    const float* bias = biases[z];
    __half* C16 = which ? g_GH16[r] : g_GI16[r];
    const int K = HH;
    const int m0 = blockIdx.x * 128;
    const int n0 = blockIdx.y * 128;

    const uint32_t sb = smem_u32(smem);
    const uint32_t sB  = sb;
    const uint32_t sA0 = sb + GB_TILE;
    const int tid  = threadIdx.x;
    const int wid  = tid >> 5;
    const int lane = tid & 31;
    const int warp_m = wid & 3;
    const int warp_n = wid >> 2;

    float acc[2][8][4];
#pragma unroll
    for (int i = 0; i < 2; i++)
#pragma unroll
        for (int j = 0; j < 8; j++)
#pragma unroll
            for (int t = 0; t < 4; t++) acc[i][j][t] = 0.f;

    // B prologue
#pragma unroll
    for (int it = 0; it < 8; it++) {
        int s = tid + it * 256;
        int row = s >> 4, q = s & 15;
        cpa16(sB + row * BROW + q * 16, B16 + (size_t)(n0 + row) * K + q * 8);
    }
    asm volatile("cp.async.commit_group;" ::: "memory");

#define FILLA(kc, stg) do {                                                     \
        const int k0f = (kc) << 5;                                              \
        const uint32_t s0 = sA0 + (stg) * GA_TILE;                              \
        _Pragma("unroll")                                                       \
        for (int it = 0; it < 2; it++) {                                        \
            int s = tid + it * 256;                                             \
            int row = s >> 2, q = s & 3;                                        \
            cpa16(s0 + row * SROW + q * 16,                                     \
                  A16 + (size_t)(m0 + row) * K + k0f + q * 8);                  \
        }                                                                       \
        asm volatile("cp.async.commit_group;" ::: "memory");                    \
    } while (0)

    FILLA(0, 0);

    const int nchunks = K >> 5;   // 4
    for (int kc = 0; kc < nchunks; kc++) {
        if (kc + 1 < nchunks) {
            FILLA(kc + 1, (kc + 1) & 1);
            asm volatile("cp.async.wait_group 1;" ::: "memory");
        } else {
            asm volatile("cp.async.wait_group 0;" ::: "memory");
        }
        __syncthreads();

        const uint32_t sA = sA0 + (kc & 1) * GA_TILE;

#pragma unroll
        for (int ks = 0; ks < 2; ks++) {
            const int kglob = kc * 32 + ks * 16;
            uint32_t af[2][4];
            {
                int rr = lane & 15;
                int c8 = lane >> 4;
                uint32_t off = (uint32_t)((warp_m * 32 + rr) * SROW + (ks * 16 + c8 * 8) * 2);
                ldsm4(af[0], sA + off);
                ldsm4(af[1], sA + off + 16 * SROW);
            }
            uint32_t bf[8][2];
            {
                int sub = lane >> 3, wi = lane & 7;
                int n_off = (sub >> 1) * 8 + wi;
                int k_off = kglob + (sub & 1) * 8;
                uint32_t base = (uint32_t)((warp_n * 64 + n_off) * BROW + k_off * 2);
#pragma unroll
                for (int jj = 0; jj < 4; jj++) {
                    uint32_t r4[4];
                    ldsm4(r4, sB + base + jj * 16 * BROW);
                    bf[2 * jj][0] = r4[0]; bf[2 * jj][1] = r4[1];
                    bf[2 * jj + 1][0] = r4[2]; bf[2 * jj + 1][1] = r4[3];
                }
            }
#pragma unroll
            for (int mi = 0; mi < 2; mi++)
#pragma unroll
                for (int j = 0; j < 8; j++)
                    mma_f16(acc[mi][j], af[mi], bf[j]);
        }
        __syncthreads();
    }
#undef FILLA

#pragma unroll
    for (int mi = 0; mi < 2; mi++) {
        int gr = m0 + warp_m * 32 + mi * 16 + (lane >> 2);
#pragma unroll
        for (int j = 0; j < 8; j++) {
            int gc = n0 + warp_n * 64 + j * 8 + 2 * (lane & 3);
            float bb0 = bias[gc], bb1 = bias[gc + 1];
#pragma unroll
            for (int half = 0; half < 2; half++) {
                int row = gr + half * 8;
                if (row >= M) continue;
                __half2 hv = __floats2half2_rn(acc[mi][j][2 * half + 0] + bb0,
                                               acc[mi][j][2 * half + 1] + bb1);
                *reinterpret_cast<__half2*>(C16 + (size_t)row * G3 + gc) = hv;
            }
        }
    }
}

// ------------------- CSR build -------------------
__global__ void hist_k(const int* e0, const int* e1, const int* e2, int E, int N)
{
    int e = blockIdx.x * blockDim.x + threadIdx.x;
    if (e >= 3 * E) return;
    int r = e / E, le = e - r * E;
    const int* ei = (r == 0) ? e0 : (r == 1) ? e1 : e2;
    atomicAdd(&g_CNT[r * N + ei[E + le]], 1);
}
__global__ void scan1_k(int ntot)
{
    __shared__ int sh[1024];
    int tid = threadIdx.x;
    int gid = blockIdx.x * 1024 + tid;
    int v = (gid < ntot) ? g_CNT[gid] : 0;
    sh[tid] = v;
    __syncthreads();
    for (int o = 1; o < 1024; o <<= 1) {
        int t = (tid >= o) ? sh[tid - o] : 0;
        __syncthreads();
        sh[tid] += t;
        __syncthreads();
    }
    if (gid < ntot) g_OFF[gid] = sh[tid] - v;
    if (tid == 1023) g_BSUM[blockIdx.x] = sh[1023];
}
__global__ void scan3_k(int ntot)
{
    __shared__ int base;
    if (threadIdx.x == 0) {
        int run = 0;
#pragma unroll 8
        for (int i = 0; i < blockIdx.x; i++) run += g_BSUM[i];
        base = run;
    }
    __syncthreads();
    int gid = blockIdx.x * 1024 + threadIdx.x;
    if (gid >= ntot) return;
    int o = g_OFF[gid] + base;
    g_OFF[gid] = o;
    g_CUR[gid] = o;
}
__global__ void scatter_idx_k(const int* e0, const int* e1, const int* e2, int E, int N)
{
    int e = blockIdx.x * blockDim.x + threadIdx.x;
    if (e >= 3 * E) return;
    int r = e / E, le = e - r * E;
    const int* ei = (r == 0) ? e0 : (r == 1) ? e1 : e2;
    int si = ei[le];
    int ti = ei[E + le];
    int pos = atomicAdd(&g_CUR[r * N + ti], 1);
    g_SRC[pos] = si;
}

// ------------------- gather aggregation (fp16 HS reads) -------------------
__global__ void gather_k(int N, int Etot)
{
    int gw   = (blockIdx.x * blockDim.x + threadIdx.x) >> 5;
    int lane = threadIdx.x & 31;
    if (gw >= 3 * N) return;
    int r = gw / N, ti = gw - r * N;
    int idx = r * N + ti;
    int s = g_OFF[idx];
    int e = (idx + 1 < 3 * N) ? g_OFF[idx + 1] : Etot;
    float* dst = g_AGG[r] + (size_t)ti * HH + lane * 4;
    uint2* dst16 = reinterpret_cast<uint2*>(g_AG16[r] + (size_t)ti * HH + lane * 4);
    float4 acc = make_float4(0.f, 0.f, 0.f, 0.f);
    if (s < e) {
        float at = g_AT[r][ti];
        float den = 0.f;
        for (int base = s; base < e; base += 32) {
            int k = base + lane;
            if (k < e) {
                int si = g_SRC[k];
                float l = g_AS[r][si] + at;
                l = (l > 0.f) ? l : 0.2f * l;
                den += expf(l);
            }
        }
#pragma unroll
        for (int o = 16; o; o >>= 1) den += __shfl_xor_sync(0xffffffffu, den, o);
        float inv = 1.f / (den + 1e-16f);
        for (int base = s; base < e; base += 32) {
            int k = base + lane;
            int si = 0;
            float ex = 0.f;
            if (k < e) {
                si = g_SRC[k];
                float l = g_AS[r][si] + at;
                l = (l > 0.f) ? l : 0.2f * l;
                ex = expf(l);
            }
            int cnt = min(32, e - base);
            for (int j = 0; j < cnt; j++) {
                float exj = __shfl_sync(0xffffffffu, ex, j);
                int   sij = __shfl_sync(0xffffffffu, si, j);
                uint2 p = *reinterpret_cast<const uint2*>(
                    g_HS16[r] + (size_t)sij * HH + lane * 4);
                float4 v = unpack4h(p);
                acc.x += exj * v.x;
                acc.y += exj * v.y;
                acc.z += exj * v.z;
                acc.w += exj * v.w;
            }
        }
        acc.x *= inv; acc.y *= inv; acc.z *= inv; acc.w *= inv;
    }
    *reinterpret_cast<float4*>(dst) = acc;
    *dst16 = pack4h(acc);
}

// ------------------- pointwise -------------------
__global__ void alpha_all(const float* q0, const float* q1, const float* q2, int n)
{
    int gw = (blockIdx.x * blockDim.x + threadIdx.x) >> 5;
    int lane = threadIdx.x & 31;
    if (gw >= 6 * n) return;
    int sel = gw / n, node = gw - sel * n;
    int r = sel >> 1, which = sel & 1;
    const float* qs[3] = {q0, q1, q2};
    const __half* feat = which ? g_HT16[r] : g_HS16[r];
    const float* q = qs[r] + which * HH;
    uint2 p = *reinterpret_cast<const uint2*>(feat + (size_t)node * HH + lane * 4);
    float4 a = unpack4h(p);
    float4 b = *reinterpret_cast<const float4*>(q + lane * 4);
    float s = a.x * b.x + a.y * b.y + a.z * b.z + a.w * b.w;
#pragma unroll
    for (int o = 16; o; o >>= 1) s += __shfl_xor_sync(0xffffffffu, s, o);
    if (lane == 0) {
        if (which) g_AT[r][node] = s;
        else       g_AS[r][node] = s;
    }
}

__global__ void gru_all(int n)
{
    long long i = (long long)blockIdx.x * blockDim.x + threadIdx.x;
    if (i >= 3LL * n * HH) return;
    int r = (int)(i / ((long long)n * HH));
    int j = (int)(i - (long long)r * n * HH);
    int nn = j / HH, h = j - nn * HH;
    const __half* gi = g_GI16[r] + (size_t)nn * G3;
    const __half* gh = g_GH16[r] + (size_t)nn * G3;
    float rr = 1.f / (1.f + expf(-(__half2float(gi[h]) + __half2float(gh[h]))));
    float z  = 1.f / (1.f + expf(-(__half2float(gi[HH + h]) + __half2float(gh[HH + h]))));
    float g  = tanhf(__half2float(gi[2 * HH + h]) + rr * __half2float(gh[2 * HH + h]));
    float a  = g_AGG[r][(size_t)nn * HH + h];
    g_HOUT[r][j] = (1.f - z) * g + z * a;
}

__global__ void final_k(float* __restrict__ out, const float* __restrict__ g, int n)
{
    int warp = (blockIdx.x * blockDim.x + threadIdx.x) >> 5;
    int lane = threadIdx.x & 31;
    if (warp >= n) return;
    size_t off = (size_t)warp * HH + lane * 4;
    float4 u = *reinterpret_cast<const float4*>(g_HOUT[1] + off);
    u.x = fmaxf(u.x, 0.f); u.y = fmaxf(u.y, 0.f);
    u.z = fmaxf(u.z, 0.f); u.w = fmaxf(u.w, 0.f);
    *reinterpret_cast<float4*>(out + off) = u;
    float4 v0 = *reinterpret_cast<const float4*>(g_HOUT[0] + off);
    float4 v1 = *reinterpret_cast<const float4*>(g_HOUT[2] + off);
    float4 gv = *reinterpret_cast<const float4*>(g + lane * 4);
    float d0 = v0.x * gv.x + v0.y * gv.y + v0.z * gv.z + v0.w * gv.w;
    float d1 = v1.x * gv.x + v1.y * gv.y + v1.z * gv.z + v1.w * gv.w;
#pragma unroll
    for (int o = 16; o; o >>= 1) {
        d0 += __shfl_xor_sync(0xffffffffu, d0, o);
        d1 += __shfl_xor_sync(0xffffffffu, d1, o);
    }
    float a0 = expf(d0), a1 = expf(d1);
    float inv = 1.f / (a0 + a1);
    float w0 = a0 * inv, w1 = a1 * inv;
    float4 o4;
    o4.x = fmaxf(w0 * v0.x + w1 * v1.x, 0.f);
    o4.y = fmaxf(w0 * v0.y + w1 * v1.y, 0.f);
    o4.z = fmaxf(w0 * v0.z + w1 * v1.z, 0.f);
    o4.w = fmaxf(w0 * v0.w + w1 * v1.w, 0.f);
    *reinterpret_cast<float4*>(out + (size_t)n * HH + off) = o4;
}

// ---------------------------------------------------------------
extern "C" void kernel_launch(void* const* d_in, const int* in_sizes, int n_in,
                              void* d_out, int out_size)
{
    const float* x_user = (const float*)d_in[0];
    const float* x_item = (const float*)d_in[1];
    const int*   ei_ui  = (const int*)d_in[2];
    const int*   ei_iu  = (const int*)d_in[3];
    const int*   ei_ii  = (const int*)d_in[4];

    int N = in_sizes[0] / DD;
    int E = in_sizes[2] / 2;
    if (N > NMAX) N = NMAX;
    if (E > EMAX) E = EMAX;

    float* out = (float*)d_out;

    cudaFuncSetAttribute(hsht_gemm, cudaFuncAttributeMaxDynamicSharedMemorySize, SMEMSZ);
    cudaFuncSetAttribute(gru_gemm,  cudaFuncAttributeMaxDynamicSharedMemorySize, GSMEM);

    // prep
    int x4 = (N * DD) / 4;
    split_x_k<<<(2 * x4 + 255) / 256, 256>>>(x_user, x_item, x4);
    prep_w_all<<<(WT_TOT + WG_TOT + 255) / 256, 256>>>(
        (const float*)d_in[5],  (const float*)d_in[6],
        (const float*)d_in[12], (const float*)d_in[13],
        (const float*)d_in[19], (const float*)d_in[20],
        (const float*)d_in[8],  (const float*)d_in[9],
        (const float*)d_in[15], (const float*)d_in[16],
        (const float*)d_in[22], (const float*)d_in[23]);

    // CSR build
    int ntot = 3 * N;
    void* pcnt;
    cudaGetSymbolAddress(&pcnt, g_CNT);
    cudaMemsetAsync(pcnt, 0, ntot * sizeof(int));
    hist_k<<<(3 * E + 255) / 256, 256>>>(ei_ui, ei_iu, ei_ii, E, N);
    int nb = (ntot + 1023) / 1024;
    scan1_k<<<nb, 1024>>>(ntot);
    scan3_k<<<nb, 1024>>>(ntot);
    scatter_idx_k<<<(3 * E + 255) / 256, 256>>>(ei_ui, ei_iu, ei_ii, E, N);

    const int mb = NPAD / 128;   // 392

    hsht_gemm<<<dim3(mb, 1, 6), 256, SMEMSZ>>>(N);

    int aBlocks = (int)(((long long)6 * N * 32 + 255) / 256);
    alpha_all<<<aBlocks, 256>>>((const float*)d_in[7], (const float*)d_in[14],
                                (const float*)d_in[21], N);

    gather_k<<<(int)(((long long)3 * N * 32 + 255) / 256), 256>>>(N, 3 * E);

    gru_gemm<<<dim3(mb, 3, 6), 256, GSMEM>>>(
        N,
        (const float*)d_in[10], (const float*)d_in[11],
        (const float*)d_in[17], (const float*)d_in[18],
        (const float*)d_in[24], (const float*)d_in[25]);

    gru_all<<<(int)((3LL * N * HH + 255) / 256), 256>>>(N);

    final_k<<<(N * 32 + 255) / 256, 256>>>(out, (const float*)d_in[27], N);
}

// round 13
// speedup vs baseline: 3.4915x; 1.2139x over previous
#include <cuda_runtime.h>
#include <cuda_fp16.h>
#include <math.h>
#include <cstdint>

#define NMAX 50000
#define NPAD 50176   // 392*128
#define EMAX 400000
#define DD   256
#define HH   128
#define G3   384
#define SROW 80                  // smem bytes per 32-halfword row (64B + 16B pad)
#define TILE_B (128 * SROW)      // 10240
#define HSTAGE (2 * TILE_B)      // 20480 (hsht: A16, B16)
#define SMEMSZ (2 * HSTAGE)      // 40960
#define BROW   272               // 128*2 + 16 pad
#define GB_TILE (128 * BROW)     // 34816
#define GA_TILE (128 * SROW)     // 10240
#define GSMEM  (GB_TILE + 2 * GA_TILE)  // 55296

// ------------------- scratch -------------------
__device__ __align__(16) __half g_GI16[3][NPAD*G3];
__device__ __align__(16) __half g_GH16[3][NPAD*G3];
__device__ __align__(16) float  g_AS [3][NMAX];
__device__ __align__(16) float  g_AT [3][NMAX];
__device__ __align__(16) __half g_XU16[NPAD*DD], g_XI16[NPAD*DD];
__device__ __align__(16) __half g_HS16[3][NPAD*HH];
__device__ __align__(16) __half g_HT16[3][NPAD*HH];
__device__ __align__(16) __half g_AG16[3][NPAD*HH];
__device__ __align__(16) __half g_WT16[6][128*DD];
__device__ __align__(16) __half g_WG16[6][G3*HH];
// CSR
__device__ int g_CNT [3*NMAX];
__device__ int g_OFF [3*NMAX];
__device__ int g_CUR [3*NMAX];
__device__ int g_SRC [3*EMAX];
__device__ int g_BSUM[256];

// ------------------- PTX helpers -------------------
__device__ __forceinline__ uint32_t smem_u32(const void* p) {
    uint32_t a;
    asm("{ .reg .u64 t; cvta.to.shared.u64 t, %1; cvt.u32.u64 %0, t; }" : "=r"(a) : "l"(p));
    return a;
}
__device__ __forceinline__ void ldsm4(uint32_t* r, uint32_t addr) {
    asm volatile("ldmatrix.sync.aligned.m8n8.x4.shared.b16 {%0,%1,%2,%3}, [%4];"
                 : "=r"(r[0]), "=r"(r[1]), "=r"(r[2]), "=r"(r[3]) : "r"(addr));
}
__device__ __forceinline__ void mma_f16(float* d, const uint32_t* a, const uint32_t* b) {
    asm volatile(
        "mma.sync.aligned.m16n8k16.row.col.f32.f16.f16.f32 "
        "{%0,%1,%2,%3}, {%4,%5,%6,%7}, {%8,%9}, {%0,%1,%2,%3};"
        : "+f"(d[0]), "+f"(d[1]), "+f"(d[2]), "+f"(d[3])
        : "r"(a[0]), "r"(a[1]), "r"(a[2]), "r"(a[3]), "r"(b[0]), "r"(b[1]));
}
__device__ __forceinline__ void cpa16(uint32_t dst, const void* src) {
    asm volatile("cp.async.cg.shared.global [%0], [%1], 16;" :: "r"(dst), "l"(src));
}
__device__ __forceinline__ uint2 pack4h(float4 v) {
    __half h0 = __float2half_rn(v.x), h1 = __float2half_rn(v.y);
    __half h2 = __float2half_rn(v.z), h3 = __float2half_rn(v.w);
    uint2 p;
    p.x = ((uint32_t)__half_as_ushort(h1) << 16) | __half_as_ushort(h0);
    p.y = ((uint32_t)__half_as_ushort(h3) << 16) | __half_as_ushort(h2);
    return p;
}
__device__ __forceinline__ float4 unpack4h(uint2 p) {
    __half2 a = *reinterpret_cast<__half2*>(&p.x);
    __half2 b = *reinterpret_cast<__half2*>(&p.y);
    float2 fa = __half22float2(a);
    float2 fb = __half22float2(b);
    return make_float4(fa.x, fa.y, fb.x, fb.y);
}

// ------------------- prep kernels -------------------
__global__ void split_x_k(const float* __restrict__ xu, const float* __restrict__ xi, int n4)
{
    int i = blockIdx.x * blockDim.x + threadIdx.x;
    if (i >= 2 * n4) return;
    const float* src = (i < n4) ? xu : xi;
    int j = (i < n4) ? i : i - n4;
    float4 v = reinterpret_cast<const float4*>(src)[j];
    uint2 p = pack4h(v);
    if (i < n4) reinterpret_cast<uint2*>(g_XU16)[j] = p;
    else        reinterpret_cast<uint2*>(g_XI16)[j] = p;
}
#define WT_TOT (6 * 128 * 256)
#define WG_TOT (6 * G3 * HH)
__global__ void prep_w_all(
    const float* a0, const float* a1, const float* a2,
    const float* a3, const float* a4, const float* a5,
    const float* g0, const float* g1, const float* g2,
    const float* g3, const float* g4, const float* g5)
{
    int i = blockIdx.x * blockDim.x + threadIdx.x;
    if (i < WT_TOT) {
        const float* ws[6] = {a0, a1, a2, a3, a4, a5};
        int z = i >> 15, j = i & 32767;
        int n = j >> 8, k = j & 255;
        g_WT16[z][j] = __float2half_rn(ws[z][k * 128 + n]);
    } else if (i < WT_TOT + WG_TOT) {
        const float* ws[6] = {g0, g1, g2, g3, g4, g5};
        int t = i - WT_TOT;
        int z = t / (G3 * HH), j = t % (G3 * HH);
        g_WG16[z][j] = __float2half_rn(ws[z][j]);
    }
}

// -------- hsht GEMM: fp16, BK=32, 2-stage -----
__global__ void __launch_bounds__(256, 2) hsht_gemm(int M)
{
    extern __shared__ char smem[];
    const int z = blockIdx.z, r = z >> 1;
    const __half* AT6[6] = {g_XU16, g_XI16, g_XI16, g_XU16, g_XI16, g_XI16};
    const __half* A16 = AT6[z];
    const __half* B16 = g_WT16[z];
    __half* C16 = (z & 1) ? g_HT16[r] : g_HS16[r];
    const int K = DD, Nc = HH;
    const int m0 = blockIdx.x * 128, n0 = 0;

    const uint32_t sb = smem_u32(smem);
    const int tid  = threadIdx.x;
    const int wid  = tid >> 5;
    const int lane = tid & 31;
    const int warp_m = wid & 3;
    const int warp_n = wid >> 2;

    float acc[2][8][4];
#pragma unroll
    for (int i = 0; i < 2; i++)
#pragma unroll
        for (int j = 0; j < 8; j++)
#pragma unroll
            for (int t = 0; t < 4; t++) acc[i][j][t] = 0.f;

    const int nchunks = K >> 5;   // 8

#define FILL(kc, stg) do {                                                      \
        const int k0f = (kc) << 5;                                              \
        const uint32_t s0 = sb + (stg) * HSTAGE;                                \
        _Pragma("unroll")                                                       \
        for (int it = 0; it < 4; it++) {                                        \
            int s = tid + it * 256;                                             \
            int tile = s >> 9, w = s & 511, row = w >> 2, q = w & 3;            \
            uint32_t dst = s0 + tile * TILE_B + row * SROW + q * 16;            \
            const __half* src = tile ? B16 : A16;                               \
            size_t off = tile ? ((size_t)(n0 + row) * K + k0f + q * 8)          \
                              : ((size_t)(m0 + row) * K + k0f + q * 8);         \
            cpa16(dst, src + off);                                              \
        }                                                                       \
        asm volatile("cp.async.commit_group;" ::: "memory");                    \
    } while (0)

    FILL(0, 0);

    for (int kc = 0; kc < nchunks; kc++) {
        if (kc + 1 < nchunks) {
            FILL(kc + 1, (kc + 1) & 1);
            asm volatile("cp.async.wait_group 1;" ::: "memory");
        } else {
            asm volatile("cp.async.wait_group 0;" ::: "memory");
        }
        __syncthreads();

        const uint32_t s0 = sb + (kc & 1) * HSTAGE;
        const uint32_t sA = s0;
        const uint32_t sB = s0 + TILE_B;

#pragma unroll
        for (int ks = 0; ks < 2; ks++) {
            uint32_t af[2][4];
            {
                int rr = lane & 15;
                int c8 = lane >> 4;
                uint32_t off = (uint32_t)((warp_m * 32 + rr) * SROW + (ks * 16 + c8 * 8) * 2);
                ldsm4(af[0], sA + off);
                ldsm4(af[1], sA + off + 16 * SROW);
            }
            uint32_t bf[8][2];
            {
                int sub = lane >> 3, wi = lane & 7;
                int n_off = (sub >> 1) * 8 + wi;
                int k_off = ks * 16 + (sub & 1) * 8;
                uint32_t base = (uint32_t)((warp_n * 64 + n_off) * SROW + k_off * 2);
#pragma unroll
                for (int jj = 0; jj < 4; jj++) {
                    uint32_t r4[4];
                    ldsm4(r4, sB + base + jj * 16 * SROW);
                    bf[2 * jj][0] = r4[0]; bf[2 * jj][1] = r4[1];
                    bf[2 * jj + 1][0] = r4[2]; bf[2 * jj + 1][1] = r4[3];
                }
            }
#pragma unroll
            for (int mi = 0; mi < 2; mi++)
#pragma unroll
                for (int j = 0; j < 8; j++)
                    mma_f16(acc[mi][j], af[mi], bf[j]);
        }
        __syncthreads();
    }
#undef FILL

#pragma unroll
    for (int mi = 0; mi < 2; mi++) {
        int gr = m0 + warp_m * 32 + mi * 16 + (lane >> 2);
#pragma unroll
        for (int j = 0; j < 8; j++) {
            int gc = n0 + warp_n * 64 + j * 8 + 2 * (lane & 3);
#pragma unroll
            for (int half = 0; half < 2; half++) {
                int row = gr + half * 8;
                if (row >= M) continue;
                __half2 hv = __floats2half2_rn(acc[mi][j][2 * half + 0],
                                               acc[mi][j][2 * half + 1]);
                *reinterpret_cast<__half2*>(C16 + (size_t)row * Nc + gc) = hv;
            }
        }
    }
}

// ---------- gru GEMM: fp16, B resident, A 2-stage --------
__global__ void __launch_bounds__(256, 2) gru_gemm(
    int M,
    const float* b0, const float* b1, const float* b2,
    const float* b3, const float* b4, const float* b5)
{
    extern __shared__ char smem[];
    const int z = blockIdx.z, r = z >> 1, which = z & 1;
    const float* biases[6] = {b0, b1, b2, b3, b4, b5};
    const __half* A16 = which ? g_AG16[r] : g_HT16[r];
    const __half* B16 = g_WG16[z];
    const float* bias = biases[z];
    __half* C16 = which ? g_GH16[r] : g_GI16[r];
    const int K = HH;
    const int m0 = blockIdx.x * 128;
    const int n0 = blockIdx.y * 128;

    const uint32_t sb = smem_u32(smem);
    const uint32_t sB  = sb;
    const uint32_t sA0 = sb + GB_TILE;
    const int tid  = threadIdx.x;
    const int wid  = tid >> 5;
    const int lane = tid & 31;
    const int warp_m = wid & 3;
    const int warp_n = wid >> 2;

    float acc[2][8][4];
#pragma unroll
    for (int i = 0; i < 2; i++)
#pragma unroll
        for (int j = 0; j < 8; j++)
#pragma unroll
            for (int t = 0; t < 4; t++) acc[i][j][t] = 0.f;

#pragma unroll
    for (int it = 0; it < 8; it++) {
        int s = tid + it * 256;
        int row = s >> 4, q = s & 15;
        cpa16(sB + row * BROW + q * 16, B16 + (size_t)(n0 + row) * K + q * 8);
    }
    asm volatile("cp.async.commit_group;" ::: "memory");

#define FILLA(kc, stg) do {                                                     \
        const int k0f = (kc) << 5;                                              \
        const uint32_t s0 = sA0 + (stg) * GA_TILE;                              \
        _Pragma("unroll")                                                       \
        for (int it = 0; it < 2; it++) {                                        \
            int s = tid + it * 256;                                             \
            int row = s >> 2, q = s & 3;                                        \
            cpa16(s0 + row * SROW + q * 16,                                     \
                  A16 + (size_t)(m0 + row) * K + k0f + q * 8);                  \
        }                                                                       \
        asm volatile("cp.async.commit_group;" ::: "memory");                    \
    } while (0)

    FILLA(0, 0);

    const int nchunks = K >> 5;   // 4
    for (int kc = 0; kc < nchunks; kc++) {
        if (kc + 1 < nchunks) {
            FILLA(kc + 1, (kc + 1) & 1);
            asm volatile("cp.async.wait_group 1;" ::: "memory");
        } else {
            asm volatile("cp.async.wait_group 0;" ::: "memory");
        }
        __syncthreads();

        const uint32_t sA = sA0 + (kc & 1) * GA_TILE;

#pragma unroll
        for (int ks = 0; ks < 2; ks++) {
            const int kglob = kc * 32 + ks * 16;
            uint32_t af[2][4];
            {
                int rr = lane & 15;
                int c8 = lane >> 4;
                uint32_t off = (uint32_t)((warp_m * 32 + rr) * SROW + (ks * 16 + c8 * 8) * 2);
                ldsm4(af[0], sA + off);
                ldsm4(af[1], sA + off + 16 * SROW);
            }
            uint32_t bf[8][2];
            {
                int sub = lane >> 3, wi = lane & 7;
                int n_off = (sub >> 1) * 8 + wi;
                int k_off = kglob + (sub & 1) * 8;
                uint32_t base = (uint32_t)((warp_n * 64 + n_off) * BROW + k_off * 2);
#pragma unroll
                for (int jj = 0; jj < 4; jj++) {
                    uint32_t r4[4];
                    ldsm4(r4, sB + base + jj * 16 * BROW);
                    bf[2 * jj][0] = r4[0]; bf[2 * jj][1] = r4[1];
                    bf[2 * jj + 1][0] = r4[2]; bf[2 * jj + 1][1] = r4[3];
                }
            }
#pragma unroll
            for (int mi = 0; mi < 2; mi++)
#pragma unroll
                for (int j = 0; j < 8; j++)
                    mma_f16(acc[mi][j], af[mi], bf[j]);
        }
        __syncthreads();
    }
#undef FILLA

#pragma unroll
    for (int mi = 0; mi < 2; mi++) {
        int gr = m0 + warp_m * 32 + mi * 16 + (lane >> 2);
#pragma unroll
        for (int j = 0; j < 8; j++) {
            int gc = n0 + warp_n * 64 + j * 8 + 2 * (lane & 3);
            float bb0 = bias[gc], bb1 = bias[gc + 1];
#pragma unroll
            for (int half = 0; half < 2; half++) {
                int row = gr + half * 8;
                if (row >= M) continue;
                __half2 hv = __floats2half2_rn(acc[mi][j][2 * half + 0] + bb0,
                                               acc[mi][j][2 * half + 1] + bb1);
                *reinterpret_cast<__half2*>(C16 + (size_t)row * G3 + gc) = hv;
            }
        }
    }
}

// ------------------- CSR build -------------------
__global__ void hist_k(const int* e0, const int* e1, const int* e2, int E, int N)
{
    int e = blockIdx.x * blockDim.x + threadIdx.x;
    if (e >= 3 * E) return;
    int r = e / E, le = e - r * E;
    const int* ei = (r == 0) ? e0 : (r == 1) ? e1 : e2;
    atomicAdd(&g_CNT[r * N + ei[E + le]], 1);
}
__global__ void scan1_k(int ntot)
{
    __shared__ int sh[1024];
    int tid = threadIdx.x;
    int gid = blockIdx.x * 1024 + tid;
    int v = (gid < ntot) ? g_CNT[gid] : 0;
    sh[tid] = v;
    __syncthreads();
    for (int o = 1; o < 1024; o <<= 1) {
        int t = (tid >= o) ? sh[tid - o] : 0;
        __syncthreads();
        sh[tid] += t;
        __syncthreads();
    }
    if (gid < ntot) g_OFF[gid] = sh[tid] - v;
    if (tid == 1023) g_BSUM[blockIdx.x] = sh[1023];
}
__global__ void scan3_k(int ntot)
{
    __shared__ int base;
    if (threadIdx.x == 0) {
        int run = 0;
#pragma unroll 8
        for (int i = 0; i < blockIdx.x; i++) run += g_BSUM[i];
        base = run;
    }
    __syncthreads();
    int gid = blockIdx.x * 1024 + threadIdx.x;
    if (gid >= ntot) return;
    int o = g_OFF[gid] + base;
    g_OFF[gid] = o;
    g_CUR[gid] = o;
}
__global__ void scatter_idx_k(const int* e0, const int* e1, const int* e2, int E, int N)
{
    int e = blockIdx.x * blockDim.x + threadIdx.x;
    if (e >= 3 * E) return;
    int r = e / E, le = e - r * E;
    const int* ei = (r == 0) ? e0 : (r == 1) ? e1 : e2;
    int si = ei[le];
    int ti = ei[E + le];
    int pos = atomicAdd(&g_CUR[r * N + ti], 1);
    g_SRC[pos] = si;
}

// ------------------- gather aggregation (fp16 in/out) -------------------
__global__ void gather_k(int N, int Etot)
{
    int gw   = (blockIdx.x * blockDim.x + threadIdx.x) >> 5;
    int lane = threadIdx.x & 31;
    if (gw >= 3 * N) return;
    int r = gw / N, ti = gw - r * N;
    int idx = r * N + ti;
    int s = g_OFF[idx];
    int e = (idx + 1 < 3 * N) ? g_OFF[idx + 1] : Etot;
    uint2* dst16 = reinterpret_cast<uint2*>(g_AG16[r] + (size_t)ti * HH + lane * 4);
    float4 acc = make_float4(0.f, 0.f, 0.f, 0.f);
    if (s < e) {
        float at = g_AT[r][ti];
        float den = 0.f;
        for (int base = s; base < e; base += 32) {
            int k = base + lane;
            if (k < e) {
                int si = g_SRC[k];
                float l = g_AS[r][si] + at;
                l = (l > 0.f) ? l : 0.2f * l;
                den += expf(l);
            }
        }
#pragma unroll
        for (int o = 16; o; o >>= 1) den += __shfl_xor_sync(0xffffffffu, den, o);
        float inv = 1.f / (den + 1e-16f);
        for (int base = s; base < e; base += 32) {
            int k = base + lane;
            int si = 0;
            float ex = 0.f;
            if (k < e) {
                si = g_SRC[k];
                float l = g_AS[r][si] + at;
                l = (l > 0.f) ? l : 0.2f * l;
                ex = expf(l);
            }
            int cnt = min(32, e - base);
            for (int j = 0; j < cnt; j++) {
                float exj = __shfl_sync(0xffffffffu, ex, j);
                int   sij = __shfl_sync(0xffffffffu, si, j);
                uint2 p = *reinterpret_cast<const uint2*>(
                    g_HS16[r] + (size_t)sij * HH + lane * 4);
                float4 v = unpack4h(p);
                acc.x += exj * v.x;
                acc.y += exj * v.y;
                acc.z += exj * v.z;
                acc.w += exj * v.w;
            }
        }
        acc.x *= inv; acc.y *= inv; acc.z *= inv; acc.w *= inv;
    }
    *dst16 = pack4h(acc);
}

// ------------------- pointwise -------------------
__global__ void alpha_all(const float* q0, const float* q1, const float* q2, int n)
{
    int gw = (blockIdx.x * blockDim.x + threadIdx.x) >> 5;
    int lane = threadIdx.x & 31;
    if (gw >= 6 * n) return;
    int sel = gw / n, node = gw - sel * n;
    int r = sel >> 1, which = sel & 1;
    const float* qs[3] = {q0, q1, q2};
    const __half* feat = which ? g_HT16[r] : g_HS16[r];
    const float* q = qs[r] + which * HH;
    uint2 p = *reinterpret_cast<const uint2*>(feat + (size_t)node * HH + lane * 4);
    float4 a = unpack4h(p);
    float4 b = *reinterpret_cast<const float4*>(q + lane * 4);
    float s = a.x * b.x + a.y * b.y + a.z * b.z + a.w * b.w;
#pragma unroll
    for (int o = 16; o; o >>= 1) s += __shfl_xor_sync(0xffffffffu, s, o);
    if (lane == 0) {
        if (which) g_AT[r][node] = s;
        else       g_AS[r][node] = s;
    }
}

// ------- fused GRU combine + final outputs: one warp per node -------
// hout[r] = (1-z)*tanh(gi_n + r*gh_n) + z*agg ; then user = relu(hout[1]),
// item = relu(semantic_att(hout[0], hout[2], g_item))
__global__ void gru_final_k(float* __restrict__ out, const float* __restrict__ g, int n)
{
    int node = (blockIdx.x * blockDim.x + threadIdx.x) >> 5;
    int lane = threadIdx.x & 31;
    if (node >= n) return;
    int h4 = lane * 4;

    float hout[3][4];
#pragma unroll
    for (int r = 0; r < 3; r++) {
        const __half* gi = g_GI16[r] + (size_t)node * G3;
        const __half* gh = g_GH16[r] + (size_t)node * G3;
        float4 gir = unpack4h(*reinterpret_cast<const uint2*>(gi + h4));
        float4 giz = unpack4h(*reinterpret_cast<const uint2*>(gi + HH + h4));
        float4 gin = unpack4h(*reinterpret_cast<const uint2*>(gi + 2 * HH + h4));
        float4 ghr = unpack4h(*reinterpret_cast<const uint2*>(gh + h4));
        float4 ghz = unpack4h(*reinterpret_cast<const uint2*>(gh + HH + h4));
        float4 ghn = unpack4h(*reinterpret_cast<const uint2*>(gh + 2 * HH + h4));
        float4 a = unpack4h(*reinterpret_cast<const uint2*>(
            g_AG16[r] + (size_t)node * HH + h4));
        float gi_r[4] = {gir.x, gir.y, gir.z, gir.w};
        float gi_z[4] = {giz.x, giz.y, giz.z, giz.w};
        float gi_n[4] = {gin.x, gin.y, gin.z, gin.w};
        float gh_r[4] = {ghr.x, ghr.y, ghr.z, ghr.w};
        float gh_z[4] = {ghz.x, ghz.y, ghz.z, ghz.w};
        float gh_n[4] = {ghn.x, ghn.y, ghn.z, ghn.w};
        float av[4]   = {a.x, a.y, a.z, a.w};
#pragma unroll
        for (int t = 0; t < 4; t++) {
            float rr = 1.f / (1.f + expf(-(gi_r[t] + gh_r[t])));
            float zz = 1.f / (1.f + expf(-(gi_z[t] + gh_z[t])));
            float gg = tanhf(gi_n[t] + rr * gh_n[t]);
            hout[r][t] = (1.f - zz) * gg + zz * av[t];
        }
    }

    size_t off = (size_t)node * HH + h4;
    // user output = relu(hout[1])
    float4 u;
    u.x = fmaxf(hout[1][0], 0.f);
    u.y = fmaxf(hout[1][1], 0.f);
    u.z = fmaxf(hout[1][2], 0.f);
    u.w = fmaxf(hout[1][3], 0.f);
    *reinterpret_cast<float4*>(out + off) = u;

    // item semantic attention over hout[0], hout[2]
    float4 gv = *reinterpret_cast<const float4*>(g + h4);
    float gvv[4] = {gv.x, gv.y, gv.z, gv.w};
    float d0 = 0.f, d1 = 0.f;
#pragma unroll
    for (int t = 0; t < 4; t++) {
        d0 += hout[0][t] * gvv[t];
        d1 += hout[2][t] * gvv[t];
    }
#pragma unroll
    for (int o = 16; o; o >>= 1) {
        d0 += __shfl_xor_sync(0xffffffffu, d0, o);
        d1 += __shfl_xor_sync(0xffffffffu, d1, o);
    }
    float a0 = expf(d0), a1 = expf(d1);
    float inv = 1.f / (a0 + a1);
    float w0 = a0 * inv, w1 = a1 * inv;
    float4 o4;
    o4.x = fmaxf(w0 * hout[0][0] + w1 * hout[2][0], 0.f);
    o4.y = fmaxf(w0 * hout[0][1] + w1 * hout[2][1], 0.f);
    o4.z = fmaxf(w0 * hout[0][2] + w1 * hout[2][2], 0.f);
    o4.w = fmaxf(w0 * hout[0][3] + w1 * hout[2][3], 0.f);
    *reinterpret_cast<float4*>(out + (size_t)n * HH + off) = o4;
}

// ---------------------------------------------------------------
extern "C" void kernel_launch(void* const* d_in, const int* in_sizes, int n_in,
                              void* d_out, int out_size)
{
    const float* x_user = (const float*)d_in[0];
    const float* x_item = (const float*)d_in[1];
    const int*   ei_ui  = (const int*)d_in[2];
    const int*   ei_iu  = (const int*)d_in[3];
    const int*   ei_ii  = (const int*)d_in[4];

    int N = in_sizes[0] / DD;
    int E = in_sizes[2] / 2;
    if (N > NMAX) N = NMAX;
    if (E > EMAX) E = EMAX;

    float* out = (float*)d_out;

    cudaFuncSetAttribute(hsht_gemm, cudaFuncAttributeMaxDynamicSharedMemorySize, SMEMSZ);
    cudaFuncSetAttribute(gru_gemm,  cudaFuncAttributeMaxDynamicSharedMemorySize, GSMEM);

    // prep
    int x4 = (N * DD) / 4;
    split_x_k<<<(2 * x4 + 255) / 256, 256>>>(x_user, x_item, x4);
    prep_w_all<<<(WT_TOT + WG_TOT + 255) / 256, 256>>>(
        (const float*)d_in[5],  (const float*)d_in[6],
        (const float*)d_in[12], (const float*)d_in[13],
        (const float*)d_in[19], (const float*)d_in[20],
        (const float*)d_in[8],  (const float*)d_in[9],
        (const float*)d_in[15], (const float*)d_in[16],
        (const float*)d_in[22], (const float*)d_in[23]);

    // CSR build
    int ntot = 3 * N;
    void* pcnt;
    cudaGetSymbolAddress(&pcnt, g_CNT);
    cudaMemsetAsync(pcnt, 0, ntot * sizeof(int));
    hist_k<<<(3 * E + 255) / 256, 256>>>(ei_ui, ei_iu, ei_ii, E, N);
    int nb = (ntot + 1023) / 1024;
    scan1_k<<<nb, 1024>>>(ntot);
    scan3_k<<<nb, 1024>>>(ntot);
    scatter_idx_k<<<(3 * E + 255) / 256, 256>>>(ei_ui, ei_iu, ei_ii, E, N);

    const int mb = NPAD / 128;   // 392

    hsht_gemm<<<dim3(mb, 1, 6), 256, SMEMSZ>>>(N);

    int aBlocks = (int)(((long long)6 * N * 32 + 255) / 256);
    alpha_all<<<aBlocks, 256>>>((const float*)d_in[7], (const float*)d_in[14],
                                (const float*)d_in[21], N);

    gather_k<<<(int)(((long long)3 * N * 32 + 255) / 256), 256>>>(N, 3 * E);

    gru_gemm<<<dim3(mb, 3, 6), 256, GSMEM>>>(
        N,
        (const float*)d_in[10], (const float*)d_in[11],
        (const float*)d_in[17], (const float*)d_in[18],
        (const float*)d_in[24], (const float*)d_in[25]);

    // fused GRU combine + outputs
    gru_final_k<<<(N * 32 + 255) / 256, 256>>>(out, (const float*)d_in[27], N);
}

// round 14
// speedup vs baseline: 3.6824x; 1.0547x over previous
#include <cuda_runtime.h>
#include <cuda_fp16.h>
#include <math.h>
#include <cstdint>

#define NMAX 50000
#define NPAD 50176   // 392*128
#define EMAX 400000
#define DD   256
#define HH   128
#define G3   384
#define SROW 80                  // smem bytes per 32-halfword row (64B + 16B pad)
#define TILE_B (128 * SROW)      // 10240
#define HSTAGE (2 * TILE_B)      // 20480 (hsht: A16, B16)
#define SMEMSZ (2 * HSTAGE)      // 40960
// gru_gemm: A resident (128x128 fp16), B 2-stage
#define GROW   272               // 128*2 + 16 pad
#define G_TILE (128 * GROW)      // 34816
#define GSMEM  (3 * G_TILE)      // 104448 (A + 2 B stages)

// ------------------- scratch -------------------
__device__ __align__(16) __half g_GI16[3][NPAD*G3];
__device__ __align__(16) __half g_GH16[3][NPAD*G3];
__device__ __align__(16) float  g_AS [3][NMAX];
__device__ __align__(16) float  g_AT [3][NMAX];
__device__ __align__(16) __half g_XU16[NPAD*DD], g_XI16[NPAD*DD];
__device__ __align__(16) __half g_HS16[3][NPAD*HH];
__device__ __align__(16) __half g_HT16[3][NPAD*HH];
__device__ __align__(16) __half g_AG16[3][NPAD*HH];
__device__ __align__(16) __half g_WT16[6][128*DD];
__device__ __align__(16) __half g_WG16[6][G3*HH];
// CSR (g_CNT is zero at load; scan1 re-zeroes it every run)
__device__ int g_CNT [3*NMAX];
__device__ int g_OFF [3*NMAX];
__device__ int g_CUR [3*NMAX];
__device__ int g_SRC [3*EMAX];
__device__ int g_BSUM[256];

// ------------------- PTX helpers -------------------
__device__ __forceinline__ uint32_t smem_u32(const void* p) {
    uint32_t a;
    asm("{ .reg .u64 t; cvta.to.shared.u64 t, %1; cvt.u32.u64 %0, t; }" : "=r"(a) : "l"(p));
    return a;
}
__device__ __forceinline__ void ldsm4(uint32_t* r, uint32_t addr) {
    asm volatile("ldmatrix.sync.aligned.m8n8.x4.shared.b16 {%0,%1,%2,%3}, [%4];"
                 : "=r"(r[0]), "=r"(r[1]), "=r"(r[2]), "=r"(r[3]) : "r"(addr));
}
__device__ __forceinline__ void mma_f16(float* d, const uint32_t* a, const uint32_t* b) {
    asm volatile(
        "mma.sync.aligned.m16n8k16.row.col.f32.f16.f16.f32 "
        "{%0,%1,%2,%3}, {%4,%5,%6,%7}, {%8,%9}, {%0,%1,%2,%3};"
        : "+f"(d[0]), "+f"(d[1]), "+f"(d[2]), "+f"(d[3])
        : "r"(a[0]), "r"(a[1]), "r"(a[2]), "r"(a[3]), "r"(b[0]), "r"(b[1]));
}
__device__ __forceinline__ void cpa16(uint32_t dst, const void* src) {
    asm volatile("cp.async.cg.shared.global [%0], [%1], 16;" :: "r"(dst), "l"(src));
}
__device__ __forceinline__ uint2 pack4h(float4 v) {
    __half h0 = __float2half_rn(v.x), h1 = __float2half_rn(v.y);
    __half h2 = __float2half_rn(v.z), h3 = __float2half_rn(v.w);
    uint2 p;
    p.x = ((uint32_t)__half_as_ushort(h1) << 16) | __half_as_ushort(h0);
    p.y = ((uint32_t)__half_as_ushort(h3) << 16) | __half_as_ushort(h2);
    return p;
}
__device__ __forceinline__ float4 unpack4h(uint2 p) {
    __half2 a = *reinterpret_cast<__half2*>(&p.x);
    __half2 b = *reinterpret_cast<__half2*>(&p.y);
    float2 fa = __half22float2(a);
    float2 fb = __half22float2(b);
    return make_float4(fa.x, fa.y, fb.x, fb.y);
}

// ------------------- prep kernels -------------------
__global__ void split_x_k(const float* __restrict__ xu, const float* __restrict__ xi, int n4)
{
    int i = blockIdx.x * blockDim.x + threadIdx.x;
    if (i >= 2 * n4) return;
    const float* src = (i < n4) ? xu : xi;
    int j = (i < n4) ? i : i - n4;
    float4 v = reinterpret_cast<const float4*>(src)[j];
    uint2 p = pack4h(v);
    if (i < n4) reinterpret_cast<uint2*>(g_XU16)[j] = p;
    else        reinterpret_cast<uint2*>(g_XI16)[j] = p;
}
#define WT_TOT (6 * 128 * 256)
#define WG_TOT (6 * G3 * HH)
__global__ void prep_w_all(
    const float* a0, const float* a1, const float* a2,
    const float* a3, const float* a4, const float* a5,
    const float* g0, const float* g1, const float* g2,
    const float* g3, const float* g4, const float* g5)
{
    int i = blockIdx.x * blockDim.x + threadIdx.x;
    if (i < WT_TOT) {
        const float* ws[6] = {a0, a1, a2, a3, a4, a5};
        int z = i >> 15, j = i & 32767;
        int n = j >> 8, k = j & 255;
        g_WT16[z][j] = __float2half_rn(ws[z][k * 128 + n]);
    } else if (i < WT_TOT + WG_TOT) {
        const float* ws[6] = {g0, g1, g2, g3, g4, g5};
        int t = i - WT_TOT;
        int z = t / (G3 * HH), j = t % (G3 * HH);
        g_WG16[z][j] = __float2half_rn(ws[z][j]);
    }
}

// -------- hsht GEMM: fp16, BK=32, 2-stage -----
__global__ void __launch_bounds__(256, 2) hsht_gemm(int M)
{
    extern __shared__ char smem[];
    const int z = blockIdx.z, r = z >> 1;
    const __half* AT6[6] = {g_XU16, g_XI16, g_XI16, g_XU16, g_XI16, g_XI16};
    const __half* A16 = AT6[z];
    const __half* B16 = g_WT16[z];
    __half* C16 = (z & 1) ? g_HT16[r] : g_HS16[r];
    const int K = DD, Nc = HH;
    const int m0 = blockIdx.x * 128, n0 = 0;

    const uint32_t sb = smem_u32(smem);
    const int tid  = threadIdx.x;
    const int wid  = tid >> 5;
    const int lane = tid & 31;
    const int warp_m = wid & 3;
    const int warp_n = wid >> 2;

    float acc[2][8][4];
#pragma unroll
    for (int i = 0; i < 2; i++)
#pragma unroll
        for (int j = 0; j < 8; j++)
#pragma unroll
            for (int t = 0; t < 4; t++) acc[i][j][t] = 0.f;

    const int nchunks = K >> 5;   // 8

#define FILL(kc, stg) do {                                                      \
        const int k0f = (kc) << 5;                                              \
        const uint32_t s0 = sb + (stg) * HSTAGE;                                \
        _Pragma("unroll")                                                       \
        for (int it = 0; it < 4; it++) {                                        \
            int s = tid + it * 256;                                             \
            int tile = s >> 9, w = s & 511, row = w >> 2, q = w & 3;            \
            uint32_t dst = s0 + tile * TILE_B + row * SROW + q * 16;            \
            const __half* src = tile ? B16 : A16;                               \
            size_t off = tile ? ((size_t)(n0 + row) * K + k0f + q * 8)          \
                              : ((size_t)(m0 + row) * K + k0f + q * 8);         \
            cpa16(dst, src + off);                                              \
        }                                                                       \
        asm volatile("cp.async.commit_group;" ::: "memory");                    \
    } while (0)

    FILL(0, 0);

    for (int kc = 0; kc < nchunks; kc++) {
        if (kc + 1 < nchunks) {
            FILL(kc + 1, (kc + 1) & 1);
            asm volatile("cp.async.wait_group 1;" ::: "memory");
        } else {
            asm volatile("cp.async.wait_group 0;" ::: "memory");
        }
        __syncthreads();

        const uint32_t s0 = sb + (kc & 1) * HSTAGE;
        const uint32_t sA = s0;
        const uint32_t sB = s0 + TILE_B;

#pragma unroll
        for (int ks = 0; ks < 2; ks++) {
            uint32_t af[2][4];
            {
                int rr = lane & 15;
                int c8 = lane >> 4;
                uint32_t off = (uint32_t)((warp_m * 32 + rr) * SROW + (ks * 16 + c8 * 8) * 2);
                ldsm4(af[0], sA + off);
                ldsm4(af[1], sA + off + 16 * SROW);
            }
            uint32_t bf[8][2];
            {
                int sub = lane >> 3, wi = lane & 7;
                int n_off = (sub >> 1) * 8 + wi;
                int k_off = ks * 16 + (sub & 1) * 8;
                uint32_t base = (uint32_t)((warp_n * 64 + n_off) * SROW + k_off * 2);
#pragma unroll
                for (int jj = 0; jj < 4; jj++) {
                    uint32_t r4[4];
                    ldsm4(r4, sB + base + jj * 16 * SROW);
                    bf[2 * jj][0] = r4[0]; bf[2 * jj][1] = r4[1];
                    bf[2 * jj + 1][0] = r4[2]; bf[2 * jj + 1][1] = r4[3];
                }
            }
#pragma unroll
            for (int mi = 0; mi < 2; mi++)
#pragma unroll
                for (int j = 0; j < 8; j++)
                    mma_f16(acc[mi][j], af[mi], bf[j]);
        }
        __syncthreads();
    }
#undef FILL

#pragma unroll
    for (int mi = 0; mi < 2; mi++) {
        int gr = m0 + warp_m * 32 + mi * 16 + (lane >> 2);
#pragma unroll
        for (int j = 0; j < 8; j++) {
            int gc = n0 + warp_n * 64 + j * 8 + 2 * (lane & 3);
#pragma unroll
            for (int half = 0; half < 2; half++) {
                int row = gr + half * 8;
                if (row >= M) continue;
                __half2 hv = __floats2half2_rn(acc[mi][j][2 * half + 0],
                                               acc[mi][j][2 * half + 1]);
                *reinterpret_cast<__half2*>(C16 + (size_t)row * Nc + gc) = hv;
            }
        }
    }
}

// ---------- gru GEMM: A resident, loop 3 n-blocks with B 2-stage ----------
__global__ void __launch_bounds__(256, 2) gru_gemm(
    int M,
    const float* b0, const float* b1, const float* b2,
    const float* b3, const float* b4, const float* b5)
{
    extern __shared__ char smem[];
    const int z = blockIdx.z, r = z >> 1, which = z & 1;
    const float* biases[6] = {b0, b1, b2, b3, b4, b5};
    const __half* A16 = which ? g_AG16[r] : g_HT16[r];
    const __half* B16 = g_WG16[z];
    const float* bias = biases[z];
    __half* C16 = which ? g_GH16[r] : g_GI16[r];
    const int K = HH;
    const int m0 = blockIdx.x * 128;

    const uint32_t sb = smem_u32(smem);
    const uint32_t sA  = sb;                 // A resident: 128x272
    const uint32_t sB0 = sb + G_TILE;        // 2 B stages
    const int tid  = threadIdx.x;
    const int wid  = tid >> 5;
    const int lane = tid & 31;
    const int warp_m = wid & 3;
    const int warp_n = wid >> 2;

    // ---- A prologue: 128 rows x 16 x 16B = 2048 cp.async (8/thread) ----
#pragma unroll
    for (int it = 0; it < 8; it++) {
        int s = tid + it * 256;
        int row = s >> 4, q = s & 15;
        cpa16(sA + row * GROW + q * 16, A16 + (size_t)(m0 + row) * K + q * 8);
    }
    asm volatile("cp.async.commit_group;" ::: "memory");

    // ---- B fill for n-block y into stage stg ----
#define FILLB(y, stg) do {                                                      \
        const uint32_t s0 = sB0 + (stg) * G_TILE;                               \
        const int nb0 = (y) * 128;                                              \
        _Pragma("unroll")                                                       \
        for (int it = 0; it < 8; it++) {                                        \
            int s = tid + it * 256;                                             \
            int row = s >> 4, q = s & 15;                                       \
            cpa16(s0 + row * GROW + q * 16,                                     \
                  B16 + (size_t)(nb0 + row) * K + q * 8);                       \
        }                                                                       \
        asm volatile("cp.async.commit_group;" ::: "memory");                    \
    } while (0)

    FILLB(0, 0);

    for (int y = 0; y < 3; y++) {
        if (y < 2) {
            FILLB(y + 1, (y + 1) & 1);
            asm volatile("cp.async.wait_group 1;" ::: "memory");
        } else {
            asm volatile("cp.async.wait_group 0;" ::: "memory");
        }
        __syncthreads();

        const uint32_t sB = sB0 + (y & 1) * G_TILE;
        const int n0 = y * 128;

        float acc[2][8][4];
#pragma unroll
        for (int i = 0; i < 2; i++)
#pragma unroll
            for (int j = 0; j < 8; j++)
#pragma unroll
                for (int t = 0; t < 4; t++) acc[i][j][t] = 0.f;

#pragma unroll
        for (int ks = 0; ks < 8; ks++) {     // K=128, 8 ksteps of 16
            uint32_t af[2][4];
            {
                int rr = lane & 15;
                int c8 = lane >> 4;
                uint32_t off = (uint32_t)((warp_m * 32 + rr) * GROW + (ks * 16 + c8 * 8) * 2);
                ldsm4(af[0], sA + off);
                ldsm4(af[1], sA + off + 16 * GROW);
            }
            uint32_t bf[8][2];
            {
                int sub = lane >> 3, wi = lane & 7;
                int n_off = (sub >> 1) * 8 + wi;
                int k_off = ks * 16 + (sub & 1) * 8;
                uint32_t base = (uint32_t)((warp_n * 64 + n_off) * GROW + k_off * 2);
#pragma unroll
                for (int jj = 0; jj < 4; jj++) {
                    uint32_t r4[4];
                    ldsm4(r4, sB + base + jj * 16 * GROW);
                    bf[2 * jj][0] = r4[0]; bf[2 * jj][1] = r4[1];
                    bf[2 * jj + 1][0] = r4[2]; bf[2 * jj + 1][1] = r4[3];
                }
            }
#pragma unroll
            for (int mi = 0; mi < 2; mi++)
#pragma unroll
                for (int j = 0; j < 8; j++)
                    mma_f16(acc[mi][j], af[mi], bf[j]);
        }
        __syncthreads();   // done reading stage before next FILLB overwrites it

        // epilogue for this n-block
#pragma unroll
        for (int mi = 0; mi < 2; mi++) {
            int gr = m0 + warp_m * 32 + mi * 16 + (lane >> 2);
#pragma unroll
            for (int j = 0; j < 8; j++) {
                int gc = n0 + warp_n * 64 + j * 8 + 2 * (lane & 3);
                float bb0 = bias[gc], bb1 = bias[gc + 1];
#pragma unroll
                for (int half = 0; half < 2; half++) {
                    int row = gr + half * 8;
                    if (row >= M) continue;
                    __half2 hv = __floats2half2_rn(acc[mi][j][2 * half + 0] + bb0,
                                                   acc[mi][j][2 * half + 1] + bb1);
                    *reinterpret_cast<__half2*>(C16 + (size_t)row * G3 + gc) = hv;
                }
            }
        }
    }
#undef FILLB
}

// ------------------- CSR build -------------------
__global__ void hist_k(const int* e0, const int* e1, const int* e2, int E, int N)
{
    int e = blockIdx.x * blockDim.x + threadIdx.x;
    if (e >= 3 * E) return;
    int r = e / E, le = e - r * E;
    const int* ei = (r == 0) ? e0 : (r == 1) ? e1 : e2;
    atomicAdd(&g_CNT[r * N + ei[E + le]], 1);
}
__global__ void scan1_k(int ntot)
{
    __shared__ int sh[1024];
    int tid = threadIdx.x;
    int gid = blockIdx.x * 1024 + tid;
    int v = 0;
    if (gid < ntot) {
        v = g_CNT[gid];
        g_CNT[gid] = 0;      // re-zero for next graph replay
    }
    sh[tid] = v;
    __syncthreads();
    for (int o = 1; o < 1024; o <<= 1) {
        int t = (tid >= o) ? sh[tid - o] : 0;
        __syncthreads();
        sh[tid] += t;
        __syncthreads();
    }
    if (gid < ntot) g_OFF[gid] = sh[tid] - v;
    if (tid == 1023) g_BSUM[blockIdx.x] = sh[1023];
}
__global__ void scan3_k(int ntot)
{
    __shared__ int base;
    if (threadIdx.x == 0) {
        int run = 0;
#pragma unroll 8
        for (int i = 0; i < blockIdx.x; i++) run += g_BSUM[i];
        base = run;
    }
    __syncthreads();
    int gid = blockIdx.x * 1024 + threadIdx.x;
    if (gid >= ntot) return;
    int o = g_OFF[gid] + base;
    g_OFF[gid] = o;
    g_CUR[gid] = o;
}
__global__ void scatter_idx_k(const int* e0, const int* e1, const int* e2, int E, int N)
{
    int e = blockIdx.x * blockDim.x + threadIdx.x;
    if (e >= 3 * E) return;
    int r = e / E, le = e - r * E;
    const int* ei = (r == 0) ? e0 : (r == 1) ? e1 : e2;
    int si = ei[le];
    int ti = ei[E + le];
    int pos = atomicAdd(&g_CUR[r * N + ti], 1);
    g_SRC[pos] = si;
}

// ---------- gather aggregation: single-pass (num + den together) ----------
__global__ void gather_k(int N, int Etot)
{
    int gw   = (blockIdx.x * blockDim.x + threadIdx.x) >> 5;
    int lane = threadIdx.x & 31;
    if (gw >= 3 * N) return;
    int r = gw / N, ti = gw - r * N;
    int idx = r * N + ti;
    int s = g_OFF[idx];
    int e = (idx + 1 < 3 * N) ? g_OFF[idx + 1] : Etot;
    uint2* dst16 = reinterpret_cast<uint2*>(g_AG16[r] + (size_t)ti * HH + lane * 4);
    float4 acc = make_float4(0.f, 0.f, 0.f, 0.f);
    if (s < e) {
        float at = g_AT[r][ti];
        float den = 0.f;
        for (int base = s; base < e; base += 32) {
            int k = base + lane;
            int si = 0;
            float ex = 0.f;
            if (k < e) {
                si = g_SRC[k];
                float l = g_AS[r][si] + at;
                l = (l > 0.f) ? l : 0.2f * l;
                ex = expf(l);
                den += ex;
            }
            int cnt = min(32, e - base);
            for (int j = 0; j < cnt; j++) {
                float exj = __shfl_sync(0xffffffffu, ex, j);
                int   sij = __shfl_sync(0xffffffffu, si, j);
                uint2 p = *reinterpret_cast<const uint2*>(
                    g_HS16[r] + (size_t)sij * HH + lane * 4);
                float4 v = unpack4h(p);
                acc.x += exj * v.x;
                acc.y += exj * v.y;
                acc.z += exj * v.z;
                acc.w += exj * v.w;
            }
        }
#pragma unroll
        for (int o = 16; o; o >>= 1) den += __shfl_xor_sync(0xffffffffu, den, o);
        float inv = 1.f / (den + 1e-16f);
        acc.x *= inv; acc.y *= inv; acc.z *= inv; acc.w *= inv;
    }
    *dst16 = pack4h(acc);
}

// ------------------- pointwise -------------------
__global__ void alpha_all(const float* q0, const float* q1, const float* q2, int n)
{
    int gw = (blockIdx.x * blockDim.x + threadIdx.x) >> 5;
    int lane = threadIdx.x & 31;
    if (gw >= 6 * n) return;
    int sel = gw / n, node = gw - sel * n;
    int r = sel >> 1, which = sel & 1;
    const float* qs[3] = {q0, q1, q2};
    const __half* feat = which ? g_HT16[r] : g_HS16[r];
    const float* q = qs[r] + which * HH;
    uint2 p = *reinterpret_cast<const uint2*>(feat + (size_t)node * HH + lane * 4);
    float4 a = unpack4h(p);
    float4 b = *reinterpret_cast<const float4*>(q + lane * 4);
    float s = a.x * b.x + a.y * b.y + a.z * b.z + a.w * b.w;
#pragma unroll
    for (int o = 16; o; o >>= 1) s += __shfl_xor_sync(0xffffffffu, s, o);
    if (lane == 0) {
        if (which) g_AT[r][node] = s;
        else       g_AS[r][node] = s;
    }
}

// ------- fused GRU combine + final outputs: one warp per node -------
__global__ void gru_final_k(float* __restrict__ out, const float* __restrict__ g, int n)
{
    int node = (blockIdx.x * blockDim.x + threadIdx.x) >> 5;
    int lane = threadIdx.x & 31;
    if (node >= n) return;
    int h4 = lane * 4;

    float hout[3][4];
#pragma unroll
    for (int r = 0; r < 3; r++) {
        const __half* gi = g_GI16[r] + (size_t)node * G3;
        const __half* gh = g_GH16[r] + (size_t)node * G3;
        float4 gir = unpack4h(*reinterpret_cast<const uint2*>(gi + h4));
        float4 giz = unpack4h(*reinterpret_cast<const uint2*>(gi + HH + h4));
        float4 gin = unpack4h(*reinterpret_cast<const uint2*>(gi + 2 * HH + h4));
        float4 ghr = unpack4h(*reinterpret_cast<const uint2*>(gh + h4));
        float4 ghz = unpack4h(*reinterpret_cast<const uint2*>(gh + HH + h4));
        float4 ghn = unpack4h(*reinterpret_cast<const uint2*>(gh + 2 * HH + h4));
        float4 a = unpack4h(*reinterpret_cast<const uint2*>(
            g_AG16[r] + (size_t)node * HH + h4));
        float gi_r[4] = {gir.x, gir.y, gir.z, gir.w};
        float gi_z[4] = {giz.x, giz.y, giz.z, giz.w};
        float gi_n[4] = {gin.x, gin.y, gin.z, gin.w};
        float gh_r[4] = {ghr.x, ghr.y, ghr.z, ghr.w};
        float gh_z[4] = {ghz.x, ghz.y, ghz.z, ghz.w};
        float gh_n[4] = {ghn.x, ghn.y, ghn.z, ghn.w};
        float av[4]   = {a.x, a.y, a.z, a.w};
#pragma unroll
        for (int t = 0; t < 4; t++) {
            float rr = 1.f / (1.f + expf(-(gi_r[t] + gh_r[t])));
            float zz = 1.f / (1.f + expf(-(gi_z[t] + gh_z[t])));
            float gg = tanhf(gi_n[t] + rr * gh_n[t]);
            hout[r][t] = (1.f - zz) * gg + zz * av[t];
        }
    }

    size_t off = (size_t)node * HH + h4;
    float4 u;
    u.x = fmaxf(hout[1][0], 0.f);
    u.y = fmaxf(hout[1][1], 0.f);
    u.z = fmaxf(hout[1][2], 0.f);
    u.w = fmaxf(hout[1][3], 0.f);
    *reinterpret_cast<float4*>(out + off) = u;

    float4 gv = *reinterpret_cast<const float4*>(g + h4);
    float gvv[4] = {gv.x, gv.y, gv.z, gv.w};
    float d0 = 0.f, d1 = 0.f;
#pragma unroll
    for (int t = 0; t < 4; t++) {
        d0 += hout[0][t] * gvv[t];
        d1 += hout[2][t] * gvv[t];
    }
#pragma unroll
    for (int o = 16; o; o >>= 1) {
        d0 += __shfl_xor_sync(0xffffffffu, d0, o);
        d1 += __shfl_xor_sync(0xffffffffu, d1, o);
    }
    float a0 = expf(d0), a1 = expf(d1);
    float inv = 1.f / (a0 + a1);
    float w0 = a0 * inv, w1 = a1 * inv;
    float4 o4;
    o4.x = fmaxf(w0 * hout[0][0] + w1 * hout[2][0], 0.f);
    o4.y = fmaxf(w0 * hout[0][1] + w1 * hout[2][1], 0.f);
    o4.z = fmaxf(w0 * hout[0][2] + w1 * hout[2][2], 0.f);
    o4.w = fmaxf(w0 * hout[0][3] + w1 * hout[2][3], 0.f);
    *reinterpret_cast<float4*>(out + (size_t)n * HH + off) = o4;
}

// ---------------------------------------------------------------
extern "C" void kernel_launch(void* const* d_in, const int* in_sizes, int n_in,
                              void* d_out, int out_size)
{
    const float* x_user = (const float*)d_in[0];
    const float* x_item = (const float*)d_in[1];
    const int*   ei_ui  = (const int*)d_in[2];
    const int*   ei_iu  = (const int*)d_in[3];
    const int*   ei_ii  = (const int*)d_in[4];

    int N = in_sizes[0] / DD;
    int E = in_sizes[2] / 2;
    if (N > NMAX) N = NMAX;
    if (E > EMAX) E = EMAX;

    float* out = (float*)d_out;

    cudaFuncSetAttribute(hsht_gemm, cudaFuncAttributeMaxDynamicSharedMemorySize, SMEMSZ);
    cudaFuncSetAttribute(gru_gemm,  cudaFuncAttributeMaxDynamicSharedMemorySize, GSMEM);

    // prep
    int x4 = (N * DD) / 4;
    split_x_k<<<(2 * x4 + 255) / 256, 256>>>(x_user, x_item, x4);
    prep_w_all<<<(WT_TOT + WG_TOT + 255) / 256, 256>>>(
        (const float*)d_in[5],  (const float*)d_in[6],
        (const float*)d_in[12], (const float*)d_in[13],
        (const float*)d_in[19], (const float*)d_in[20],
        (const float*)d_in[8],  (const float*)d_in[9],
        (const float*)d_in[15], (const float*)d_in[16],
        (const float*)d_in[22], (const float*)d_in[23]);

    // CSR build (g_CNT zeroed by scan1 of previous replay / static init)
    int ntot = 3 * N;
    hist_k<<<(3 * E + 255) / 256, 256>>>(ei_ui, ei_iu, ei_ii, E, N);
    int nb = (ntot + 1023) / 1024;
    scan1_k<<<nb, 1024>>>(ntot);
    scan3_k<<<nb, 1024>>>(ntot);
    scatter_idx_k<<<(3 * E + 255) / 256, 256>>>(ei_ui, ei_iu, ei_ii, E, N);

    const int mb = NPAD / 128;   // 392

    hsht_gemm<<<dim3(mb, 1, 6), 256, SMEMSZ>>>(N);

    int aBlocks = (int)(((long long)6 * N * 32 + 255) / 256);
    alpha_all<<<aBlocks, 256>>>((const float*)d_in[7], (const float*)d_in[14],
                                (const float*)d_in[21], N);

    gather_k<<<(int)(((long long)3 * N * 32 + 255) / 256), 256>>>(N, 3 * E);

    gru_gemm<<<dim3(mb, 1, 6), 256, GSMEM>>>(
        N,
        (const float*)d_in[10], (const float*)d_in[11],
        (const float*)d_in[17], (const float*)d_in[18],
        (const float*)d_in[24], (const float*)d_in[25]);

    gru_final_k<<<(N * 32 + 255) / 256, 256>>>(out, (const float*)d_in[27], N);
}

// round 15
// speedup vs baseline: 3.8469x; 1.0447x over previous
#include <cuda_runtime.h>
#include <cuda_fp16.h>
#include <math.h>
#include <cstdint>

#define NMAX 50000
#define NPAD 50176   // 392*128
#define EMAX 400000
#define DD   256
#define HH   128
#define G3   384
#define SROW 80                  // smem bytes per 32-halfword row (64B + 16B pad)
#define TILE_B (128 * SROW)      // 10240
#define HSTAGE (2 * TILE_B)      // 20480 (hsht: A16, B16)
#define SMEMSZ (2 * HSTAGE)      // 40960
#define GROW   272               // 128*2 + 16 pad
#define G_TILE (128 * GROW)      // 34816
#define GSMEM  (3 * G_TILE)      // 104448 (A + 2 B stages)

// ------------------- scratch -------------------
__device__ __align__(16) __half g_GI16[3][NPAD*G3];
__device__ __align__(16) __half g_GH16[3][NPAD*G3];
__device__ __align__(16) float  g_AS [3][NMAX];
__device__ __align__(16) float  g_AT [3][NMAX];
__device__ __align__(16) __half g_XU16[NPAD*DD], g_XI16[NPAD*DD];
__device__ __align__(16) __half g_HS16[3][NPAD*HH];
__device__ __align__(16) __half g_HT16[3][NPAD*HH];
__device__ __align__(16) __half g_AG16[3][NPAD*HH];
__device__ __align__(16) __half g_WT16[6][128*DD];
__device__ __align__(16) __half g_WG16[6][G3*HH];
// CSR (g_CNT zero at load; scan1 re-zeroes each run)
__device__ int g_CNT [3*NMAX];
__device__ int g_OFF [3*NMAX];
__device__ int g_CUR [3*NMAX];
__device__ int g_SRC [3*EMAX];
__device__ int g_BSUM[256];

// ------------------- PTX helpers -------------------
__device__ __forceinline__ uint32_t smem_u32(const void* p) {
    uint32_t a;
    asm("{ .reg .u64 t; cvta.to.shared.u64 t, %1; cvt.u32.u64 %0, t; }" : "=r"(a) : "l"(p));
    return a;
}
__device__ __forceinline__ void ldsm4(uint32_t* r, uint32_t addr) {
    asm volatile("ldmatrix.sync.aligned.m8n8.x4.shared.b16 {%0,%1,%2,%3}, [%4];"
                 : "=r"(r[0]), "=r"(r[1]), "=r"(r[2]), "=r"(r[3]) : "r"(addr));
}
__device__ __forceinline__ void mma_f16(float* d, const uint32_t* a, const uint32_t* b) {
    asm volatile(
        "mma.sync.aligned.m16n8k16.row.col.f32.f16.f16.f32 "
        "{%0,%1,%2,%3}, {%4,%5,%6,%7}, {%8,%9}, {%0,%1,%2,%3};"
        : "+f"(d[0]), "+f"(d[1]), "+f"(d[2]), "+f"(d[3])
        : "r"(a[0]), "r"(a[1]), "r"(a[2]), "r"(a[3]), "r"(b[0]), "r"(b[1]));
}
__device__ __forceinline__ void cpa16(uint32_t dst, const void* src) {
    asm volatile("cp.async.cg.shared.global [%0], [%1], 16;" :: "r"(dst), "l"(src));
}
__device__ __forceinline__ uint2 pack4h(float4 v) {
    __half h0 = __float2half_rn(v.x), h1 = __float2half_rn(v.y);
    __half h2 = __float2half_rn(v.z), h3 = __float2half_rn(v.w);
    uint2 p;
    p.x = ((uint32_t)__half_as_ushort(h1) << 16) | __half_as_ushort(h0);
    p.y = ((uint32_t)__half_as_ushort(h3) << 16) | __half_as_ushort(h2);
    return p;
}
__device__ __forceinline__ float4 unpack4h(uint2 p) {
    __half2 a = *reinterpret_cast<__half2*>(&p.x);
    __half2 b = *reinterpret_cast<__half2*>(&p.y);
    float2 fa = __half22float2(a);
    float2 fb = __half22float2(b);
    return make_float4(fa.x, fa.y, fb.x, fb.y);
}

// ------------- fused prep: x split + both weight preps -------------
#define X4TOT  (NMAX * DD / 4)              // per-tensor float4 count (N=NMAX assumed cap)
#define WT_TOT (6 * 128 * 256)
#define WG_TOT (6 * G3 * HH)
__global__ void prep_all(
    const float* xu, const float* xi, int n4,
    const float* a0, const float* a1, const float* a2,
    const float* a3, const float* a4, const float* a5,
    const float* g0, const float* g1, const float* g2,
    const float* g3, const float* g4, const float* g5)
{
    int i = blockIdx.x * blockDim.x + threadIdx.x;
    if (i < 2 * n4) {
        const float* src = (i < n4) ? xu : xi;
        int j = (i < n4) ? i : i - n4;
        float4 v = reinterpret_cast<const float4*>(src)[j];
        uint2 p = pack4h(v);
        if (i < n4) reinterpret_cast<uint2*>(g_XU16)[j] = p;
        else        reinterpret_cast<uint2*>(g_XI16)[j] = p;
        return;
    }
    int t = i - 2 * n4;
    if (t < WT_TOT) {
        const float* ws[6] = {a0, a1, a2, a3, a4, a5};
        int z = t >> 15, j = t & 32767;
        int n = j >> 8, k = j & 255;
        g_WT16[z][j] = __float2half_rn(ws[z][k * 128 + n]);
    } else if (t < WT_TOT + WG_TOT) {
        const float* ws[6] = {g0, g1, g2, g3, g4, g5};
        int u = t - WT_TOT;
        int z = u / (G3 * HH), j = u % (G3 * HH);
        g_WG16[z][j] = __float2half_rn(ws[z][j]);
    }
}

// -------- hsht GEMM: fp16, BK=32, 2-stage, fused alpha --------
__global__ void __launch_bounds__(256, 2) hsht_gemm(
    int M, const float* q0, const float* q1, const float* q2)
{
    extern __shared__ char smem[];
    const int z = blockIdx.z, r = z >> 1, which = z & 1;
    const __half* AT6[6] = {g_XU16, g_XI16, g_XI16, g_XU16, g_XI16, g_XI16};
    const __half* A16 = AT6[z];
    const __half* B16 = g_WT16[z];
    __half* C16 = which ? g_HT16[r] : g_HS16[r];
    float* alpha = which ? g_AT[r] : g_AS[r];
    const float* qs3[3] = {q0, q1, q2};
    const float* q = qs3[r] + which * HH;
    const int K = DD, Nc = HH;
    const int m0 = blockIdx.x * 128, n0 = 0;

    const uint32_t sb = smem_u32(smem);
    const int tid  = threadIdx.x;
    const int wid  = tid >> 5;
    const int lane = tid & 31;
    const int warp_m = wid & 3;
    const int warp_n = wid >> 2;

    float acc[2][8][4];
#pragma unroll
    for (int i = 0; i < 2; i++)
#pragma unroll
        for (int j = 0; j < 8; j++)
#pragma unroll
            for (int t = 0; t < 4; t++) acc[i][j][t] = 0.f;

    const int nchunks = K >> 5;   // 8

#define FILL(kc, stg) do {                                                      \
        const int k0f = (kc) << 5;                                              \
        const uint32_t s0 = sb + (stg) * HSTAGE;                                \
        _Pragma("unroll")                                                       \
        for (int it = 0; it < 4; it++) {                                        \
            int s = tid + it * 256;                                             \
            int tile = s >> 9, w = s & 511, row = w >> 2, qq = w & 3;           \
            uint32_t dst = s0 + tile * TILE_B + row * SROW + qq * 16;           \
            const __half* src = tile ? B16 : A16;                               \
            size_t off = tile ? ((size_t)(n0 + row) * K + k0f + qq * 8)         \
                              : ((size_t)(m0 + row) * K + k0f + qq * 8);        \
            cpa16(dst, src + off);                                              \
        }                                                                       \
        asm volatile("cp.async.commit_group;" ::: "memory");                    \
    } while (0)

    FILL(0, 0);

    for (int kc = 0; kc < nchunks; kc++) {
        if (kc + 1 < nchunks) {
            FILL(kc + 1, (kc + 1) & 1);
            asm volatile("cp.async.wait_group 1;" ::: "memory");
        } else {
            asm volatile("cp.async.wait_group 0;" ::: "memory");
        }
        __syncthreads();

        const uint32_t s0 = sb + (kc & 1) * HSTAGE;
        const uint32_t sA = s0;
        const uint32_t sB = s0 + TILE_B;

#pragma unroll
        for (int ks = 0; ks < 2; ks++) {
            uint32_t af[2][4];
            {
                int rr = lane & 15;
                int c8 = lane >> 4;
                uint32_t off = (uint32_t)((warp_m * 32 + rr) * SROW + (ks * 16 + c8 * 8) * 2);
                ldsm4(af[0], sA + off);
                ldsm4(af[1], sA + off + 16 * SROW);
            }
            uint32_t bf[8][2];
            {
                int sub = lane >> 3, wi = lane & 7;
                int n_off = (sub >> 1) * 8 + wi;
                int k_off = ks * 16 + (sub & 1) * 8;
                uint32_t base = (uint32_t)((warp_n * 64 + n_off) * SROW + k_off * 2);
#pragma unroll
                for (int jj = 0; jj < 4; jj++) {
                    uint32_t r4[4];
                    ldsm4(r4, sB + base + jj * 16 * SROW);
                    bf[2 * jj][0] = r4[0]; bf[2 * jj][1] = r4[1];
                    bf[2 * jj + 1][0] = r4[2]; bf[2 * jj + 1][1] = r4[3];
                }
            }
#pragma unroll
            for (int mi = 0; mi < 2; mi++)
#pragma unroll
                for (int j = 0; j < 8; j++)
                    mma_f16(acc[mi][j], af[mi], bf[j]);
        }
        __syncthreads();
    }
#undef FILL

    // ---- epilogue: store fp16 + fused alpha dot ----
#pragma unroll
    for (int mi = 0; mi < 2; mi++) {
#pragma unroll
        for (int half = 0; half < 2; half++) {
            int row = m0 + warp_m * 32 + mi * 16 + half * 8 + (lane >> 2);
            float dot = 0.f;
#pragma unroll
            for (int j = 0; j < 8; j++) {
                int gc = n0 + warp_n * 64 + j * 8 + 2 * (lane & 3);
                float v0 = acc[mi][j][2 * half + 0];
                float v1 = acc[mi][j][2 * half + 1];
                if (row < M) {
                    __half2 hv = __floats2half2_rn(v0, v1);
                    *reinterpret_cast<__half2*>(C16 + (size_t)row * Nc + gc) = hv;
                    dot += v0 * q[gc] + v1 * q[gc + 1];
                }
            }
            // reduce over the 4 lanes of the quad owning this row
            dot += __shfl_xor_sync(0xffffffffu, dot, 1);
            dot += __shfl_xor_sync(0xffffffffu, dot, 2);
            if ((lane & 3) == 0 && row < M)
                atomicAdd(alpha + row, dot);
        }
    }
}

// ---------- gru GEMM: A resident, loop 3 n-blocks with B 2-stage ----------
__global__ void __launch_bounds__(256, 2) gru_gemm(
    int M,
    const float* b0, const float* b1, const float* b2,
    const float* b3, const float* b4, const float* b5)
{
    extern __shared__ char smem[];
    const int z = blockIdx.z, r = z >> 1, which = z & 1;
    const float* biases[6] = {b0, b1, b2, b3, b4, b5};
    const __half* A16 = which ? g_AG16[r] : g_HT16[r];
    const __half* B16 = g_WG16[z];
    const float* bias = biases[z];
    __half* C16 = which ? g_GH16[r] : g_GI16[r];
    const int K = HH;
    const int m0 = blockIdx.x * 128;

    const uint32_t sb = smem_u32(smem);
    const uint32_t sA  = sb;
    const uint32_t sB0 = sb + G_TILE;
    const int tid  = threadIdx.x;
    const int wid  = tid >> 5;
    const int lane = tid & 31;
    const int warp_m = wid & 3;
    const int warp_n = wid >> 2;

#pragma unroll
    for (int it = 0; it < 8; it++) {
        int s = tid + it * 256;
        int row = s >> 4, q = s & 15;
        cpa16(sA + row * GROW + q * 16, A16 + (size_t)(m0 + row) * K + q * 8);
    }
    asm volatile("cp.async.commit_group;" ::: "memory");

#define FILLB(y, stg) do {                                                      \
        const uint32_t s0 = sB0 + (stg) * G_TILE;                               \
        const int nb0 = (y) * 128;                                              \
        _Pragma("unroll")                                                       \
        for (int it = 0; it < 8; it++) {                                        \
            int s = tid + it * 256;                                             \
            int row = s >> 4, q = s & 15;                                       \
            cpa16(s0 + row * GROW + q * 16,                                     \
                  B16 + (size_t)(nb0 + row) * K + q * 8);                       \
        }                                                                       \
        asm volatile("cp.async.commit_group;" ::: "memory");                    \
    } while (0)

    FILLB(0, 0);

    for (int y = 0; y < 3; y++) {
        if (y < 2) {
            FILLB(y + 1, (y + 1) & 1);
            asm volatile("cp.async.wait_group 1;" ::: "memory");
        } else {
            asm volatile("cp.async.wait_group 0;" ::: "memory");
        }
        __syncthreads();

        const uint32_t sB = sB0 + (y & 1) * G_TILE;
        const int n0 = y * 128;

        float acc[2][8][4];
#pragma unroll
        for (int i = 0; i < 2; i++)
#pragma unroll
            for (int j = 0; j < 8; j++)
#pragma unroll
                for (int t = 0; t < 4; t++) acc[i][j][t] = 0.f;

#pragma unroll
        for (int ks = 0; ks < 8; ks++) {
            uint32_t af[2][4];
            {
                int rr = lane & 15;
                int c8 = lane >> 4;
                uint32_t off = (uint32_t)((warp_m * 32 + rr) * GROW + (ks * 16 + c8 * 8) * 2);
                ldsm4(af[0], sA + off);
                ldsm4(af[1], sA + off + 16 * GROW);
            }
            uint32_t bf[8][2];
            {
                int sub = lane >> 3, wi = lane & 7;
                int n_off = (sub >> 1) * 8 + wi;
                int k_off = ks * 16 + (sub & 1) * 8;
                uint32_t base = (uint32_t)((warp_n * 64 + n_off) * GROW + k_off * 2);
#pragma unroll
                for (int jj = 0; jj < 4; jj++) {
                    uint32_t r4[4];
                    ldsm4(r4, sB + base + jj * 16 * GROW);
                    bf[2 * jj][0] = r4[0]; bf[2 * jj][1] = r4[1];
                    bf[2 * jj + 1][0] = r4[2]; bf[2 * jj + 1][1] = r4[3];
                }
            }
#pragma unroll
            for (int mi = 0; mi < 2; mi++)
#pragma unroll
                for (int j = 0; j < 8; j++)
                    mma_f16(acc[mi][j], af[mi], bf[j]);
        }
        __syncthreads();

#pragma unroll
        for (int mi = 0; mi < 2; mi++) {
            int gr = m0 + warp_m * 32 + mi * 16 + (lane >> 2);
#pragma unroll
            for (int j = 0; j < 8; j++) {
                int gc = n0 + warp_n * 64 + j * 8 + 2 * (lane & 3);
                float bb0 = bias[gc], bb1 = bias[gc + 1];
#pragma unroll
                for (int half = 0; half < 2; half++) {
                    int row = gr + half * 8;
                    if (row >= M) continue;
                    __half2 hv = __floats2half2_rn(acc[mi][j][2 * half + 0] + bb0,
                                                   acc[mi][j][2 * half + 1] + bb1);
                    *reinterpret_cast<__half2*>(C16 + (size_t)row * G3 + gc) = hv;
                }
            }
        }
    }
#undef FILLB
}

// ------------------- CSR build -------------------
__global__ void hist_k(const int* e0, const int* e1, const int* e2, int E, int N)
{
    int e = blockIdx.x * blockDim.x + threadIdx.x;
    if (e >= 3 * E) return;
    int r = e / E, le = e - r * E;
    const int* ei = (r == 0) ? e0 : (r == 1) ? e1 : e2;
    atomicAdd(&g_CNT[r * N + ei[E + le]], 1);
}
__global__ void scan1_k(int ntot)
{
    __shared__ int sh[1024];
    int tid = threadIdx.x;
    int gid = blockIdx.x * 1024 + tid;
    int v = 0;
    if (gid < ntot) {
        v = g_CNT[gid];
        g_CNT[gid] = 0;
    }
    sh[tid] = v;
    __syncthreads();
    for (int o = 1; o < 1024; o <<= 1) {
        int t = (tid >= o) ? sh[tid - o] : 0;
        __syncthreads();
        sh[tid] += t;
        __syncthreads();
    }
    if (gid < ntot) g_OFF[gid] = sh[tid] - v;
    if (tid == 1023) g_BSUM[blockIdx.x] = sh[1023];
}
// scan3: finalize OFF/CUR and zero AS/AT for the fused-alpha atomics
__global__ void scan3_k(int ntot)
{
    __shared__ int base;
    if (threadIdx.x == 0) {
        int run = 0;
#pragma unroll 8
        for (int i = 0; i < blockIdx.x; i++) run += g_BSUM[i];
        base = run;
    }
    __syncthreads();
    int gid = blockIdx.x * 1024 + threadIdx.x;
    if (gid >= ntot) return;
    int o = g_OFF[gid] + base;
    g_OFF[gid] = o;
    g_CUR[gid] = o;
    (&g_AS[0][0])[gid] = 0.f;
    (&g_AT[0][0])[gid] = 0.f;
}
__global__ void scatter_idx_k(const int* e0, const int* e1, const int* e2, int E, int N)
{
    int e = blockIdx.x * blockDim.x + threadIdx.x;
    if (e >= 3 * E) return;
    int r = e / E, le = e - r * E;
    const int* ei = (r == 0) ? e0 : (r == 1) ? e1 : e2;
    int si = ei[le];
    int ti = ei[E + le];
    int pos = atomicAdd(&g_CUR[r * N + ti], 1);
    g_SRC[pos] = si;
}

// ---------- gather aggregation: single-pass ----------
__global__ void gather_k(int N, int Etot)
{
    int gw   = (blockIdx.x * blockDim.x + threadIdx.x) >> 5;
    int lane = threadIdx.x & 31;
    if (gw >= 3 * N) return;
    int r = gw / N, ti = gw - r * N;
    int idx = r * N + ti;
    int s = g_OFF[idx];
    int e = (idx + 1 < 3 * N) ? g_OFF[idx + 1] : Etot;
    uint2* dst16 = reinterpret_cast<uint2*>(g_AG16[r] + (size_t)ti * HH + lane * 4);
    float4 acc = make_float4(0.f, 0.f, 0.f, 0.f);
    if (s < e) {
        float at = g_AT[r][ti];
        float den = 0.f;
        for (int base = s; base < e; base += 32) {
            int k = base + lane;
            int si = 0;
            float ex = 0.f;
            if (k < e) {
                si = g_SRC[k];
                float l = g_AS[r][si] + at;
                l = (l > 0.f) ? l : 0.2f * l;
                ex = expf(l);
                den += ex;
            }
            int cnt = min(32, e - base);
            for (int j = 0; j < cnt; j++) {
                float exj = __shfl_sync(0xffffffffu, ex, j);
                int   sij = __shfl_sync(0xffffffffu, si, j);
                uint2 p = *reinterpret_cast<const uint2*>(
                    g_HS16[r] + (size_t)sij * HH + lane * 4);
                float4 v = unpack4h(p);
                acc.x += exj * v.x;
                acc.y += exj * v.y;
                acc.z += exj * v.z;
                acc.w += exj * v.w;
            }
        }
#pragma unroll
        for (int o = 16; o; o >>= 1) den += __shfl_xor_sync(0xffffffffu, den, o);
        float inv = 1.f / (den + 1e-16f);
        acc.x *= inv; acc.y *= inv; acc.z *= inv; acc.w *= inv;
    }
    *dst16 = pack4h(acc);
}

// ------- fused GRU combine + final outputs -------
__global__ void gru_final_k(float* __restrict__ out, const float* __restrict__ g, int n)
{
    int node = (blockIdx.x * blockDim.x + threadIdx.x) >> 5;
    int lane = threadIdx.x & 31;
    if (node >= n) return;
    int h4 = lane * 4;

    float hout[3][4];
#pragma unroll
    for (int r = 0; r < 3; r++) {
        const __half* gi = g_GI16[r] + (size_t)node * G3;
        const __half* gh = g_GH16[r] + (size_t)node * G3;
        float4 gir = unpack4h(*reinterpret_cast<const uint2*>(gi + h4));
        float4 giz = unpack4h(*reinterpret_cast<const uint2*>(gi + HH + h4));
        float4 gin = unpack4h(*reinterpret_cast<const uint2*>(gi + 2 * HH + h4));
        float4 ghr = unpack4h(*reinterpret_cast<const uint2*>(gh + h4));
        float4 ghz = unpack4h(*reinterpret_cast<const uint2*>(gh + HH + h4));
        float4 ghn = unpack4h(*reinterpret_cast<const uint2*>(gh + 2 * HH + h4));
        float4 a = unpack4h(*reinterpret_cast<const uint2*>(
            g_AG16[r] + (size_t)node * HH + h4));
        float gi_r[4] = {gir.x, gir.y, gir.z, gir.w};
        float gi_z[4] = {giz.x, giz.y, giz.z, giz.w};
        float gi_n[4] = {gin.x, gin.y, gin.z, gin.w};
        float gh_r[4] = {ghr.x, ghr.y, ghr.z, ghr.w};
        float gh_z[4] = {ghz.x, ghz.y, ghz.z, ghz.w};
        float gh_n[4] = {ghn.x, ghn.y, ghn.z, ghn.w};
        float av[4]   = {a.x, a.y, a.z, a.w};
#pragma unroll
        for (int t = 0; t < 4; t++) {
            float rr = 1.f / (1.f + expf(-(gi_r[t] + gh_r[t])));
            float zz = 1.f / (1.f + expf(-(gi_z[t] + gh_z[t])));
            float gg = tanhf(gi_n[t] + rr * gh_n[t]);
            hout[r][t] = (1.f - zz) * gg + zz * av[t];
        }
    }

    size_t off = (size_t)node * HH + h4;
    float4 u;
    u.x = fmaxf(hout[1][0], 0.f);
    u.y = fmaxf(hout[1][1], 0.f);
    u.z = fmaxf(hout[1][2], 0.f);
    u.w = fmaxf(hout[1][3], 0.f);
    *reinterpret_cast<float4*>(out + off) = u;

    float4 gv = *reinterpret_cast<const float4*>(g + h4);
    float gvv[4] = {gv.x, gv.y, gv.z, gv.w};
    float d0 = 0.f, d1 = 0.f;
#pragma unroll
    for (int t = 0; t < 4; t++) {
        d0 += hout[0][t] * gvv[t];
        d1 += hout[2][t] * gvv[t];
    }
#pragma unroll
    for (int o = 16; o; o >>= 1) {
        d0 += __shfl_xor_sync(0xffffffffu, d0, o);
        d1 += __shfl_xor_sync(0xffffffffu, d1, o);
    }
    float a0 = expf(d0), a1 = expf(d1);
    float inv = 1.f / (a0 + a1);
    float w0 = a0 * inv, w1 = a1 * inv;
    float4 o4;
    o4.x = fmaxf(w0 * hout[0][0] + w1 * hout[2][0], 0.f);
    o4.y = fmaxf(w0 * hout[0][1] + w1 * hout[2][1], 0.f);
    o4.z = fmaxf(w0 * hout[0][2] + w1 * hout[2][2], 0.f);
    o4.w = fmaxf(w0 * hout[0][3] + w1 * hout[2][3], 0.f);
    *reinterpret_cast<float4*>(out + (size_t)n * HH + off) = o4;
}

// ---------------------------------------------------------------
extern "C" void kernel_launch(void* const* d_in, const int* in_sizes, int n_in,
                              void* d_out, int out_size)
{
    const float* x_user = (const float*)d_in[0];
    const float* x_item = (const float*)d_in[1];
    const int*   ei_ui  = (const int*)d_in[2];
    const int*   ei_iu  = (const int*)d_in[3];
    const int*   ei_ii  = (const int*)d_in[4];

    int N = in_sizes[0] / DD;
    int E = in_sizes[2] / 2;
    if (N > NMAX) N = NMAX;
    if (E > EMAX) E = EMAX;

    float* out = (float*)d_out;

    cudaFuncSetAttribute(hsht_gemm, cudaFuncAttributeMaxDynamicSharedMemorySize, SMEMSZ);
    cudaFuncSetAttribute(gru_gemm,  cudaFuncAttributeMaxDynamicSharedMemorySize, GSMEM);

    // fused prep
    int x4 = (N * DD) / 4;
    int prepTot = 2 * x4 + WT_TOT + WG_TOT;
    prep_all<<<(prepTot + 255) / 256, 256>>>(
        x_user, x_item, x4,
        (const float*)d_in[5],  (const float*)d_in[6],
        (const float*)d_in[12], (const float*)d_in[13],
        (const float*)d_in[19], (const float*)d_in[20],
        (const float*)d_in[8],  (const float*)d_in[9],
        (const float*)d_in[15], (const float*)d_in[16],
        (const float*)d_in[22], (const float*)d_in[23]);

    // CSR build (+ AS/AT zeroing in scan3)
    int ntot = 3 * N;
    hist_k<<<(3 * E + 255) / 256, 256>>>(ei_ui, ei_iu, ei_ii, E, N);
    int nb = (ntot + 1023) / 1024;
    scan1_k<<<nb, 1024>>>(ntot);
    scan3_k<<<nb, 1024>>>(ntot);
    scatter_idx_k<<<(3 * E + 255) / 256, 256>>>(ei_ui, ei_iu, ei_ii, E, N);

    const int mb = NPAD / 128;   // 392

    hsht_gemm<<<dim3(mb, 1, 6), 256, SMEMSZ>>>(
        N, (const float*)d_in[7], (const float*)d_in[14], (const float*)d_in[21]);

    gather_k<<<(int)(((long long)3 * N * 32 + 255) / 256), 256>>>(N, 3 * E);

    gru_gemm<<<dim3(mb, 1, 6), 256, GSMEM>>>(
        N,
        (const float*)d_in[10], (const float*)d_in[11],
        (const float*)d_in[17], (const float*)d_in[18],
        (const float*)d_in[24], (const float*)d_in[25]);

    gru_final_k<<<(N * 32 + 255) / 256, 256>>>(out, (const float*)d_in[27], N);
}

// round 16
// speedup vs baseline: 3.9031x; 1.0146x over previous
#include <cuda_runtime.h>
#include <cuda_fp16.h>
#include <math.h>
#include <cstdint>

#define NMAX 50000
#define NPAD 50176   // 392*128
#define EMAX 400000
#define DD   256
#define HH   128
#define G3   384
#define SROW 80                  // smem bytes per 32-halfword row (64B + 16B pad)
// hsht: A resident (128x256 fp16), B 2-stage chunks of 32k
#define AROW   528               // 256*2 + 16 pad
#define A_RES  (128 * AROW)      // 67584
#define HB_TILE (128 * SROW)     // 10240
#define HSMEM  (A_RES + 2 * HB_TILE)  // 88064
// gru: A resident (128x128 fp16), B 2-stage
#define GROW   272               // 128*2 + 16 pad
#define G_TILE (128 * GROW)      // 34816
#define GSMEM  (3 * G_TILE)      // 104448

// ------------------- scratch -------------------
__device__ __align__(16) __half g_GI16[3][NPAD*G3];
__device__ __align__(16) __half g_GH16[3][NPAD*G3];
__device__ __align__(16) float  g_AS [3][NMAX];
__device__ __align__(16) float  g_AT [3][NMAX];
__device__ __align__(16) __half g_XU16[NPAD*DD], g_XI16[NPAD*DD];
__device__ __align__(16) __half g_HS16[3][NPAD*HH];
__device__ __align__(16) __half g_HT16[3][NPAD*HH];
__device__ __align__(16) __half g_AG16[3][NPAD*HH];
__device__ __align__(16) __half g_WT16[6][128*DD];
__device__ __align__(16) __half g_WG16[6][G3*HH];
// CSR (g_CNT zero at load; scan1 re-zeroes each run)
__device__ int g_CNT [3*NMAX];
__device__ int g_OFF [3*NMAX];
__device__ int g_CUR [3*NMAX];
__device__ int g_SRC [3*EMAX];
__device__ int g_BSUM[256];

// ------------------- PTX helpers -------------------
__device__ __forceinline__ uint32_t smem_u32(const void* p) {
    uint32_t a;
    asm("{ .reg .u64 t; cvta.to.shared.u64 t, %1; cvt.u32.u64 %0, t; }" : "=r"(a) : "l"(p));
    return a;
}
__device__ __forceinline__ void ldsm4(uint32_t* r, uint32_t addr) {
    asm volatile("ldmatrix.sync.aligned.m8n8.x4.shared.b16 {%0,%1,%2,%3}, [%4];"
                 : "=r"(r[0]), "=r"(r[1]), "=r"(r[2]), "=r"(r[3]) : "r"(addr));
}
__device__ __forceinline__ void mma_f16(float* d, const uint32_t* a, const uint32_t* b) {
    asm volatile(
        "mma.sync.aligned.m16n8k16.row.col.f32.f16.f16.f32 "
        "{%0,%1,%2,%3}, {%4,%5,%6,%7}, {%8,%9}, {%0,%1,%2,%3};"
        : "+f"(d[0]), "+f"(d[1]), "+f"(d[2]), "+f"(d[3])
        : "r"(a[0]), "r"(a[1]), "r"(a[2]), "r"(a[3]), "r"(b[0]), "r"(b[1]));
}
__device__ __forceinline__ void cpa16(uint32_t dst, const void* src) {
    asm volatile("cp.async.cg.shared.global [%0], [%1], 16;" :: "r"(dst), "l"(src));
}
__device__ __forceinline__ uint2 pack4h(float4 v) {
    __half h0 = __float2half_rn(v.x), h1 = __float2half_rn(v.y);
    __half h2 = __float2half_rn(v.z), h3 = __float2half_rn(v.w);
    uint2 p;
    p.x = ((uint32_t)__half_as_ushort(h1) << 16) | __half_as_ushort(h0);
    p.y = ((uint32_t)__half_as_ushort(h3) << 16) | __half_as_ushort(h2);
    return p;
}
__device__ __forceinline__ float4 unpack4h(uint2 p) {
    __half2 a = *reinterpret_cast<__half2*>(&p.x);
    __half2 b = *reinterpret_cast<__half2*>(&p.y);
    float2 fa = __half22float2(a);
    float2 fb = __half22float2(b);
    return make_float4(fa.x, fa.y, fb.x, fb.y);
}

// ------------- fused prep -------------
#define WT_TOT (6 * 128 * 256)
#define WG_TOT (6 * G3 * HH)
__global__ void prep_all(
    const float* xu, const float* xi, int n4,
    const float* a0, const float* a1, const float* a2,
    const float* a3, const float* a4, const float* a5,
    const float* g0, const float* g1, const float* g2,
    const float* g3, const float* g4, const float* g5)
{
    int i = blockIdx.x * blockDim.x + threadIdx.x;
    if (i < 2 * n4) {
        const float* src = (i < n4) ? xu : xi;
        int j = (i < n4) ? i : i - n4;
        float4 v = reinterpret_cast<const float4*>(src)[j];
        uint2 p = pack4h(v);
        if (i < n4) reinterpret_cast<uint2*>(g_XU16)[j] = p;
        else        reinterpret_cast<uint2*>(g_XI16)[j] = p;
        return;
    }
    int t = i - 2 * n4;
    if (t < WT_TOT) {
        const float* ws[6] = {a0, a1, a2, a3, a4, a5};
        int z = t >> 15, j = t & 32767;
        int n = j >> 8, k = j & 255;
        g_WT16[z][j] = __float2half_rn(ws[z][k * 128 + n]);
    } else if (t < WT_TOT + WG_TOT) {
        const float* ws[6] = {g0, g1, g2, g3, g4, g5};
        int u = t - WT_TOT;
        int z = u / (G3 * HH), j = u % (G3 * HH);
        g_WG16[z][j] = __float2half_rn(ws[z][j]);
    }
}

// -------- hsht GEMM: A resident, 2 weight sets per CTA, fused alpha --------
// grid(392,1,3): g=0 -> A=XU, zs={0,3}; g=1 -> A=XI, zs={1,2}; g=2 -> A=XI, zs={4,5}
__global__ void __launch_bounds__(256, 2) hsht_gemm(
    int M, const float* q0, const float* q1, const float* q2)
{
    extern __shared__ char smem[];
    const int g = blockIdx.z;
    const __half* A16 = (g == 0) ? g_XU16 : g_XI16;
    const int zs0 = (g == 0) ? 0 : (g == 1) ? 1 : 4;
    const int zs1 = (g == 0) ? 3 : (g == 1) ? 2 : 5;
    const float* qs3[3] = {q0, q1, q2};
    const int m0 = blockIdx.x * 128;

    const uint32_t sb = smem_u32(smem);
    const uint32_t sA  = sb;
    const uint32_t sB0 = sb + A_RES;
    const int tid  = threadIdx.x;
    const int wid  = tid >> 5;
    const int lane = tid & 31;
    const int warp_m = wid & 3;
    const int warp_n = wid >> 2;

    // ---- A resident fill: 128 rows x 32 x 16B = 4096 cp.async (16/thread) ----
#pragma unroll
    for (int it = 0; it < 16; it++) {
        int s = tid + it * 256;
        int row = s >> 5, q = s & 31;
        cpa16(sA + row * AROW + q * 16, A16 + (size_t)(m0 + row) * DD + q * 8);
    }
    asm volatile("cp.async.commit_group;" ::: "memory");

    // ---- B chunk fill: chunk c covers ws=c>>3, kc=c&7 ----
#define FILLB(c) do {                                                           \
        const int zc_ = ((c) >> 3) ? zs1 : zs0;                                 \
        const int kc_ = (c) & 7;                                                \
        const uint32_t s0 = sB0 + ((c) & 1) * HB_TILE;                          \
        const __half* B16_ = g_WT16[zc_];                                       \
        _Pragma("unroll")                                                       \
        for (int it = 0; it < 2; it++) {                                        \
            int s = tid + it * 256;                                             \
            int row = s >> 2, q = s & 3;                                        \
            cpa16(s0 + row * SROW + q * 16,                                     \
                  B16_ + (size_t)row * DD + kc_ * 32 + q * 8);                  \
        }                                                                       \
        asm volatile("cp.async.commit_group;" ::: "memory");                    \
    } while (0)

    FILLB(0);

    float acc[2][8][4];
#pragma unroll
    for (int i = 0; i < 2; i++)
#pragma unroll
        for (int j = 0; j < 8; j++)
#pragma unroll
            for (int t = 0; t < 4; t++) acc[i][j][t] = 0.f;

    for (int c = 0; c < 16; c++) {
        if (c < 15) {
            FILLB(c + 1);
            asm volatile("cp.async.wait_group 1;" ::: "memory");
        } else {
            asm volatile("cp.async.wait_group 0;" ::: "memory");
        }
        __syncthreads();

        const int kc = c & 7;
        const uint32_t sB = sB0 + (c & 1) * HB_TILE;

#pragma unroll
        for (int ks = 0; ks < 2; ks++) {
            const int kglob = kc * 32 + ks * 16;
            uint32_t af[2][4];
            {
                int rr = lane & 15;
                int c8 = lane >> 4;
                uint32_t off = (uint32_t)((warp_m * 32 + rr) * AROW + (kglob + c8 * 8) * 2);
                ldsm4(af[0], sA + off);
                ldsm4(af[1], sA + off + 16 * AROW);
            }
            uint32_t bf[8][2];
            {
                int sub = lane >> 3, wi = lane & 7;
                int n_off = (sub >> 1) * 8 + wi;
                int k_off = ks * 16 + (sub & 1) * 8;
                uint32_t base = (uint32_t)((warp_n * 64 + n_off) * SROW + k_off * 2);
#pragma unroll
                for (int jj = 0; jj < 4; jj++) {
                    uint32_t r4[4];
                    ldsm4(r4, sB + base + jj * 16 * SROW);
                    bf[2 * jj][0] = r4[0]; bf[2 * jj][1] = r4[1];
                    bf[2 * jj + 1][0] = r4[2]; bf[2 * jj + 1][1] = r4[3];
                }
            }
#pragma unroll
            for (int mi = 0; mi < 2; mi++)
#pragma unroll
                for (int j = 0; j < 8; j++)
                    mma_f16(acc[mi][j], af[mi], bf[j]);
        }
        __syncthreads();

        if (kc == 7) {
            // ---- epilogue for weight set zc ----
            const int zc = (c >> 3) ? zs1 : zs0;
            const int which = zc & 1, r = zc >> 1;
            __half* C16 = which ? g_HT16[r] : g_HS16[r];
            float* alpha = which ? g_AT[r] : g_AS[r];
            const float* q = qs3[r] + which * HH;
#pragma unroll
            for (int mi = 0; mi < 2; mi++) {
#pragma unroll
                for (int half = 0; half < 2; half++) {
                    int row = m0 + warp_m * 32 + mi * 16 + half * 8 + (lane >> 2);
                    float dot = 0.f;
#pragma unroll
                    for (int j = 0; j < 8; j++) {
                        int gc = warp_n * 64 + j * 8 + 2 * (lane & 3);
                        float v0 = acc[mi][j][2 * half + 0];
                        float v1 = acc[mi][j][2 * half + 1];
                        if (row < M) {
                            __half2 hv = __floats2half2_rn(v0, v1);
                            *reinterpret_cast<__half2*>(C16 + (size_t)row * HH + gc) = hv;
                            dot += v0 * q[gc] + v1 * q[gc + 1];
                        }
                    }
                    dot += __shfl_xor_sync(0xffffffffu, dot, 1);
                    dot += __shfl_xor_sync(0xffffffffu, dot, 2);
                    if ((lane & 3) == 0 && row < M)
                        atomicAdd(alpha + row, dot);
                }
            }
            // reset acc for next weight set
#pragma unroll
            for (int i = 0; i < 2; i++)
#pragma unroll
                for (int j = 0; j < 8; j++)
#pragma unroll
                    for (int t = 0; t < 4; t++) acc[i][j][t] = 0.f;
        }
    }
#undef FILLB
}

// ---------- gru GEMM: A resident, loop 3 n-blocks with B 2-stage ----------
__global__ void __launch_bounds__(256, 2) gru_gemm(
    int M,
    const float* b0, const float* b1, const float* b2,
    const float* b3, const float* b4, const float* b5)
{
    extern __shared__ char smem[];
    const int z = blockIdx.z, r = z >> 1, which = z & 1;
    const float* biases[6] = {b0, b1, b2, b3, b4, b5};
    const __half* A16 = which ? g_AG16[r] : g_HT16[r];
    const __half* B16 = g_WG16[z];
    const float* bias = biases[z];
    __half* C16 = which ? g_GH16[r] : g_GI16[r];
    const int K = HH;
    const int m0 = blockIdx.x * 128;

    const uint32_t sb = smem_u32(smem);
    const uint32_t sA  = sb;
    const uint32_t sB0 = sb + G_TILE;
    const int tid  = threadIdx.x;
    const int wid  = tid >> 5;
    const int lane = tid & 31;
    const int warp_m = wid & 3;
    const int warp_n = wid >> 2;

#pragma unroll
    for (int it = 0; it < 8; it++) {
        int s = tid + it * 256;
        int row = s >> 4, q = s & 15;
        cpa16(sA + row * GROW + q * 16, A16 + (size_t)(m0 + row) * K + q * 8);
    }
    asm volatile("cp.async.commit_group;" ::: "memory");

#define FILLB(y, stg) do {                                                      \
        const uint32_t s0 = sB0 + (stg) * G_TILE;                               \
        const int nb0 = (y) * 128;                                              \
        _Pragma("unroll")                                                       \
        for (int it = 0; it < 8; it++) {                                        \
            int s = tid + it * 256;                                             \
            int row = s >> 4, q = s & 15;                                       \
            cpa16(s0 + row * GROW + q * 16,                                     \
                  B16 + (size_t)(nb0 + row) * K + q * 8);                       \
        }                                                                       \
        asm volatile("cp.async.commit_group;" ::: "memory");                    \
    } while (0)

    FILLB(0, 0);

    for (int y = 0; y < 3; y++) {
        if (y < 2) {
            FILLB(y + 1, (y + 1) & 1);
            asm volatile("cp.async.wait_group 1;" ::: "memory");
        } else {
            asm volatile("cp.async.wait_group 0;" ::: "memory");
        }
        __syncthreads();

        const uint32_t sB = sB0 + (y & 1) * G_TILE;
        const int n0 = y * 128;

        float acc[2][8][4];
#pragma unroll
        for (int i = 0; i < 2; i++)
#pragma unroll
            for (int j = 0; j < 8; j++)
#pragma unroll
                for (int t = 0; t < 4; t++) acc[i][j][t] = 0.f;

#pragma unroll
        for (int ks = 0; ks < 8; ks++) {
            uint32_t af[2][4];
            {
                int rr = lane & 15;
                int c8 = lane >> 4;
                uint32_t off = (uint32_t)((warp_m * 32 + rr) * GROW + (ks * 16 + c8 * 8) * 2);
                ldsm4(af[0], sA + off);
                ldsm4(af[1], sA + off + 16 * GROW);
            }
            uint32_t bf[8][2];
            {
                int sub = lane >> 3, wi = lane & 7;
                int n_off = (sub >> 1) * 8 + wi;
                int k_off = ks * 16 + (sub & 1) * 8;
                uint32_t base = (uint32_t)((warp_n * 64 + n_off) * GROW + k_off * 2);
#pragma unroll
                for (int jj = 0; jj < 4; jj++) {
                    uint32_t r4[4];
                    ldsm4(r4, sB + base + jj * 16 * GROW);
                    bf[2 * jj][0] = r4[0]; bf[2 * jj][1] = r4[1];
                    bf[2 * jj + 1][0] = r4[2]; bf[2 * jj + 1][1] = r4[3];
                }
            }
#pragma unroll
            for (int mi = 0; mi < 2; mi++)
#pragma unroll
                for (int j = 0; j < 8; j++)
                    mma_f16(acc[mi][j], af[mi], bf[j]);
        }
        __syncthreads();

#pragma unroll
        for (int mi = 0; mi < 2; mi++) {
            int gr = m0 + warp_m * 32 + mi * 16 + (lane >> 2);
#pragma unroll
            for (int j = 0; j < 8; j++) {
                int gc = n0 + warp_n * 64 + j * 8 + 2 * (lane & 3);
                float bb0 = bias[gc], bb1 = bias[gc + 1];
#pragma unroll
                for (int half = 0; half < 2; half++) {
                    int row = gr + half * 8;
                    if (row >= M) continue;
                    __half2 hv = __floats2half2_rn(acc[mi][j][2 * half + 0] + bb0,
                                                   acc[mi][j][2 * half + 1] + bb1);
                    *reinterpret_cast<__half2*>(C16 + (size_t)row * G3 + gc) = hv;
                }
            }
        }
    }
#undef FILLB
}

// ------------------- CSR build -------------------
__global__ void hist_k(const int* e0, const int* e1, const int* e2, int E, int N)
{
    int e = blockIdx.x * blockDim.x + threadIdx.x;
    if (e >= 3 * E) return;
    int r = e / E, le = e - r * E;
    const int* ei = (r == 0) ? e0 : (r == 1) ? e1 : e2;
    atomicAdd(&g_CNT[r * N + ei[E + le]], 1);
}
__global__ void scan1_k(int ntot)
{
    __shared__ int sh[1024];
    int tid = threadIdx.x;
    int gid = blockIdx.x * 1024 + tid;
    int v = 0;
    if (gid < ntot) {
        v = g_CNT[gid];
        g_CNT[gid] = 0;
    }
    sh[tid] = v;
    __syncthreads();
    for (int o = 1; o < 1024; o <<= 1) {
        int t = (tid >= o) ? sh[tid - o] : 0;
        __syncthreads();
        sh[tid] += t;
        __syncthreads();
    }
    if (gid < ntot) g_OFF[gid] = sh[tid] - v;
    if (tid == 1023) g_BSUM[blockIdx.x] = sh[1023];
}
// scan3: finalize OFF/CUR, zero AS/AT; warp-parallel block prefix
__global__ void scan3_k(int ntot)
{
    __shared__ int base;
    if (threadIdx.x < 32) {
        int run = 0;
        for (int i = threadIdx.x; i < blockIdx.x; i += 32) run += g_BSUM[i];
#pragma unroll
        for (int o = 16; o; o >>= 1) run += __shfl_xor_sync(0xffffffffu, run, o);
        if (threadIdx.x == 0) base = run;
    }
    __syncthreads();
    int gid = blockIdx.x * 1024 + threadIdx.x;
    if (gid >= ntot) return;
    int o = g_OFF[gid] + base;
    g_OFF[gid] = o;
    g_CUR[gid] = o;
    (&g_AS[0][0])[gid] = 0.f;
    (&g_AT[0][0])[gid] = 0.f;
}
__global__ void scatter_idx_k(const int* e0, const int* e1, const int* e2, int E, int N)
{
    int e = blockIdx.x * blockDim.x + threadIdx.x;
    if (e >= 3 * E) return;
    int r = e / E, le = e - r * E;
    const int* ei = (r == 0) ? e0 : (r == 1) ? e1 : e2;
    int si = ei[le];
    int ti = ei[E + le];
    int pos = atomicAdd(&g_CUR[r * N + ti], 1);
    g_SRC[pos] = si;
}

// ---------- gather aggregation: single-pass ----------
__global__ void gather_k(int N, int Etot)
{
    int gw   = (blockIdx.x * blockDim.x + threadIdx.x) >> 5;
    int lane = threadIdx.x & 31;
    if (gw >= 3 * N) return;
    int r = gw / N, ti = gw - r * N;
    int idx = r * N + ti;
    int s = g_OFF[idx];
    int e = (idx + 1 < 3 * N) ? g_OFF[idx + 1] : Etot;
    uint2* dst16 = reinterpret_cast<uint2*>(g_AG16[r] + (size_t)ti * HH + lane * 4);
    float4 acc = make_float4(0.f, 0.f, 0.f, 0.f);
    if (s < e) {
        float at = g_AT[r][ti];
        float den = 0.f;
        for (int base = s; base < e; base += 32) {
            int k = base + lane;
            int si = 0;
            float ex = 0.f;
            if (k < e) {
                si = g_SRC[k];
                float l = g_AS[r][si] + at;
                l = (l > 0.f) ? l : 0.2f * l;
                ex = expf(l);
                den += ex;
            }
            int cnt = min(32, e - base);
            for (int j = 0; j < cnt; j++) {
                float exj = __shfl_sync(0xffffffffu, ex, j);
                int   sij = __shfl_sync(0xffffffffu, si, j);
                uint2 p = *reinterpret_cast<const uint2*>(
                    g_HS16[r] + (size_t)sij * HH + lane * 4);
                float4 v = unpack4h(p);
                acc.x += exj * v.x;
                acc.y += exj * v.y;
                acc.z += exj * v.z;
                acc.w += exj * v.w;
            }
        }
#pragma unroll
        for (int o = 16; o; o >>= 1) den += __shfl_xor_sync(0xffffffffu, den, o);
        float inv = 1.f / (den + 1e-16f);
        acc.x *= inv; acc.y *= inv; acc.z *= inv; acc.w *= inv;
    }
    *dst16 = pack4h(acc);
}

// ------- fused GRU combine + final outputs -------
__global__ void gru_final_k(float* __restrict__ out, const float* __restrict__ g, int n)
{
    int node = (blockIdx.x * blockDim.x + threadIdx.x) >> 5;
    int lane = threadIdx.x & 31;
    if (node >= n) return;
    int h4 = lane * 4;

    float hout[3][4];
#pragma unroll
    for (int r = 0; r < 3; r++) {
        const __half* gi = g_GI16[r] + (size_t)node * G3;
        const __half* gh = g_GH16[r] + (size_t)node * G3;
        float4 gir = unpack4h(*reinterpret_cast<const uint2*>(gi + h4));
        float4 giz = unpack4h(*reinterpret_cast<const uint2*>(gi + HH + h4));
        float4 gin = unpack4h(*reinterpret_cast<const uint2*>(gi + 2 * HH + h4));
        float4 ghr = unpack4h(*reinterpret_cast<const uint2*>(gh + h4));
        float4 ghz = unpack4h(*reinterpret_cast<const uint2*>(gh + HH + h4));
        float4 ghn = unpack4h(*reinterpret_cast<const uint2*>(gh + 2 * HH + h4));
        float4 a = unpack4h(*reinterpret_cast<const uint2*>(
            g_AG16[r] + (size_t)node * HH + h4));
        float gi_r[4] = {gir.x, gir.y, gir.z, gir.w};
        float gi_z[4] = {giz.x, giz.y, giz.z, giz.w};
        float gi_n[4] = {gin.x, gin.y, gin.z, gin.w};
        float gh_r[4] = {ghr.x, ghr.y, ghr.z, ghr.w};
        float gh_z[4] = {ghz.x, ghz.y, ghz.z, ghz.w};
        float gh_n[4] = {ghn.x, ghn.y, ghn.z, ghn.w};
        float av[4]   = {a.x, a.y, a.z, a.w};
#pragma unroll
        for (int t = 0; t < 4; t++) {
            float rr = 1.f / (1.f + expf(-(gi_r[t] + gh_r[t])));
            float zz = 1.f / (1.f + expf(-(gi_z[t] + gh_z[t])));
            float gg = tanhf(gi_n[t] + rr * gh_n[t]);
            hout[r][t] = (1.f - zz) * gg + zz * av[t];
        }
    }

    size_t off = (size_t)node * HH + h4;
    float4 u;
    u.x = fmaxf(hout[1][0], 0.f);
    u.y = fmaxf(hout[1][1], 0.f);
    u.z = fmaxf(hout[1][2], 0.f);
    u.w = fmaxf(hout[1][3], 0.f);
    *reinterpret_cast<float4*>(out + off) = u;

    float4 gv = *reinterpret_cast<const float4*>(g + h4);
    float gvv[4] = {gv.x, gv.y, gv.z, gv.w};
    float d0 = 0.f, d1 = 0.f;
#pragma unroll
    for (int t = 0; t < 4; t++) {
        d0 += hout[0][t] * gvv[t];
        d1 += hout[2][t] * gvv[t];
    }
#pragma unroll
    for (int o = 16; o; o >>= 1) {
        d0 += __shfl_xor_sync(0xffffffffu, d0, o);
        d1 += __shfl_xor_sync(0xffffffffu, d1, o);
    }
    float a0 = expf(d0), a1 = expf(d1);
    float inv = 1.f / (a0 + a1);
    float w0 = a0 * inv, w1 = a1 * inv;
    float4 o4;
    o4.x = fmaxf(w0 * hout[0][0] + w1 * hout[2][0], 0.f);
    o4.y = fmaxf(w0 * hout[0][1] + w1 * hout[2][1], 0.f);
    o4.z = fmaxf(w0 * hout[0][2] + w1 * hout[2][2], 0.f);
    o4.w = fmaxf(w0 * hout[0][3] + w1 * hout[2][3], 0.f);
    *reinterpret_cast<float4*>(out + (size_t)n * HH + off) = o4;
}

// ---------------------------------------------------------------
extern "C" void kernel_launch(void* const* d_in, const int* in_sizes, int n_in,
                              void* d_out, int out_size)
{
    const float* x_user = (const float*)d_in[0];
    const float* x_item = (const float*)d_in[1];
    const int*   ei_ui  = (const int*)d_in[2];
    const int*   ei_iu  = (const int*)d_in[3];
    const int*   ei_ii  = (const int*)d_in[4];

    int N = in_sizes[0] / DD;
    int E = in_sizes[2] / 2;
    if (N > NMAX) N = NMAX;
    if (E > EMAX) E = EMAX;

    float* out = (float*)d_out;

    cudaFuncSetAttribute(hsht_gemm, cudaFuncAttributeMaxDynamicSharedMemorySize, HSMEM);
    cudaFuncSetAttribute(gru_gemm,  cudaFuncAttributeMaxDynamicSharedMemorySize, GSMEM);

    // fused prep
    int x4 = (N * DD) / 4;
    int prepTot = 2 * x4 + WT_TOT + WG_TOT;
    prep_all<<<(prepTot + 255) / 256, 256>>>(
        x_user, x_item, x4,
        (const float*)d_in[5],  (const float*)d_in[6],
        (const float*)d_in[12], (const float*)d_in[13],
        (const float*)d_in[19], (const float*)d_in[20],
        (const float*)d_in[8],  (const float*)d_in[9],
        (const float*)d_in[15], (const float*)d_in[16],
        (const float*)d_in[22], (const float*)d_in[23]);

    // CSR build (+ AS/AT zeroing in scan3)
    int ntot = 3 * N;
    hist_k<<<(3 * E + 255) / 256, 256>>>(ei_ui, ei_iu, ei_ii, E, N);
    int nb = (ntot + 1023) / 1024;
    scan1_k<<<nb, 1024>>>(ntot);
    scan3_k<<<nb, 1024>>>(ntot);
    scatter_idx_k<<<(3 * E + 255) / 256, 256>>>(ei_ui, ei_iu, ei_ii, E, N);

    const int mb = NPAD / 128;   // 392

    hsht_gemm<<<dim3(mb, 1, 3), 256, HSMEM>>>(
        N, (const float*)d_in[7], (const float*)d_in[14], (const float*)d_in[21]);

    gather_k<<<(int)(((long long)3 * N * 32 + 255) / 256), 256>>>(N, 3 * E);

    gru_gemm<<<dim3(mb, 1, 6), 256, GSMEM>>>(
        N,
        (const float*)d_in[10], (const float*)d_in[11],
        (const float*)d_in[17], (const float*)d_in[18],
        (const float*)d_in[24], (const float*)d_in[25]);

    gru_final_k<<<(N * 32 + 255) / 256, 256>>>(out, (const float*)d_in[27], N);
}